// round 5
// baseline (speedup 1.0000x reference)
#include <cuda_runtime.h>

#define HID 128
#define NMAX 50000
#define EMAX 500000

// ---------------- device scratch (no allocations allowed) ----------------
__device__ float g_agg[(size_t)NMAX * HID];
__device__ float g_inv[NMAX];
__device__ int   g_indeg[NMAX];
__device__ int   g_eperm[EMAX];
__device__ int   g_nperm[NMAX];
__device__ int   g_ecnt[8], g_eoff[8], g_ecur[8];
__device__ int   g_ncnt[8], g_noff[8], g_ncur[8];

// ---------------- packed f32x2 helpers ----------------
static __device__ __forceinline__ unsigned long long pk(float x, float y){
    unsigned long long r;
    asm("mov.b64 %0, {%1, %2};" : "=l"(r) : "f"(x), "f"(y));
    return r;
}
static __device__ __forceinline__ unsigned long long pk2(float a){ return pk(a, a); }
static __device__ __forceinline__ unsigned long long ffma2(unsigned long long a, unsigned long long b, unsigned long long c){
    unsigned long long d;
    asm("fma.rn.f32x2 %0, %1, %2, %3;" : "=l"(d) : "l"(a), "l"(b), "l"(c));
    return d;
}
static __device__ __forceinline__ float lo2(unsigned long long v){ return __uint_as_float((unsigned)v); }
static __device__ __forceinline__ float hi2(unsigned long long v){ return __uint_as_float((unsigned)(v >> 32)); }

// ---------------- bucketing kernels ----------------
__global__ void k_zero(int nagg, int N){
    int i  = blockIdx.x * blockDim.x + threadIdx.x;
    int st = gridDim.x * blockDim.x;
    for (int j = i; j < nagg; j += st) g_agg[j] = 0.f;
    for (int j = i; j < N;    j += st) g_indeg[j] = 0;
    if (i < 8){ g_ecnt[i] = 0; g_ncnt[i] = 0; }
}

__global__ void k_count(const int* __restrict__ ei, const int* __restrict__ depth, int N, int E){
    int i = blockIdx.x * blockDim.x + threadIdx.x;
    if (i < E){
        int dst = ei[E + i];
        atomicAdd(&g_ecnt[depth[dst]], 1);
        atomicAdd(&g_indeg[dst], 1);
    }
    if (i < N){
        atomicAdd(&g_ncnt[depth[i]], 1);
    }
}

__global__ void k_scan(){
    int e = 0, n = 0;
    for (int d = 0; d < 8; ++d){
        g_eoff[d] = e; g_ecur[d] = e; e += g_ecnt[d];
        g_noff[d] = n; g_ncur[d] = n; n += g_ncnt[d];
    }
}

__global__ void k_scatter(const int* __restrict__ ei, const int* __restrict__ depth, int N, int E){
    int i = blockIdx.x * blockDim.x + threadIdx.x;
    if (i < E){
        int dst = ei[E + i];
        int p = atomicAdd(&g_ecur[depth[dst]], 1);
        g_eperm[p] = i;
    }
    if (i < N){
        int p = atomicAdd(&g_ncur[depth[i]], 1);
        g_nperm[p] = i;
        int c = g_indeg[i];
        g_inv[i] = 1.0f / (float)(c > 0 ? c : 1);
    }
}

// ---------------- GEMM building blocks ----------------
// A is i-major in shared: A[(i0+ii)*LDA + k], broadcast-friendly reads.
// Ws is one staged 16 x 128 slab of the (row-major K x 128) weight.
template<int LDA>
static __device__ __forceinline__ void mm16(const float* __restrict__ A, const float* __restrict__ Ws,
                                            int i0, int j0, unsigned long long acc[4][4]){
    #pragma unroll
    for (int kk = 0; kk < 16; ++kk){
        const float* wr = Ws + kk * HID + j0;
        ulonglong2 wA = *(const ulonglong2*)(wr);
        ulonglong2 wB = *(const ulonglong2*)(wr + 4);
        #pragma unroll
        for (int ii = 0; ii < 4; ++ii){
            unsigned long long a2 = pk2(A[(i0 + ii) * LDA + kk]);
            acc[ii][0] = ffma2(a2, wA.x, acc[ii][0]);
            acc[ii][1] = ffma2(a2, wA.y, acc[ii][1]);
            acc[ii][2] = ffma2(a2, wB.x, acc[ii][2]);
            acc[ii][3] = ffma2(a2, wB.y, acc[ii][3]);
        }
    }
}

// Stage rows [k0, k0+16) of W (K x 128 row-major) into Ws; zero-fill rows >= K.
static __device__ __forceinline__ void stage_w(float* Ws, const float* __restrict__ W, int k0, int K, int tid){
    #pragma unroll
    for (int r = 0; r < 2; ++r){
        int idx = tid + (r << 8);           // float4 index 0..511
        int kr  = idx >> 5;                 // slab row 0..15
        int c4  = (idx & 31) << 2;          // column 0..124
        int k   = k0 + kr;
        float4 v = make_float4(0.f, 0.f, 0.f, 0.f);
        if (k < K) v = *(const float4*)(W + (size_t)k * HID + c4);
        *(float4*)(Ws + kr * HID + c4) = v;
    }
}

static __device__ __forceinline__ void init_acc_bias(const float* __restrict__ b, int j0, unsigned long long acc[4][4]){
    float4 b0 = *(const float4*)(b + j0);
    float4 b1 = *(const float4*)(b + j0 + 4);
    unsigned long long p0 = pk(b0.x, b0.y), p1 = pk(b0.z, b0.w);
    unsigned long long p2 = pk(b1.x, b1.y), p3 = pk(b1.z, b1.w);
    #pragma unroll
    for (int ii = 0; ii < 4; ++ii){
        acc[ii][0] = p0; acc[ii][1] = p1; acc[ii][2] = p2; acc[ii][3] = p3;
    }
}

// ---------------- projection: h = x @ pw + pb ----------------
#define SMEM_PROJ ((64*132 + 16*128) * 4)
__global__ __launch_bounds__(256) void k_proj(const float* __restrict__ x, const float* __restrict__ pw,
                                              const float* __restrict__ pb, float* __restrict__ h, int N){
    extern __shared__ float sm[];
    const int LDA = 132;
    float* As = sm;                 // 64 x 132
    float* Ws = sm + 64 * LDA;      // 16 x 128
    int tid = threadIdx.x;
    int r0  = blockIdx.x * 64;
    {
        int i = tid >> 2, sub = tid & 3;
        int row = r0 + i;
        const float4* xr = (const float4*)(x + (size_t)(row < N ? row : 0) * HID);
        #pragma unroll
        for (int c = 0; c < 8; ++c){
            int k4 = (sub << 3) + c;
            *(float4*)(As + i * LDA + (k4 << 2)) = xr[k4];
        }
    }
    int ti = tid & 15, tj = tid >> 4;
    int i0 = tj << 2, j0 = ti << 3;
    unsigned long long acc[4][4];
    init_acc_bias(pb, j0, acc);
    for (int s = 0; s < 8; ++s){
        __syncthreads();
        stage_w(Ws, pw, s * 16, 128, tid);
        __syncthreads();
        mm16<132>(As + s * 16, Ws, i0, j0, acc);
    }
    #pragma unroll
    for (int ii = 0; ii < 4; ++ii){
        int row = r0 + i0 + ii;
        if (row < N){
            float* hr = h + (size_t)row * HID + j0;
            #pragma unroll
            for (int p = 0; p < 4; ++p)
                *(float2*)(hr + (p << 1)) = make_float2(lo2(acc[ii][p]), hi2(acc[ii][p]));
        }
    }
}

// ---------------- message MLP per level (only edges with dst_depth == lvl) ----------------
#define SMEM_MSG ((64*144 + 64*132 + 16*128) * 4 + 64 * 4)
__global__ __launch_bounds__(256, 2) void k_msg(const float* __restrict__ h, const int* __restrict__ ei,
                                                const float* __restrict__ eattr,
                                                const float* __restrict__ mw1, const float* __restrict__ mb1,
                                                const float* __restrict__ mw2, const float* __restrict__ mb2,
                                                int E, int lvl){
    extern __shared__ float sm[];
    const int LDA = 144;            // K=129 padded to 144 (9 slabs of 16)
    const int LDT = 132;
    float* As = sm;                 // 64 x 144
    float* T  = As + 64 * LDA;      // 64 x 132
    float* Ws = T + 64 * LDT;       // 16 x 128
    int* sdst = (int*)(Ws + 16 * HID);  // 64

    int tid = threadIdx.x;
    int ti = tid & 15, tj = tid >> 4;
    int i0 = tj << 2, j0 = ti << 3;

    int cnt  = g_ecnt[lvl];
    int base = g_eoff[lvl];
    int ntiles = (cnt + 63) >> 6;

    for (int t = blockIdx.x; t < ntiles; t += gridDim.x){
        __syncthreads();
        // gather A = [h[src] | edge_attr | zero-pad]
        {
            int i = tid >> 2, sub = tid & 3;
            int p = t * 64 + i;
            int e = (p < cnt) ? g_eperm[base + p] : -1;
            int src = (e >= 0) ? ei[e] : 0;
            const float4* hr = (const float4*)(h + (size_t)src * HID);
            #pragma unroll
            for (int c = 0; c < 8; ++c){
                int k4 = (sub << 3) + c;
                *(float4*)(As + i * LDA + (k4 << 2)) = hr[k4];
            }
            if (sub == 0){
                As[i * LDA + 128] = (e >= 0) ? eattr[e] : 0.f;
                #pragma unroll
                for (int c = 129; c < 144; ++c) As[i * LDA + c] = 0.f;
                sdst[i] = (e >= 0) ? ei[E + e] : -1;
            }
        }
        __syncthreads();
        // layer 1: K = 129
        unsigned long long acc[4][4];
        init_acc_bias(mb1, j0, acc);
        for (int s = 0; s < 9; ++s){
            __syncthreads();
            stage_w(Ws, mw1, s * 16, 129, tid);
            __syncthreads();
            mm16<144>(As + s * 16, Ws, i0, j0, acc);
        }
        // relu -> T (i-major)
        #pragma unroll
        for (int ii = 0; ii < 4; ++ii){
            float* trow = T + (i0 + ii) * LDT + j0;
            #pragma unroll
            for (int p = 0; p < 4; ++p){
                trow[2*p]   = fmaxf(lo2(acc[ii][p]), 0.f);
                trow[2*p+1] = fmaxf(hi2(acc[ii][p]), 0.f);
            }
        }
        // layer 2: K = 128
        init_acc_bias(mb2, j0, acc);
        for (int s = 0; s < 8; ++s){
            __syncthreads();
            stage_w(Ws, mw2, s * 16, 128, tid);
            __syncthreads();
            mm16<132>(T + s * 16, Ws, i0, j0, acc);
        }
        // epilogue: relu + atomic accumulate into g_agg[dst]
        #pragma unroll
        for (int ii = 0; ii < 4; ++ii){
            int i = i0 + ii;
            int p = t * 64 + i;
            if (p < cnt){
                int dst = sdst[i];
                float* arow = g_agg + (size_t)dst * HID + j0;
                #pragma unroll
                for (int q = 0; q < 4; ++q){
                    atomicAdd(arow + 2*q,     fmaxf(lo2(acc[ii][q]), 0.f));
                    atomicAdd(arow + 2*q + 1, fmaxf(hi2(acc[ii][q]), 0.f));
                }
            }
        }
    }
}

// ---------------- node update per level (only nodes with depth == lvl) ----------------
#define SMEM_UPD ((64*260 + 64*132 + 16*128) * 4 + 64 * 4)
__global__ __launch_bounds__(256, 2) void k_upd(float* __restrict__ h,
                                                const float* __restrict__ uw1, const float* __restrict__ ub1,
                                                const float* __restrict__ uw2, const float* __restrict__ ub2,
                                                int lvl){
    extern __shared__ float sm[];
    const int LDA = 260;            // K=256, pad +4
    const int LDT = 132;
    float* As = sm;                 // 64 x 260
    float* T  = As + 64 * LDA;      // 64 x 132
    float* Ws = T + 64 * LDT;       // 16 x 128
    int* snode = (int*)(Ws + 16 * HID);

    int tid = threadIdx.x;
    int ti = tid & 15, tj = tid >> 4;
    int i0 = tj << 2, j0 = ti << 3;

    int cnt  = g_ncnt[lvl];
    int base = g_noff[lvl];
    int ntiles = (cnt + 63) >> 6;

    for (int t = blockIdx.x; t < ntiles; t += gridDim.x){
        __syncthreads();
        // gather A = [h[v] | agg[v] * inv[v]]
        {
            int i = tid >> 2, sub = tid & 3;
            int p = t * 64 + i;
            int v = (p < cnt) ? g_nperm[base + p] : 0;
            float inv = g_inv[v];
            const float4* hr = (const float4*)(h + (size_t)v * HID);
            const float4* ar = (const float4*)(g_agg + (size_t)v * HID);
            #pragma unroll
            for (int c = 0; c < 8; ++c){
                int k4 = (sub << 3) + c;
                *(float4*)(As + i * LDA + (k4 << 2)) = hr[k4];
                float4 a = ar[k4];
                a.x *= inv; a.y *= inv; a.z *= inv; a.w *= inv;
                *(float4*)(As + i * LDA + 128 + (k4 << 2)) = a;
            }
            if (sub == 0) snode[i] = (p < cnt) ? v : -1;
        }
        __syncthreads();
        // layer 1: K = 256
        unsigned long long acc[4][4];
        init_acc_bias(ub1, j0, acc);
        for (int s = 0; s < 16; ++s){
            __syncthreads();
            stage_w(Ws, uw1, s * 16, 256, tid);
            __syncthreads();
            mm16<260>(As + s * 16, Ws, i0, j0, acc);
        }
        #pragma unroll
        for (int ii = 0; ii < 4; ++ii){
            float* trow = T + (i0 + ii) * LDT + j0;
            #pragma unroll
            for (int p = 0; p < 4; ++p){
                trow[2*p]   = fmaxf(lo2(acc[ii][p]), 0.f);
                trow[2*p+1] = fmaxf(hi2(acc[ii][p]), 0.f);
            }
        }
        // layer 2: K = 128
        init_acc_bias(ub2, j0, acc);
        for (int s = 0; s < 8; ++s){
            __syncthreads();
            stage_w(Ws, uw2, s * 16, 128, tid);
            __syncthreads();
            mm16<132>(T + s * 16, Ws, i0, j0, acc);
        }
        // epilogue: relu -> overwrite h[v]
        #pragma unroll
        for (int ii = 0; ii < 4; ++ii){
            int v = snode[i0 + ii];
            if (v >= 0){
                float* hr = h + (size_t)v * HID + j0;
                #pragma unroll
                for (int p = 0; p < 4; ++p)
                    *(float2*)(hr + (p << 1)) = make_float2(fmaxf(lo2(acc[ii][p]), 0.f),
                                                            fmaxf(hi2(acc[ii][p]), 0.f));
            }
        }
    }
}

// ---------------- host launch ----------------
extern "C" void kernel_launch(void* const* d_in, const int* in_sizes, int n_in,
                              void* d_out, int out_size){
    const float* x     = (const float*)d_in[0];
    const int*   ei    = (const int*)  d_in[1];
    const float* eattr = (const float*)d_in[2];
    const int*   depth = (const int*)  d_in[3];
    const float* pw    = (const float*)d_in[4];
    const float* pb    = (const float*)d_in[5];
    const float* mw1   = (const float*)d_in[6];
    const float* mb1   = (const float*)d_in[7];
    const float* mw2   = (const float*)d_in[8];
    const float* mb2   = (const float*)d_in[9];
    const float* uw1   = (const float*)d_in[10];
    const float* ub1   = (const float*)d_in[11];
    const float* uw2   = (const float*)d_in[12];
    const float* ub2   = (const float*)d_in[13];
    float* h = (float*)d_out;

    int N = in_sizes[3];       // depth has N elements
    int E = in_sizes[2];       // edge_attr has E elements (EDGE_DIM = 1)

    cudaFuncSetAttribute(k_proj, cudaFuncAttributeMaxDynamicSharedMemorySize, SMEM_PROJ);
    cudaFuncSetAttribute(k_msg,  cudaFuncAttributeMaxDynamicSharedMemorySize, SMEM_MSG);
    cudaFuncSetAttribute(k_upd,  cudaFuncAttributeMaxDynamicSharedMemorySize, SMEM_UPD);

    k_zero<<<1024, 256>>>(N * HID, N);

    int mx = (E > N) ? E : N;
    int gb = (mx + 255) / 256;
    k_count<<<gb, 256>>>(ei, depth, N, E);
    k_scan<<<1, 1>>>();
    k_scatter<<<gb, 256>>>(ei, depth, N, E);

    k_proj<<<(N + 63) / 64, 256, SMEM_PROJ>>>(x, pw, pb, h, N);

    for (int d = 1; d <= 4; ++d){
        k_msg<<<1184, 256, SMEM_MSG>>>(h, ei, eattr, mw1, mb1, mw2, mb2, E, d);
        k_upd<<<512, 256, SMEM_UPD>>>(h, uw1, ub1, uw2, ub2, d);
    }
}

// round 6
// speedup vs baseline: 1.1231x; 1.1231x over previous
#include <cuda_runtime.h>

#define HID 128
#define NMAX 50000
#define EMAX 500000

// ---------------- device scratch ----------------
__device__ float g_agg[(size_t)NMAX * HID];
__device__ float g_inv[NMAX];
__device__ int   g_indeg[NMAX];
__device__ int   g_eperm[EMAX];
__device__ int   g_nperm[NMAX];
__device__ int   g_rank[NMAX];
__device__ int   g_nodeoff[NMAX];
__device__ int   g_nodecur[NMAX];
__device__ int   g_partial[256];
__device__ int   g_ecnt[8], g_eoff[8];
__device__ int   g_ncnt[8], g_noff[8], g_ncur[8];

// ---------------- packed f32x2 helpers ----------------
static __device__ __forceinline__ unsigned long long pk(float x, float y){
    unsigned long long r;
    asm("mov.b64 %0, {%1, %2};" : "=l"(r) : "f"(x), "f"(y));
    return r;
}
static __device__ __forceinline__ unsigned long long pk2(float a){ return pk(a, a); }
static __device__ __forceinline__ unsigned long long ffma2(unsigned long long a, unsigned long long b, unsigned long long c){
    unsigned long long d;
    asm("fma.rn.f32x2 %0, %1, %2, %3;" : "=l"(d) : "l"(a), "l"(b), "l"(c));
    return d;
}
static __device__ __forceinline__ float lo2(unsigned long long v){ return __uint_as_float((unsigned)v); }
static __device__ __forceinline__ float hi2(unsigned long long v){ return __uint_as_float((unsigned)(v >> 32)); }

// ---------------- bucketing ----------------
__global__ void k_zero(int nagg, int N){
    int i  = blockIdx.x * blockDim.x + threadIdx.x;
    int st = gridDim.x * blockDim.x;
    for (int j = i; j < nagg; j += st) g_agg[j] = 0.f;
    for (int j = i; j < N;    j += st) g_indeg[j] = 0;
    if (i < 8) g_ncnt[i] = 0;
}

__global__ void k_count(const int* __restrict__ ei, const int* __restrict__ depth, int N, int E){
    __shared__ int scnt[8];
    int t = threadIdx.x;
    if (t < 8) scnt[t] = 0;
    __syncthreads();
    int i = blockIdx.x * blockDim.x + t;
    if (i < E) atomicAdd(&g_indeg[ei[E + i]], 1);
    if (i < N) atomicAdd(&scnt[depth[i]], 1);
    __syncthreads();
    if (t < 8 && scnt[t]) atomicAdd(&g_ncnt[t], scnt[t]);
}

__global__ void k_nscan(){
    int n = 0;
    for (int d = 0; d < 8; ++d){ g_noff[d] = n; g_ncur[d] = n; n += g_ncnt[d]; }
}

__global__ void k_snodes(const int* __restrict__ depth, int N){
    __shared__ int scnt[8], sbase[8];
    int t = threadIdx.x;
    if (t < 8) scnt[t] = 0;
    __syncthreads();
    int i = blockIdx.x * blockDim.x + t;
    int d = 0, pl = 0;
    if (i < N){ d = depth[i]; pl = atomicAdd(&scnt[d], 1); }
    __syncthreads();
    if (t < 8) sbase[t] = scnt[t] ? atomicAdd(&g_ncur[t], scnt[t]) : 0;
    __syncthreads();
    if (i < N){
        int pos = sbase[d] + pl;
        g_nperm[pos] = i;
        g_rank[i] = pos;
        int c = g_indeg[i];
        g_inv[i] = 1.0f / (float)(c > 0 ? c : 1);
    }
}

// 3-phase exclusive scan of indeg[] in nperm order (N <= 65536)
__global__ void k_escan1(int N){
    __shared__ int sh[256];
    int chunk = (N + 255) / 256;
    int t = threadIdx.x;
    int i = blockIdx.x * chunk + t;
    int v = 0;
    if (t < chunk && i < N) v = g_indeg[g_nperm[i]];
    sh[t] = v; __syncthreads();
    for (int s = 128; s > 0; s >>= 1){
        if (t < s) sh[t] += sh[t + s];
        __syncthreads();
    }
    if (t == 0) g_partial[blockIdx.x] = sh[0];
}
__global__ void k_escan2(){
    __shared__ int sh[256];
    int t = threadIdx.x;
    int orig = g_partial[t];
    sh[t] = orig; __syncthreads();
    for (int s = 1; s < 256; s <<= 1){
        int v = (t >= s) ? sh[t - s] : 0;
        __syncthreads();
        sh[t] += v;
        __syncthreads();
    }
    g_partial[t] = sh[t] - orig;
}
__global__ void k_escan3(int N){
    __shared__ int sh[256];
    int chunk = (N + 255) / 256;
    int t = threadIdx.x;
    int i = blockIdx.x * chunk + t;
    int orig = 0;
    if (t < chunk && i < N) orig = g_indeg[g_nperm[i]];
    sh[t] = orig; __syncthreads();
    for (int s = 1; s < 256; s <<= 1){
        int v = (t >= s) ? sh[t - s] : 0;
        __syncthreads();
        sh[t] += v;
        __syncthreads();
    }
    if (t < chunk && i < N){
        int excl = g_partial[blockIdx.x] + sh[t] - orig;
        g_nodeoff[i] = excl;
        g_nodecur[i] = excl;
    }
}
__global__ void k_levels(int N, int E){
    for (int d = 0; d < 8; ++d){
        int b0 = g_noff[d];
        int b1 = b0 + g_ncnt[d];
        int o0 = (b0 < N) ? g_nodeoff[b0] : E;
        int o1 = (b1 < N) ? g_nodeoff[b1] : E;
        g_eoff[d] = o0; g_ecnt[d] = o1 - o0;
    }
}
__global__ void k_sedges(const int* __restrict__ ei, int E){
    int e = blockIdx.x * blockDim.x + threadIdx.x;
    if (e < E){
        int dst = ei[E + e];
        int pos = atomicAdd(&g_nodecur[g_rank[dst]], 1);
        g_eperm[pos] = e;
    }
}

// ---------------- GEMM core ----------------
// A i-major (row stride LDA floats), W in SMEM row-major [Kpad][128].
// Thread computes RR rows x 8 cols. K4 = K/4 chunks.
template<int LDA, int RR>
static __device__ __forceinline__ void mmK(const float* __restrict__ A, const float* __restrict__ W,
                                           int K4, int i0, int j0, unsigned long long acc[RR][4]){
    for (int c = 0; c < K4; ++c){
        float4 av[RR];
        #pragma unroll
        for (int ii = 0; ii < RR; ++ii)
            av[ii] = *(const float4*)(A + (i0 + ii) * LDA + (c << 2));
        const float* wr = W + (c << 2) * HID + j0;
        #pragma unroll
        for (int q = 0; q < 4; ++q){
            ulonglong2 wA = *(const ulonglong2*)(wr + q * HID);
            ulonglong2 wB = *(const ulonglong2*)(wr + q * HID + 4);
            #pragma unroll
            for (int ii = 0; ii < RR; ++ii){
                float aq = (q == 0) ? av[ii].x : (q == 1) ? av[ii].y : (q == 2) ? av[ii].z : av[ii].w;
                unsigned long long a2 = pk2(aq);
                acc[ii][0] = ffma2(a2, wA.x, acc[ii][0]);
                acc[ii][1] = ffma2(a2, wA.y, acc[ii][1]);
                acc[ii][2] = ffma2(a2, wB.x, acc[ii][2]);
                acc[ii][3] = ffma2(a2, wB.y, acc[ii][3]);
            }
        }
    }
}

// stage W (Krows x 128) into SMEM [Kpad][128], zero-fill padding rows
static __device__ __forceinline__ void load_w_smem(float* Wsm, const float* __restrict__ W,
                                                   int Krows, int Kpad, int tid){
    int tot = Kpad * 32;  // float4 count
    for (int i = tid; i < tot; i += 256){
        int r = i >> 5, c4 = (i & 31) << 2;
        float4 v = make_float4(0.f, 0.f, 0.f, 0.f);
        if (r < Krows) v = *(const float4*)(W + (size_t)r * HID + c4);
        *(float4*)(Wsm + r * HID + c4) = v;
    }
}

template<int RR>
static __device__ __forceinline__ void acc_bias(float4 ba, float4 bb, unsigned long long acc[RR][4]){
    unsigned long long p0 = pk(ba.x, ba.y), p1 = pk(ba.z, ba.w);
    unsigned long long p2 = pk(bb.x, bb.y), p3 = pk(bb.z, bb.w);
    #pragma unroll
    for (int ii = 0; ii < RR; ++ii){
        acc[ii][0] = p0; acc[ii][1] = p1; acc[ii][2] = p2; acc[ii][3] = p3;
    }
}

// ---------------- projection: h = x @ pw + pb ----------------
#define SMEM_PROJ ((64*132 + 128*128) * 4)
__global__ __launch_bounds__(256) void k_proj(const float* __restrict__ x, const float* __restrict__ pw,
                                              const float* __restrict__ pb, float* __restrict__ h, int N){
    extern __shared__ float sm[];
    const int LDA = 132;
    float* As = sm;                 // 64 x 132
    float* Ws = sm + 64 * LDA;      // 128 x 128
    int tid = threadIdx.x;
    int r0  = blockIdx.x * 64;
    load_w_smem(Ws, pw, 128, 128, tid);
    {
        int i = tid >> 2, sub = tid & 3;
        int row = r0 + i;
        const float4* xr = (const float4*)(x + (size_t)(row < N ? row : 0) * HID);
        #pragma unroll
        for (int c = 0; c < 8; ++c){
            int k4 = (sub << 3) + c;
            *(float4*)(As + i * LDA + (k4 << 2)) = xr[k4];
        }
    }
    int ti = tid & 15, tj = tid >> 4;
    int i0 = tj << 2, j0 = ti << 3;
    float4 ba = *(const float4*)(pb + j0);
    float4 bb = *(const float4*)(pb + j0 + 4);
    __syncthreads();
    unsigned long long acc[4][4];
    acc_bias<4>(ba, bb, acc);
    mmK<132, 4>(As, Ws, 32, i0, j0, acc);
    #pragma unroll
    for (int ii = 0; ii < 4; ++ii){
        int row = r0 + i0 + ii;
        if (row < N){
            float* hr = h + (size_t)row * HID + j0;
            #pragma unroll
            for (int p = 0; p < 4; ++p)
                *(float2*)(hr + (p << 1)) = make_float2(lo2(acc[ii][p]), hi2(acc[ii][p]));
        }
    }
}

// ---------------- message MLP per level ----------------
// SMEM: W1s 132x128, W2s 128x128, As 64x132 (A / T / Z), sdst 64, segst 66, segd 64, nseg 1
#define SMEM_MSG ((132*128 + 128*128 + 64*132) * 4 + (64 + 66 + 64 + 2) * 4)
__global__ __launch_bounds__(256, 1) void k_msg(const float* __restrict__ h, const int* __restrict__ ei,
                                                const float* __restrict__ eattr,
                                                const float* __restrict__ mw1, const float* __restrict__ mb1,
                                                const float* __restrict__ mw2, const float* __restrict__ mb2,
                                                int E, int lvl){
    extern __shared__ float sm[];
    const int LDA = 132;
    float* W1s = sm;                         // 132 x 128 (rows 129..131 zero)
    float* W2s = W1s + 132 * HID;            // 128 x 128
    float* As  = W2s + 128 * HID;            // 64 x 132
    int* sdst  = (int*)(As + 64 * LDA);
    int* segst = sdst + 64;                  // 66
    int* segd  = segst + 66;                 // 64
    int* nsegp = segd + 64;

    int tid = threadIdx.x;
    int ti = tid & 15, tj = tid >> 4;
    int i0 = tj << 2, j0 = ti << 3;

    load_w_smem(W1s, mw1, 129, 132, tid);
    load_w_smem(W2s, mw2, 128, 128, tid);
    float4 b1a = *(const float4*)(mb1 + j0), b1b = *(const float4*)(mb1 + j0 + 4);
    float4 b2a = *(const float4*)(mb2 + j0), b2b = *(const float4*)(mb2 + j0 + 4);

    int cnt  = g_ecnt[lvl];
    int base = g_eoff[lvl];
    int ntiles = (cnt + 63) >> 6;

    for (int t = blockIdx.x; t < ntiles; t += gridDim.x){
        __syncthreads();                     // W ready / As reuse safe
        {   // gather A = [h[src] | eattr | 0 pad], dsts sorted within tile
            int i = tid >> 2, sub = tid & 3;
            int p = t * 64 + i;
            int e = (p < cnt) ? g_eperm[base + p] : -1;
            int src = (e >= 0) ? ei[e] : 0;
            const float4* hr = (const float4*)(h + (size_t)src * HID);
            #pragma unroll
            for (int c = 0; c < 8; ++c){
                int k4 = (sub << 3) + c;
                *(float4*)(As + i * LDA + (k4 << 2)) = hr[k4];
            }
            if (sub == 0){
                As[i * LDA + 128] = (e >= 0) ? eattr[e] : 0.f;
                As[i * LDA + 129] = 0.f;
                As[i * LDA + 130] = 0.f;
                As[i * LDA + 131] = 0.f;
                sdst[i] = (e >= 0) ? ei[E + e] : -1;
            }
        }
        __syncthreads();
        unsigned long long acc[4][4];
        acc_bias<4>(b1a, b1b, acc);
        mmK<132, 4>(As, W1s, 33, i0, j0, acc);   // K = 132 (padded)
        __syncthreads();
        #pragma unroll
        for (int ii = 0; ii < 4; ++ii){          // T = relu(layer1) into As cols 0..127
            float* trow = As + (i0 + ii) * LDA + j0;
            #pragma unroll
            for (int p = 0; p < 4; ++p){
                trow[2*p]   = fmaxf(lo2(acc[ii][p]), 0.f);
                trow[2*p+1] = fmaxf(hi2(acc[ii][p]), 0.f);
            }
        }
        __syncthreads();
        acc_bias<4>(b2a, b2b, acc);
        mmK<132, 4>(As, W2s, 32, i0, j0, acc);   // K = 128
        __syncthreads();
        #pragma unroll
        for (int ii = 0; ii < 4; ++ii){          // Z = relu(layer2) into As
            float* zrow = As + (i0 + ii) * LDA + j0;
            #pragma unroll
            for (int p = 0; p < 4; ++p){
                zrow[2*p]   = fmaxf(lo2(acc[ii][p]), 0.f);
                zrow[2*p+1] = fmaxf(hi2(acc[ii][p]), 0.f);
            }
        }
        if (tid == 0){                           // segment boundaries in sorted sdst
            int ns = 0, prev = -2;
            for (int i = 0; i < 64; ++i){
                int d = sdst[i];
                if (d != prev){ segst[ns] = i; segd[ns] = d; prev = d; ++ns; }
            }
            segst[ns] = 64;
            *nsegp = ns;
        }
        __syncthreads();
        {   // segmented column sums -> one atomic per (segment, col)
            int c = tid & 127, sg = tid >> 7;
            int ns = *nsegp;
            for (int s = sg; s < ns; s += 2){
                int d = segd[s];
                if (d < 0) continue;
                float ssum = 0.f;
                int r1 = segst[s + 1];
                for (int r = segst[s]; r < r1; ++r) ssum += As[r * LDA + c];
                atomicAdd(&g_agg[(size_t)d * HID + c], ssum);
            }
        }
    }
}

// ---------------- node update per level ----------------
// SMEM: W1s 256x128, W2s 128x128, As 32x260, snode 32
#define SMEM_UPD ((256*128 + 128*128 + 32*260) * 4 + 32 * 4)
__global__ __launch_bounds__(256, 1) void k_upd(float* __restrict__ h,
                                                const float* __restrict__ uw1, const float* __restrict__ ub1,
                                                const float* __restrict__ uw2, const float* __restrict__ ub2,
                                                int lvl){
    extern __shared__ float sm[];
    const int LDA = 260;
    float* W1s = sm;                         // 256 x 128
    float* W2s = W1s + 256 * HID;            // 128 x 128
    float* As  = W2s + 128 * HID;            // 32 x 260
    int* snode = (int*)(As + 32 * LDA);

    int tid = threadIdx.x;
    int ti = tid & 15, tj = tid >> 4;
    int i0 = tj << 1, j0 = ti << 3;          // 2 rows x 8 cols per thread

    load_w_smem(W1s, uw1, 256, 256, tid);
    load_w_smem(W2s, uw2, 128, 128, tid);
    float4 b1a = *(const float4*)(ub1 + j0), b1b = *(const float4*)(ub1 + j0 + 4);
    float4 b2a = *(const float4*)(ub2 + j0), b2b = *(const float4*)(ub2 + j0 + 4);

    int cnt  = g_ncnt[lvl];
    int base = g_noff[lvl];
    int ntiles = (cnt + 31) >> 5;

    for (int t = blockIdx.x; t < ntiles; t += gridDim.x){
        __syncthreads();
        {   // gather A = [h[v] | agg[v] * inv[v]]
            int i = tid >> 3, sub = tid & 7;
            int p = t * 32 + i;
            int v = (p < cnt) ? g_nperm[base + p] : 0;
            float inv = g_inv[v];
            const float4* hr = (const float4*)(h + (size_t)v * HID);
            const float4* ar = (const float4*)(g_agg + (size_t)v * HID);
            #pragma unroll
            for (int c = 0; c < 8; ++c){
                int k4 = (sub << 3) + c;     // 0..63
                if (k4 < 32){
                    *(float4*)(As + i * LDA + (k4 << 2)) = hr[k4];
                } else {
                    float4 a = ar[k4 - 32];
                    a.x *= inv; a.y *= inv; a.z *= inv; a.w *= inv;
                    *(float4*)(As + i * LDA + (k4 << 2)) = a;
                }
            }
            if (sub == 0) snode[i] = (p < cnt) ? v : -1;
        }
        __syncthreads();
        unsigned long long acc[2][4];
        acc_bias<2>(b1a, b1b, acc);
        mmK<260, 2>(As, W1s, 64, i0, j0, acc);   // K = 256
        __syncthreads();
        #pragma unroll
        for (int ii = 0; ii < 2; ++ii){
            float* trow = As + (i0 + ii) * LDA + j0;
            #pragma unroll
            for (int p = 0; p < 4; ++p){
                trow[2*p]   = fmaxf(lo2(acc[ii][p]), 0.f);
                trow[2*p+1] = fmaxf(hi2(acc[ii][p]), 0.f);
            }
        }
        __syncthreads();
        acc_bias<2>(b2a, b2b, acc);
        mmK<260, 2>(As, W2s, 32, i0, j0, acc);   // K = 128
        #pragma unroll
        for (int ii = 0; ii < 2; ++ii){
            int v = snode[i0 + ii];
            if (v >= 0){
                float* hr = h + (size_t)v * HID + j0;
                #pragma unroll
                for (int p = 0; p < 4; ++p)
                    *(float2*)(hr + (p << 1)) = make_float2(fmaxf(lo2(acc[ii][p]), 0.f),
                                                            fmaxf(hi2(acc[ii][p]), 0.f));
            }
        }
    }
}

// ---------------- host launch ----------------
extern "C" void kernel_launch(void* const* d_in, const int* in_sizes, int n_in,
                              void* d_out, int out_size){
    const float* x     = (const float*)d_in[0];
    const int*   ei    = (const int*)  d_in[1];
    const float* eattr = (const float*)d_in[2];
    const int*   depth = (const int*)  d_in[3];
    const float* pw    = (const float*)d_in[4];
    const float* pb    = (const float*)d_in[5];
    const float* mw1   = (const float*)d_in[6];
    const float* mb1   = (const float*)d_in[7];
    const float* mw2   = (const float*)d_in[8];
    const float* mb2   = (const float*)d_in[9];
    const float* uw1   = (const float*)d_in[10];
    const float* ub1   = (const float*)d_in[11];
    const float* uw2   = (const float*)d_in[12];
    const float* ub2   = (const float*)d_in[13];
    float* h = (float*)d_out;

    int N = in_sizes[3];
    int E = in_sizes[2];

    static int sms = 0;
    if (sms == 0){
        cudaDeviceGetAttribute(&sms, cudaDevAttrMultiProcessorCount, 0);
        if (sms <= 0) sms = 148;
        cudaFuncSetAttribute(k_proj, cudaFuncAttributeMaxDynamicSharedMemorySize, SMEM_PROJ);
        cudaFuncSetAttribute(k_msg,  cudaFuncAttributeMaxDynamicSharedMemorySize, SMEM_MSG);
        cudaFuncSetAttribute(k_upd,  cudaFuncAttributeMaxDynamicSharedMemorySize, SMEM_UPD);
    }

    k_zero<<<1024, 256>>>(N * HID, N);

    int mx = (E > N) ? E : N;
    int gbE = (mx + 255) / 256;
    int gbN = (N + 255) / 256;
    k_count<<<gbE, 256>>>(ei, depth, N, E);
    k_nscan<<<1, 1>>>();
    k_snodes<<<gbN, 256>>>(depth, N);
    k_escan1<<<256, 256>>>(N);
    k_escan2<<<1, 256>>>();
    k_escan3<<<256, 256>>>(N);
    k_levels<<<1, 1>>>(N, E);
    k_sedges<<<(E + 255) / 256, 256>>>(ei, E);

    k_proj<<<(N + 63) / 64, 256, SMEM_PROJ>>>(x, pw, pb, h, N);

    for (int d = 1; d <= 4; ++d){
        k_msg<<<sms, 256, SMEM_MSG>>>(h, ei, eattr, mw1, mb1, mw2, mb2, E, d);
        k_upd<<<sms, 256, SMEM_UPD>>>(h, uw1, ub1, uw2, ub2, d);
    }
}

// round 8
// speedup vs baseline: 2.0452x; 1.8211x over previous
#include <cuda_runtime.h>

typedef unsigned int u32;
typedef unsigned long long u64;
typedef unsigned short u16;

#define HID 128
#define NMAX 50000
#define EMAX 500000

// ---------------- device scratch ----------------
__device__ float g_agg[(size_t)NMAX * HID];
__device__ float g_inv[NMAX];
__device__ int   g_indeg[NMAX];
__device__ int   g_eperm[EMAX];
__device__ int   g_nperm[NMAX];
__device__ int   g_rank[NMAX];
__device__ int   g_nodeoff[NMAX];
__device__ int   g_nodecur[NMAX];
__device__ int   g_partial[256];
__device__ int   g_ecnt[8], g_eoff[8];
__device__ int   g_ncnt[8], g_noff[8], g_ncur[8];
// bf16 hi/lo images of h
__device__ u16   g_hh[(size_t)NMAX * HID];
__device__ u16   g_hl[(size_t)NMAX * HID];
// weight images, [n][k] row-major bf16 hi/lo
__device__ u16   g_w1h[16384], g_w1l[16384], g_w2h[16384], g_w2l[16384];

// ---------------- f32x2 helpers (FFMA path) ----------------
static __device__ __forceinline__ u64 pk(float x, float y){
    u64 r; asm("mov.b64 %0, {%1, %2};" : "=l"(r) : "f"(x), "f"(y)); return r;
}
static __device__ __forceinline__ u64 pk2(float a){ return pk(a, a); }
static __device__ __forceinline__ u64 ffma2(u64 a, u64 b, u64 c){
    u64 d; asm("fma.rn.f32x2 %0, %1, %2, %3;" : "=l"(d) : "l"(a), "l"(b), "l"(c)); return d;
}
static __device__ __forceinline__ float lo2(u64 v){ return __uint_as_float((u32)v); }
static __device__ __forceinline__ float hi2(u64 v){ return __uint_as_float((u32)(v >> 32)); }
// packed bf16x2: low half = f0
static __device__ __forceinline__ u32 bf2(float f0, float f1){
    u32 r; asm("cvt.rn.bf16x2.f32 %0, %1, %2;" : "=r"(r) : "f"(f1), "f"(f0)); return r;
}
static __device__ __forceinline__ u32 s2u(const void* p){
    u32 a; asm("{ .reg .u64 t; cvta.to.shared.u64 t, %1; cvt.u32.u64 %0, t; }" : "=r"(a) : "l"(p));
    return a;
}

// ---------------- HMMA helpers ----------------
#define LDX4(r, a) \
    asm volatile("ldmatrix.sync.aligned.m8n8.x4.shared.b16 {%0,%1,%2,%3}, [%4];" \
        : "=r"((r)[0]), "=r"((r)[1]), "=r"((r)[2]), "=r"((r)[3]) : "r"(a))

#define MMA(d, a, b0, b1) \
    asm("mma.sync.aligned.m16n8k16.row.col.f32.bf16.bf16.f32 " \
        "{%0,%1,%2,%3}, {%4,%5,%6,%7}, {%8,%9}, {%0,%1,%2,%3};" \
        : "+f"((d)[0]), "+f"((d)[1]), "+f"((d)[2]), "+f"((d)[3]) \
        : "r"((a)[0]), "r"((a)[1]), "r"((a)[2]), "r"((a)[3]), "r"(b0), "r"(b1))

// ---------------- bucketing ----------------
__global__ void k_zero(int nagg, int N){
    int i  = blockIdx.x * blockDim.x + threadIdx.x;
    int st = gridDim.x * blockDim.x;
    for (int j = i; j < nagg; j += st) g_agg[j] = 0.f;
    for (int j = i; j < N;    j += st) g_indeg[j] = 0;
    if (i < 8) g_ncnt[i] = 0;
}

__global__ void k_count(const int* __restrict__ ei, const int* __restrict__ depth, int N, int E){
    __shared__ int scnt[8];
    int t = threadIdx.x;
    if (t < 8) scnt[t] = 0;
    __syncthreads();
    int i = blockIdx.x * blockDim.x + t;
    if (i < E) atomicAdd(&g_indeg[ei[E + i]], 1);
    if (i < N) atomicAdd(&scnt[depth[i]], 1);
    __syncthreads();
    if (t < 8 && scnt[t]) atomicAdd(&g_ncnt[t], scnt[t]);
}

__global__ void k_nscan(){
    int n = 0;
    for (int d = 0; d < 8; ++d){ g_noff[d] = n; g_ncur[d] = n; n += g_ncnt[d]; }
}

__global__ void k_snodes(const int* __restrict__ depth, int N){
    __shared__ int scnt[8], sbase[8];
    int t = threadIdx.x;
    if (t < 8) scnt[t] = 0;
    __syncthreads();
    int i = blockIdx.x * blockDim.x + t;
    int d = 0, pl = 0;
    if (i < N){ d = depth[i]; pl = atomicAdd(&scnt[d], 1); }
    __syncthreads();
    if (t < 8) sbase[t] = scnt[t] ? atomicAdd(&g_ncur[t], scnt[t]) : 0;
    __syncthreads();
    if (i < N){
        int pos = sbase[d] + pl;
        g_nperm[pos] = i;
        g_rank[i] = pos;
        int c = g_indeg[i];
        g_inv[i] = 1.0f / (float)(c > 0 ? c : 1);
    }
}

__global__ void k_escan1(int N){
    __shared__ int sh[256];
    int chunk = (N + 255) / 256;
    int t = threadIdx.x;
    int i = blockIdx.x * chunk + t;
    int v = 0;
    if (t < chunk && i < N) v = g_indeg[g_nperm[i]];
    sh[t] = v; __syncthreads();
    for (int s = 128; s > 0; s >>= 1){
        if (t < s) sh[t] += sh[t + s];
        __syncthreads();
    }
    if (t == 0) g_partial[blockIdx.x] = sh[0];
}
__global__ void k_escan2(){
    __shared__ int sh[256];
    int t = threadIdx.x;
    int orig = g_partial[t];
    sh[t] = orig; __syncthreads();
    for (int s = 1; s < 256; s <<= 1){
        int v = (t >= s) ? sh[t - s] : 0;
        __syncthreads();
        sh[t] += v;
        __syncthreads();
    }
    g_partial[t] = sh[t] - orig;
}
__global__ void k_escan3(int N){
    __shared__ int sh[256];
    int chunk = (N + 255) / 256;
    int t = threadIdx.x;
    int i = blockIdx.x * chunk + t;
    int orig = 0;
    if (t < chunk && i < N) orig = g_indeg[g_nperm[i]];
    sh[t] = orig; __syncthreads();
    for (int s = 1; s < 256; s <<= 1){
        int v = (t >= s) ? sh[t - s] : 0;
        __syncthreads();
        sh[t] += v;
        __syncthreads();
    }
    if (t < chunk && i < N){
        int excl = g_partial[blockIdx.x] + sh[t] - orig;
        g_nodeoff[i] = excl;
        g_nodecur[i] = excl;
    }
}
__global__ void k_levels(int N, int E){
    for (int d = 0; d < 8; ++d){
        int b0 = g_noff[d];
        int b1 = b0 + g_ncnt[d];
        int o0 = (b0 < N) ? g_nodeoff[b0] : E;
        int o1 = (b1 < N) ? g_nodeoff[b1] : E;
        g_eoff[d] = o0; g_ecnt[d] = o1 - o0;
    }
}
__global__ void k_sedges(const int* __restrict__ ei, int E){
    int e = blockIdx.x * blockDim.x + threadIdx.x;
    if (e < E){
        int dst = ei[E + e];
        int pos = atomicAdd(&g_nodecur[g_rank[dst]], 1);
        g_eperm[pos] = e;
    }
}

// ---------------- weight image prep: [n][k] = W[k][n], bf16 hi/lo ----------------
__global__ void k_prep(const float* __restrict__ mw1, const float* __restrict__ mw2){
    int idx = blockIdx.x * blockDim.x + threadIdx.x;
    if (idx >= 32768) return;
    int mtx = idx >> 14;
    int rem = idx & 16383;
    int n = rem >> 7, k = rem & 127;
    const float* W = mtx ? mw2 : mw1;
    float v = W[k * HID + n];
    u16 hu; asm("cvt.rn.bf16.f32 %0, %1;" : "=h"(hu) : "f"(v));
    float hf = __uint_as_float(((u32)hu) << 16);
    u16 lu; asm("cvt.rn.bf16.f32 %0, %1;" : "=h"(lu) : "f"(v - hf));
    (mtx ? g_w2h : g_w1h)[n * HID + k] = hu;
    (mtx ? g_w2l : g_w1l)[n * HID + k] = lu;
}

// ---------------- FFMA GEMM pieces (proj / upd) ----------------
template<int LDA, int RR>
static __device__ __forceinline__ void mmK(const float* __restrict__ A, const float* __restrict__ W,
                                           int K4, int i0, int j0, u64 acc[RR][4]){
    for (int c = 0; c < K4; ++c){
        float4 av[RR];
        #pragma unroll
        for (int ii = 0; ii < RR; ++ii)
            av[ii] = *(const float4*)(A + (i0 + ii) * LDA + (c << 2));
        const float* wr = W + (c << 2) * HID + j0;
        #pragma unroll
        for (int q = 0; q < 4; ++q){
            ulonglong2 wA = *(const ulonglong2*)(wr + q * HID);
            ulonglong2 wB = *(const ulonglong2*)(wr + q * HID + 4);
            #pragma unroll
            for (int ii = 0; ii < RR; ++ii){
                float aq = (q == 0) ? av[ii].x : (q == 1) ? av[ii].y : (q == 2) ? av[ii].z : av[ii].w;
                u64 a2 = pk2(aq);
                acc[ii][0] = ffma2(a2, wA.x, acc[ii][0]);
                acc[ii][1] = ffma2(a2, wA.y, acc[ii][1]);
                acc[ii][2] = ffma2(a2, wB.x, acc[ii][2]);
                acc[ii][3] = ffma2(a2, wB.y, acc[ii][3]);
            }
        }
    }
}

static __device__ __forceinline__ void load_w_smem(float* Wsm, const float* __restrict__ W,
                                                   int Krows, int Kpad, int tid){
    int tot = Kpad * 32;
    for (int i = tid; i < tot; i += 256){
        int r = i >> 5, c4 = (i & 31) << 2;
        float4 v = make_float4(0.f, 0.f, 0.f, 0.f);
        if (r < Krows) v = *(const float4*)(W + (size_t)r * HID + c4);
        *(float4*)(Wsm + r * HID + c4) = v;
    }
}

template<int RR>
static __device__ __forceinline__ void acc_bias(float4 ba, float4 bb, u64 acc[RR][4]){
    u64 p0 = pk(ba.x, ba.y), p1 = pk(ba.z, ba.w);
    u64 p2 = pk(bb.x, bb.y), p3 = pk(bb.z, bb.w);
    #pragma unroll
    for (int ii = 0; ii < RR; ++ii){
        acc[ii][0] = p0; acc[ii][1] = p1; acc[ii][2] = p2; acc[ii][3] = p3;
    }
}

// write 8 cols (j0..j0+7) of row's hi/lo bf16 image
static __device__ __forceinline__ void write_img(int row, int j0, const float f[8]){
    u32 hp[4], lp[4];
    #pragma unroll
    for (int p = 0; p < 4; ++p){
        float f0 = f[2*p], f1 = f[2*p+1];
        u32 h = bf2(f0, f1);
        float h0 = __uint_as_float(h << 16);
        float h1 = __uint_as_float(h & 0xffff0000u);
        hp[p] = h;
        lp[p] = bf2(f0 - h0, f1 - h1);
    }
    *(uint4*)(&g_hh[(size_t)row * HID + j0]) = make_uint4(hp[0], hp[1], hp[2], hp[3]);
    *(uint4*)(&g_hl[(size_t)row * HID + j0]) = make_uint4(lp[0], lp[1], lp[2], lp[3]);
}

// ---------------- projection ----------------
#define SMEM_PROJ ((64*132 + 128*128) * 4)
__global__ __launch_bounds__(256) void k_proj(const float* __restrict__ x, const float* __restrict__ pw,
                                              const float* __restrict__ pb, float* __restrict__ h, int N){
    extern __shared__ float sm[];
    const int LDA = 132;
    float* As = sm;
    float* Ws = sm + 64 * LDA;
    int tid = threadIdx.x;
    int r0  = blockIdx.x * 64;
    load_w_smem(Ws, pw, 128, 128, tid);
    {
        int i = tid >> 2, sub = tid & 3;
        int row = r0 + i;
        const float4* xr = (const float4*)(x + (size_t)(row < N ? row : 0) * HID);
        #pragma unroll
        for (int c = 0; c < 8; ++c){
            int k4 = (sub << 3) + c;
            *(float4*)(As + i * LDA + (k4 << 2)) = xr[k4];
        }
    }
    int ti = tid & 15, tj = tid >> 4;
    int i0 = tj << 2, j0 = ti << 3;
    float4 ba = *(const float4*)(pb + j0);
    float4 bb = *(const float4*)(pb + j0 + 4);
    __syncthreads();
    u64 acc[4][4];
    acc_bias<4>(ba, bb, acc);
    mmK<132, 4>(As, Ws, 32, i0, j0, acc);
    #pragma unroll
    for (int ii = 0; ii < 4; ++ii){
        int row = r0 + i0 + ii;
        if (row < N){
            float* hr = h + (size_t)row * HID + j0;
            float f[8];
            #pragma unroll
            for (int p = 0; p < 4; ++p){
                f[2*p] = lo2(acc[ii][p]); f[2*p+1] = hi2(acc[ii][p]);
                *(float2*)(hr + (p << 1)) = make_float2(f[2*p], f[2*p+1]);
            }
            write_img(row, j0, f);
        }
    }
}

// ---------------- message MLP: HMMA bf16 hi/lo 3-term ----------------
// SMEM bytes: A/T/stage region 0..69631 (Ah [128][136]bf16 at 0, Al at 34816; stage f32 [128][136])
// W1h 69632, W1l 104448, W2h 139264, W2l 174080 (each [128][136] bf16)
// sdst 208896 (512), seattr 209408 (512), b1 209920, b2 210432, wls 210944
#define AOFF   0
#define ALOFF  34816
#define W1HOFF 69632
#define W2HOFF 139264
#define SDOFF  208896
#define SMEM_MSG 211456

__global__ __launch_bounds__(256, 1) void k_msg(const int* __restrict__ ei, const float* __restrict__ eattr,
                                                const float* __restrict__ mw1, const float* __restrict__ mb1,
                                                const float* __restrict__ mb2, int E, int lvl){
    extern __shared__ char smc[];
    u32 smb = s2u(smc);
    int tid = threadIdx.x, wid = tid >> 5, lane = tid & 31;

    int*   sdst   = (int*)  (smc + SDOFF);
    float* seat   = (float*)(smc + SDOFF + 512);
    float* b1s    = (float*)(smc + SDOFF + 1024);
    float* b2s    = (float*)(smc + SDOFF + 1536);
    float* wls    = (float*)(smc + SDOFF + 2048);
    float* stagef = (float*)(smc);

    // stage weight images ([n][k] -> [128][136] padded rows)
    for (int i = tid; i < 2048; i += 256){
        int n = i >> 4, kc = i & 15;
        u32 off = (u32)n * 272 + (u32)kc * 16;
        *(uint4*)(smc + W1HOFF + off)          = ((const uint4*)g_w1h)[i];
        *(uint4*)(smc + W1HOFF + 34816 + off)  = ((const uint4*)g_w1l)[i];
        *(uint4*)(smc + W2HOFF + off)          = ((const uint4*)g_w2h)[i];
        *(uint4*)(smc + W2HOFF + 34816 + off)  = ((const uint4*)g_w2l)[i];
    }
    if (tid < 128){
        b1s[tid] = mb1[tid];
        b2s[tid] = mb2[tid];
        wls[tid] = mw1[128 * HID + tid];
    }
    __syncthreads();

    int cnt  = g_ecnt[lvl];
    int base = g_eoff[lvl];
    int ntiles = (cnt + 127) >> 7;

    for (int t = blockIdx.x; t < ntiles; t += gridDim.x){
        // ---- gather A = bf16 hi/lo of h[src]; sdst/seattr ----
        {
            int m = tid >> 1, half = tid & 1;
            int p = t * 128 + m;
            int e = (p < cnt) ? g_eperm[base + p] : -1;
            int src = (e >= 0) ? ei[e] : 0;
            if (half == 0){
                sdst[m] = (e >= 0) ? ei[E + e] : -1;
                seat[m] = (e >= 0) ? eattr[e] : 0.f;
            }
            const uint4* hh = (const uint4*)(&g_hh[(size_t)src * HID]) + half * 8;
            const uint4* hl = (const uint4*)(&g_hl[(size_t)src * HID]) + half * 8;
            u32 bo = (u32)m * 272 + (u32)half * 128;
            #pragma unroll
            for (int j = 0; j < 8; ++j){
                *(uint4*)(smc + AOFF  + bo + j * 16) = hh[j];
                *(uint4*)(smc + ALOFF + bo + j * 16) = hl[j];
            }
        }
        __syncthreads();

        // per-warp fragment bases
        u32 afrag = smb + AOFF + (u32)(wid * 16 + (lane & 15)) * 272 + (u32)((lane >> 4) * 16);
        int ra = wid * 16 + (lane >> 2);
        int rb = ra + 8;
        u32 ah[8][4], al[8][4];

        // ---- layer 1 ----
        #pragma unroll
        for (int kc = 0; kc < 8; ++kc){
            LDX4(ah[kc], afrag + kc * 32);
            LDX4(al[kc], afrag + 34816 + kc * 32);
        }
        float ea_a = seat[ra], ea_b = seat[rb];
        u32 wfrag = smb + W1HOFF + (u32)(((lane >> 4) << 3) + (lane & 7)) * 272 + (u32)(((lane >> 3) & 1) << 4);
        #pragma unroll
        for (int np = 0; np < 8; ++np){
            float acc0[4] = {0,0,0,0}, acc1[4] = {0,0,0,0};
            u32 wb = wfrag + (u32)np * 16 * 272;
            #pragma unroll
            for (int kc = 0; kc < 8; ++kc){
                u32 bh[4], bl[4];
                LDX4(bh, wb + kc * 32);
                LDX4(bl, wb + 34816 + kc * 32);
                MMA(acc0, ah[kc], bh[0], bh[1]);
                MMA(acc0, al[kc], bh[0], bh[1]);
                MMA(acc0, ah[kc], bl[0], bl[1]);
                MMA(acc1, ah[kc], bh[2], bh[3]);
                MMA(acc1, al[kc], bh[2], bh[3]);
                MMA(acc1, ah[kc], bl[2], bl[3]);
            }
            #pragma unroll
            for (int nch = 0; nch < 2; ++nch){
                const float* a = nch ? acc1 : acc0;
                int c = np * 16 + nch * 8 + 2 * (lane & 3);
                float w0 = wls[c], w1v = wls[c+1], bb0 = b1s[c], bb1 = b1s[c+1];
                float v0 = fmaxf(a[0] + bb0 + ea_a * w0,  0.f);
                float v1 = fmaxf(a[1] + bb1 + ea_a * w1v, 0.f);
                u32 hp = bf2(v0, v1);
                u32 lp = bf2(v0 - __uint_as_float(hp << 16), v1 - __uint_as_float(hp & 0xffff0000u));
                *(u32*)(smc + AOFF  + ra * 272 + c * 2) = hp;
                *(u32*)(smc + ALOFF + ra * 272 + c * 2) = lp;
                v0 = fmaxf(a[2] + bb0 + ea_b * w0,  0.f);
                v1 = fmaxf(a[3] + bb1 + ea_b * w1v, 0.f);
                hp = bf2(v0, v1);
                lp = bf2(v0 - __uint_as_float(hp << 16), v1 - __uint_as_float(hp & 0xffff0000u));
                *(u32*)(smc + AOFF  + rb * 272 + c * 2) = hp;
                *(u32*)(smc + ALOFF + rb * 272 + c * 2) = lp;
            }
        }
        __syncwarp();
        // reload T fragments (own rows only)
        #pragma unroll
        for (int kc = 0; kc < 8; ++kc){
            LDX4(ah[kc], afrag + kc * 32);
            LDX4(al[kc], afrag + 34816 + kc * 32);
        }
        __syncthreads();   // all T in regs; A region becomes float stage

        // ---- layer 2 ----
        u32 wfrag2 = smb + W2HOFF + (u32)(((lane >> 4) << 3) + (lane & 7)) * 272 + (u32)(((lane >> 3) & 1) << 4);
        #pragma unroll
        for (int np = 0; np < 8; ++np){
            float acc0[4] = {0,0,0,0}, acc1[4] = {0,0,0,0};
            u32 wb = wfrag2 + (u32)np * 16 * 272;
            #pragma unroll
            for (int kc = 0; kc < 8; ++kc){
                u32 bh[4], bl[4];
                LDX4(bh, wb + kc * 32);
                LDX4(bl, wb + 34816 + kc * 32);
                MMA(acc0, ah[kc], bh[0], bh[1]);
                MMA(acc0, al[kc], bh[0], bh[1]);
                MMA(acc0, ah[kc], bl[0], bl[1]);
                MMA(acc1, ah[kc], bh[2], bh[3]);
                MMA(acc1, al[kc], bh[2], bh[3]);
                MMA(acc1, ah[kc], bl[2], bl[3]);
            }
            #pragma unroll
            for (int nch = 0; nch < 2; ++nch){
                const float* a = nch ? acc1 : acc0;
                int c = np * 16 + nch * 8 + 2 * (lane & 3);
                float bb0 = b2s[c], bb1 = b2s[c+1];
                stagef[ra * 136 + c]     = fmaxf(a[0] + bb0, 0.f);
                stagef[ra * 136 + c + 1] = fmaxf(a[1] + bb1, 0.f);
                stagef[rb * 136 + c]     = fmaxf(a[2] + bb0, 0.f);
                stagef[rb * 136 + c + 1] = fmaxf(a[3] + bb1, 0.f);
            }
        }
        __syncthreads();

        // ---- segmented flush (dst-sorted rows) ----
        {
            int c = tid & 127, hf = tid >> 7;
            int r0 = hf * 64;
            float run = 0.f;
            int prev = sdst[r0];
            for (int r = 0; r < 64; ++r){
                int d = sdst[r0 + r];
                float v = stagef[(r0 + r) * 136 + c];
                if (d != prev){
                    if (prev >= 0) atomicAdd(&g_agg[(size_t)prev * HID + c], run);
                    run = 0.f;
                    prev = d;
                }
                run += v;
            }
            if (prev >= 0) atomicAdd(&g_agg[(size_t)prev * HID + c], run);
        }
        __syncthreads();
    }
}

// ---------------- node update (FFMA, persistent weights) ----------------
#define SMEM_UPD ((256*128 + 128*128 + 32*260) * 4 + 32 * 4)
__global__ __launch_bounds__(256, 1) void k_upd(float* __restrict__ h,
                                                const float* __restrict__ uw1, const float* __restrict__ ub1,
                                                const float* __restrict__ uw2, const float* __restrict__ ub2,
                                                int lvl){
    extern __shared__ float sm[];
    const int LDA = 260;
    float* W1s = sm;
    float* W2s = W1s + 256 * HID;
    float* As  = W2s + 128 * HID;
    int* snode = (int*)(As + 32 * LDA);

    int tid = threadIdx.x;
    int ti = tid & 15, tj = tid >> 4;
    int i0 = tj << 1, j0 = ti << 3;

    load_w_smem(W1s, uw1, 256, 256, tid);
    load_w_smem(W2s, uw2, 128, 128, tid);
    float4 b1a = *(const float4*)(ub1 + j0), b1b = *(const float4*)(ub1 + j0 + 4);
    float4 b2a = *(const float4*)(ub2 + j0), b2b = *(const float4*)(ub2 + j0 + 4);

    int cnt  = g_ncnt[lvl];
    int base = g_noff[lvl];
    int ntiles = (cnt + 31) >> 5;

    for (int t = blockIdx.x; t < ntiles; t += gridDim.x){
        __syncthreads();
        {
            int i = tid >> 3, sub = tid & 7;
            int p = t * 32 + i;
            int v = (p < cnt) ? g_nperm[base + p] : 0;
            float inv = g_inv[v];
            const float4* hr = (const float4*)(h + (size_t)v * HID);
            const float4* ar = (const float4*)(g_agg + (size_t)v * HID);
            #pragma unroll
            for (int c = 0; c < 8; ++c){
                int k4 = (sub << 3) + c;
                if (k4 < 32){
                    *(float4*)(As + i * LDA + (k4 << 2)) = hr[k4];
                } else {
                    float4 a = ar[k4 - 32];
                    a.x *= inv; a.y *= inv; a.z *= inv; a.w *= inv;
                    *(float4*)(As + i * LDA + (k4 << 2)) = a;
                }
            }
            if (sub == 0) snode[i] = (p < cnt) ? v : -1;
        }
        __syncthreads();
        u64 acc[2][4];
        acc_bias<2>(b1a, b1b, acc);
        mmK<260, 2>(As, W1s, 64, i0, j0, acc);
        __syncthreads();
        #pragma unroll
        for (int ii = 0; ii < 2; ++ii){
            float* trow = As + (i0 + ii) * LDA + j0;
            #pragma unroll
            for (int p = 0; p < 4; ++p){
                trow[2*p]   = fmaxf(lo2(acc[ii][p]), 0.f);
                trow[2*p+1] = fmaxf(hi2(acc[ii][p]), 0.f);
            }
        }
        __syncthreads();
        acc_bias<2>(b2a, b2b, acc);
        mmK<260, 2>(As, W2s, 32, i0, j0, acc);
        #pragma unroll
        for (int ii = 0; ii < 2; ++ii){
            int v = snode[i0 + ii];
            if (v >= 0){
                float* hr = h + (size_t)v * HID + j0;
                float f[8];
                #pragma unroll
                for (int p = 0; p < 4; ++p){
                    f[2*p]   = fmaxf(lo2(acc[ii][p]), 0.f);
                    f[2*p+1] = fmaxf(hi2(acc[ii][p]), 0.f);
                    *(float2*)(hr + (p << 1)) = make_float2(f[2*p], f[2*p+1]);
                }
                write_img(v, j0, f);
            }
        }
    }
}

// ---------------- host launch ----------------
extern "C" void kernel_launch(void* const* d_in, const int* in_sizes, int n_in,
                              void* d_out, int out_size){
    const float* x     = (const float*)d_in[0];
    const int*   ei    = (const int*)  d_in[1];
    const float* eattr = (const float*)d_in[2];
    const int*   depth = (const int*)  d_in[3];
    const float* pw    = (const float*)d_in[4];
    const float* pb    = (const float*)d_in[5];
    const float* mw1   = (const float*)d_in[6];
    const float* mb1   = (const float*)d_in[7];
    const float* mw2   = (const float*)d_in[8];
    const float* mb2   = (const float*)d_in[9];
    const float* uw1   = (const float*)d_in[10];
    const float* ub1   = (const float*)d_in[11];
    const float* uw2   = (const float*)d_in[12];
    const float* ub2   = (const float*)d_in[13];
    float* h = (float*)d_out;

    int N = in_sizes[3];
    int E = in_sizes[2];

    static int sms = 0;
    if (sms == 0){
        cudaDeviceGetAttribute(&sms, cudaDevAttrMultiProcessorCount, 0);
        if (sms <= 0) sms = 148;
        cudaFuncSetAttribute(k_proj, cudaFuncAttributeMaxDynamicSharedMemorySize, SMEM_PROJ);
        cudaFuncSetAttribute(k_msg,  cudaFuncAttributeMaxDynamicSharedMemorySize, SMEM_MSG);
        cudaFuncSetAttribute(k_upd,  cudaFuncAttributeMaxDynamicSharedMemorySize, SMEM_UPD);
    }

    k_zero<<<1024, 256>>>(N * HID, N);
    k_prep<<<128, 256>>>(mw1, mw2);

    int mx = (E > N) ? E : N;
    k_count<<<(mx + 255) / 256, 256>>>(ei, depth, N, E);
    k_nscan<<<1, 1>>>();
    k_snodes<<<(N + 255) / 256, 256>>>(depth, N);
    k_escan1<<<256, 256>>>(N);
    k_escan2<<<1, 256>>>();
    k_escan3<<<256, 256>>>(N);
    k_levels<<<1, 1>>>(N, E);
    k_sedges<<<(E + 255) / 256, 256>>>(ei, E);

    k_proj<<<(N + 63) / 64, 256, SMEM_PROJ>>>(x, pw, pb, h, N);

    for (int d = 1; d <= 4; ++d){
        k_msg<<<sms, 256, SMEM_MSG>>>(ei, eattr, mw1, mb1, mb2, E, d);
        k_upd<<<sms, 256, SMEM_UPD>>>(h, uw1, ub1, uw2, ub2, d);
    }
}

// round 10
// speedup vs baseline: 2.4060x; 1.1764x over previous
#include <cuda_runtime.h>
#include <cuda_fp16.h>

typedef unsigned int u32;
typedef unsigned long long u64;
typedef unsigned short u16;

#define HID 128
#define NMAX 50000
#define EMAX 500000

// ---------------- device scratch ----------------
__device__ float g_agg[(size_t)NMAX * HID];
__device__ float g_inv[NMAX];
__device__ int   g_indeg[NMAX];
__device__ int   g_eperm[EMAX];
__device__ int   g_nperm[NMAX];
__device__ int   g_rank[NMAX];
__device__ int   g_nodeoff[NMAX];
__device__ int   g_nodecur[NMAX];
__device__ int   g_partial[256];
__device__ int   g_ecnt[8], g_eoff[8];
__device__ int   g_ncnt[8], g_noff[8], g_ncur[8];
// fp16 image of h
__device__ u16   g_hf[(size_t)NMAX * HID];
// weight images, [n][k] row-major: fp16 hi, fp16 lo (lo pre-scaled by 2048)
__device__ u16   g_w1h[16384], g_w1l[16384], g_w2h[16384], g_w2l[16384];

// ---------------- f32x2 helpers (FFMA path) ----------------
static __device__ __forceinline__ u64 pk(float x, float y){
    u64 r; asm("mov.b64 %0, {%1, %2};" : "=l"(r) : "f"(x), "f"(y)); return r;
}
static __device__ __forceinline__ u64 pk2(float a){ return pk(a, a); }
static __device__ __forceinline__ u64 ffma2(u64 a, u64 b, u64 c){
    u64 d; asm("fma.rn.f32x2 %0, %1, %2, %3;" : "=l"(d) : "l"(a), "l"(b), "l"(c)); return d;
}
static __device__ __forceinline__ float lo2(u64 v){ return __uint_as_float((u32)v); }
static __device__ __forceinline__ float hi2(u64 v){ return __uint_as_float((u32)(v >> 32)); }
static __device__ __forceinline__ u32 h2pack(float f0, float f1){
    __half2 h = __floats2half2_rn(f0, f1);   // .x (low) = f0
    return *(u32*)&h;
}
static __device__ __forceinline__ u32 s2u(const void* p){
    u32 a; asm("{ .reg .u64 t; cvta.to.shared.u64 t, %1; cvt.u32.u64 %0, t; }" : "=r"(a) : "l"(p));
    return a;
}

// ---------------- HMMA helpers ----------------
#define LDX4(r, a) \
    asm volatile("ldmatrix.sync.aligned.m8n8.x4.shared.b16 {%0,%1,%2,%3}, [%4];" \
        : "=r"((r)[0]), "=r"((r)[1]), "=r"((r)[2]), "=r"((r)[3]) : "r"(a))

#define MMAH(d, a, b0, b1) \
    asm("mma.sync.aligned.m16n8k16.row.col.f32.f16.f16.f32 " \
        "{%0,%1,%2,%3}, {%4,%5,%6,%7}, {%8,%9}, {%0,%1,%2,%3};" \
        : "+f"((d)[0]), "+f"((d)[1]), "+f"((d)[2]), "+f"((d)[3]) \
        : "r"((a)[0]), "r"((a)[1]), "r"((a)[2]), "r"((a)[3]), "r"(b0), "r"(b1))

// ---------------- bucketing ----------------
__global__ void k_zero(int nagg, int N){
    int i  = blockIdx.x * blockDim.x + threadIdx.x;
    int st = gridDim.x * blockDim.x;
    for (int j = i; j < nagg; j += st) g_agg[j] = 0.f;
    for (int j = i; j < N;    j += st) g_indeg[j] = 0;
    if (i < 8) g_ncnt[i] = 0;
}

__global__ void k_count(const int* __restrict__ ei, const int* __restrict__ depth, int N, int E){
    __shared__ int scnt[8];
    int t = threadIdx.x;
    if (t < 8) scnt[t] = 0;
    __syncthreads();
    int i = blockIdx.x * blockDim.x + t;
    if (i < E) atomicAdd(&g_indeg[ei[E + i]], 1);
    if (i < N) atomicAdd(&scnt[depth[i]], 1);
    __syncthreads();
    if (t < 8 && scnt[t]) atomicAdd(&g_ncnt[t], scnt[t]);
}

__global__ void k_nscan(){
    int n = 0;
    for (int d = 0; d < 8; ++d){ g_noff[d] = n; g_ncur[d] = n; n += g_ncnt[d]; }
}

__global__ void k_snodes(const int* __restrict__ depth, int N){
    __shared__ int scnt[8], sbase[8];
    int t = threadIdx.x;
    if (t < 8) scnt[t] = 0;
    __syncthreads();
    int i = blockIdx.x * blockDim.x + t;
    int d = 0, pl = 0;
    if (i < N){ d = depth[i]; pl = atomicAdd(&scnt[d], 1); }
    __syncthreads();
    if (t < 8) sbase[t] = scnt[t] ? atomicAdd(&g_ncur[t], scnt[t]) : 0;
    __syncthreads();
    if (i < N){
        int pos = sbase[d] + pl;
        g_nperm[pos] = i;
        g_rank[i] = pos;
        int c = g_indeg[i];
        g_inv[i] = 1.0f / (float)(c > 0 ? c : 1);
    }
}

__global__ void k_escan1(int N){
    __shared__ int sh[256];
    int chunk = (N + 255) / 256;
    int t = threadIdx.x;
    int i = blockIdx.x * chunk + t;
    int v = 0;
    if (t < chunk && i < N) v = g_indeg[g_nperm[i]];
    sh[t] = v; __syncthreads();
    for (int s = 128; s > 0; s >>= 1){
        if (t < s) sh[t] += sh[t + s];
        __syncthreads();
    }
    if (t == 0) g_partial[blockIdx.x] = sh[0];
}
__global__ void k_escan2(){
    __shared__ int sh[256];
    int t = threadIdx.x;
    int orig = g_partial[t];
    sh[t] = orig; __syncthreads();
    for (int s = 1; s < 256; s <<= 1){
        int v = (t >= s) ? sh[t - s] : 0;
        __syncthreads();
        sh[t] += v;
        __syncthreads();
    }
    g_partial[t] = sh[t] - orig;
}
__global__ void k_escan3(int N){
    __shared__ int sh[256];
    int chunk = (N + 255) / 256;
    int t = threadIdx.x;
    int i = blockIdx.x * chunk + t;
    int orig = 0;
    if (t < chunk && i < N) orig = g_indeg[g_nperm[i]];
    sh[t] = orig; __syncthreads();
    for (int s = 1; s < 256; s <<= 1){
        int v = (t >= s) ? sh[t - s] : 0;
        __syncthreads();
        sh[t] += v;
        __syncthreads();
    }
    if (t < chunk && i < N){
        int excl = g_partial[blockIdx.x] + sh[t] - orig;
        g_nodeoff[i] = excl;
        g_nodecur[i] = excl;
    }
}
__global__ void k_levels(int N, int E){
    for (int d = 0; d < 8; ++d){
        int b0 = g_noff[d];
        int b1 = b0 + g_ncnt[d];
        int o0 = (b0 < N) ? g_nodeoff[b0] : E;
        int o1 = (b1 < N) ? g_nodeoff[b1] : E;
        g_eoff[d] = o0; g_ecnt[d] = o1 - o0;
    }
}
__global__ void k_sedges(const int* __restrict__ ei, int E){
    int e = blockIdx.x * blockDim.x + threadIdx.x;
    if (e < E){
        int dst = ei[E + e];
        int pos = atomicAdd(&g_nodecur[g_rank[dst]], 1);
        g_eperm[pos] = e;
    }
}

// ---------------- weight image prep: [n][k] = W[k][n], fp16 hi + scaled lo ----------------
__global__ void k_prep(const float* __restrict__ mw1, const float* __restrict__ mw2){
    int idx = blockIdx.x * blockDim.x + threadIdx.x;
    if (idx >= 32768) return;
    int mtx = idx >> 14;
    int rem = idx & 16383;
    int n = rem >> 7, k = rem & 127;
    const float* W = mtx ? mw2 : mw1;
    float v = W[k * HID + n];
    __half hh = __float2half_rn(v);
    float hf = __half2float(hh);
    __half hl = __float2half_rn((v - hf) * 2048.0f);
    (mtx ? g_w2h : g_w1h)[n * HID + k] = *(u16*)&hh;
    (mtx ? g_w2l : g_w1l)[n * HID + k] = *(u16*)&hl;
}

// ---------------- FFMA GEMM pieces (proj / upd) ----------------
template<int LDA, int RR>
static __device__ __forceinline__ void mmK(const float* __restrict__ A, const float* __restrict__ W,
                                           int K4, int i0, int j0, u64 acc[RR][4]){
    for (int c = 0; c < K4; ++c){
        float4 av[RR];
        #pragma unroll
        for (int ii = 0; ii < RR; ++ii)
            av[ii] = *(const float4*)(A + (i0 + ii) * LDA + (c << 2));
        const float* wr = W + (c << 2) * HID + j0;
        #pragma unroll
        for (int q = 0; q < 4; ++q){
            ulonglong2 wA = *(const ulonglong2*)(wr + q * HID);
            ulonglong2 wB = *(const ulonglong2*)(wr + q * HID + 4);
            #pragma unroll
            for (int ii = 0; ii < RR; ++ii){
                float aq = (q == 0) ? av[ii].x : (q == 1) ? av[ii].y : (q == 2) ? av[ii].z : av[ii].w;
                u64 a2 = pk2(aq);
                acc[ii][0] = ffma2(a2, wA.x, acc[ii][0]);
                acc[ii][1] = ffma2(a2, wA.y, acc[ii][1]);
                acc[ii][2] = ffma2(a2, wB.x, acc[ii][2]);
                acc[ii][3] = ffma2(a2, wB.y, acc[ii][3]);
            }
        }
    }
}

static __device__ __forceinline__ void load_w_smem(float* Wsm, const float* __restrict__ W,
                                                   int Krows, int Kpad, int tid){
    int tot = Kpad * 32;
    for (int i = tid; i < tot; i += 256){
        int r = i >> 5, c4 = (i & 31) << 2;
        float4 v = make_float4(0.f, 0.f, 0.f, 0.f);
        if (r < Krows) v = *(const float4*)(W + (size_t)r * HID + c4);
        *(float4*)(Wsm + r * HID + c4) = v;
    }
}

template<int RR>
static __device__ __forceinline__ void acc_bias(float4 ba, float4 bb, u64 acc[RR][4]){
    u64 p0 = pk(ba.x, ba.y), p1 = pk(ba.z, ba.w);
    u64 p2 = pk(bb.x, bb.y), p3 = pk(bb.z, bb.w);
    #pragma unroll
    for (int ii = 0; ii < RR; ++ii){
        acc[ii][0] = p0; acc[ii][1] = p1; acc[ii][2] = p2; acc[ii][3] = p3;
    }
}

// write 8 cols (j0..j0+7) of row's fp16 image
static __device__ __forceinline__ void write_imgh(int row, int j0, const float f[8]){
    u32 p0 = h2pack(f[0], f[1]);
    u32 p1 = h2pack(f[2], f[3]);
    u32 p2 = h2pack(f[4], f[5]);
    u32 p3 = h2pack(f[6], f[7]);
    *(uint4*)(&g_hf[(size_t)row * HID + j0]) = make_uint4(p0, p1, p2, p3);
}

// ---------------- projection ----------------
#define SMEM_PROJ ((64*132 + 128*128) * 4)
__global__ __launch_bounds__(256) void k_proj(const float* __restrict__ x, const float* __restrict__ pw,
                                              const float* __restrict__ pb, float* __restrict__ h, int N){
    extern __shared__ float sm[];
    const int LDA = 132;
    float* As = sm;
    float* Ws = sm + 64 * LDA;
    int tid = threadIdx.x;
    int r0  = blockIdx.x * 64;
    load_w_smem(Ws, pw, 128, 128, tid);
    {
        int i = tid >> 2, sub = tid & 3;
        int row = r0 + i;
        const float4* xr = (const float4*)(x + (size_t)(row < N ? row : 0) * HID);
        #pragma unroll
        for (int c = 0; c < 8; ++c){
            int k4 = (sub << 3) + c;
            *(float4*)(As + i * LDA + (k4 << 2)) = xr[k4];
        }
    }
    int ti = tid & 15, tj = tid >> 4;
    int i0 = tj << 2, j0 = ti << 3;
    float4 ba = *(const float4*)(pb + j0);
    float4 bb = *(const float4*)(pb + j0 + 4);
    __syncthreads();
    u64 acc[4][4];
    acc_bias<4>(ba, bb, acc);
    mmK<132, 4>(As, Ws, 32, i0, j0, acc);
    #pragma unroll
    for (int ii = 0; ii < 4; ++ii){
        int row = r0 + i0 + ii;
        if (row < N){
            float* hr = h + (size_t)row * HID + j0;
            float f[8];
            #pragma unroll
            for (int p = 0; p < 4; ++p){
                f[2*p] = lo2(acc[ii][p]); f[2*p+1] = hi2(acc[ii][p]);
                *(float2*)(hr + (p << 1)) = make_float2(f[2*p], f[2*p+1]);
            }
            write_imgh(row, j0, f);
        }
    }
}

// ---------------- message MLP: HMMA fp16 2-product (W split hi + 2^11-scaled lo) ----------------
// SMEM bytes: A fp16 [128][272] at 0 (stage f32 [128][136] overlays bytes 0..69631)
// W1h 69632, W1l 104448, W2h 139264, W2l 174080 (each [128][272] fp16 image, 16B row pad)
// sdst 208896(512), seat 209408(512), b1 209920, b2 210432, wls 210944 -> end 211456
#define AOFF   0
#define W1HOFF 69632
#define W2HOFF 139264
#define SDOFF  208896
#define SMEM_MSG 211456

__global__ __launch_bounds__(512, 1) void k_msg(const int* __restrict__ ei, const float* __restrict__ eattr,
                                                const float* __restrict__ mw1, const float* __restrict__ mb1,
                                                const float* __restrict__ mb2, int E, int lvl){
    extern __shared__ char smc[];
    u32 smb = s2u(smc);
    int tid = threadIdx.x, wid = tid >> 5, lane = tid & 31;
    const float INV2K = 1.0f / 2048.0f;

    int*   sdst   = (int*)  (smc + SDOFF);
    float* seat   = (float*)(smc + SDOFF + 512);
    float* b1s    = (float*)(smc + SDOFF + 1024);
    float* b2s    = (float*)(smc + SDOFF + 1536);
    float* wls    = (float*)(smc + SDOFF + 2048);
    float* stagef = (float*)(smc);

    // stage weight images ([n][k] -> [128] rows of 272 bytes)
    for (int i = tid; i < 2048; i += 512){
        int n = i >> 4, kc = i & 15;
        u32 off = (u32)n * 272 + (u32)kc * 16;
        *(uint4*)(smc + W1HOFF + off)         = ((const uint4*)g_w1h)[i];
        *(uint4*)(smc + W1HOFF + 34816 + off) = ((const uint4*)g_w1l)[i];
        *(uint4*)(smc + W2HOFF + off)         = ((const uint4*)g_w2h)[i];
        *(uint4*)(smc + W2HOFF + 34816 + off) = ((const uint4*)g_w2l)[i];
    }
    if (tid < 128){
        b1s[tid] = mb1[tid];
        b2s[tid] = mb2[tid];
        wls[tid] = mw1[128 * HID + tid];
    }
    __syncthreads();

    int cnt  = g_ecnt[lvl];
    int base = g_eoff[lvl];
    int ntiles = (cnt + 127) >> 7;

    // warp mapping: rgrp = wid>>1 owns rows rgrp*16..+15; nh = wid&1 owns cols nh*64..+63
    int rgrp = wid >> 1, nh = wid & 1;
    u32 afrag = smb + AOFF + (u32)(rgrp * 16 + (lane & 15)) * 272 + (u32)((lane >> 4) << 4);
    int ra = rgrp * 16 + (lane >> 2);
    int rb = ra + 8;
    u32 lanemap = (u32)(((lane >> 4) << 3) + (lane & 7)) * 272 + (u32)(((lane >> 3) & 1) << 4);

    for (int t = blockIdx.x; t < ntiles; t += gridDim.x){
        // ---- gather A = fp16 h[src] (16 uint4 per row = 256B); sdst/seat ----
        {
            int m = tid >> 2, q = tid & 3;
            int p = t * 128 + m;
            int e = (p < cnt) ? g_eperm[base + p] : -1;
            int src = (e >= 0) ? ei[e] : 0;
            if (q == 0){
                sdst[m] = (e >= 0) ? ei[E + e] : -1;
                seat[m] = (e >= 0) ? eattr[e] : 0.f;
            }
            const uint4* hr = (const uint4*)(&g_hf[(size_t)src * HID]);
            #pragma unroll
            for (int j = 0; j < 4; ++j){
                int q4 = q * 4 + j;          // 0..15
                *(uint4*)(smc + AOFF + (u32)m * 272 + (u32)q4 * 16) = hr[q4];
            }
        }
        __syncthreads();

        u32 a[8][4];
        #pragma unroll
        for (int kc = 0; kc < 8; ++kc) LDX4(a[kc], afrag + kc * 32);
        float ea_a = seat[ra], ea_b = seat[rb];
        __syncthreads();   // all A frags in regs before any T write

        // ---- layer 1 ----
        u32 w1b = smb + W1HOFF + (u32)(nh * 64) * 272 + lanemap;
        #pragma unroll
        for (int np = 0; np < 4; ++np){
            float aH0[4] = {0,0,0,0}, aH1[4] = {0,0,0,0};
            float aL0[4] = {0,0,0,0}, aL1[4] = {0,0,0,0};
            u32 wb = w1b + (u32)np * 16 * 272;
            #pragma unroll
            for (int kc = 0; kc < 8; ++kc){
                u32 bh[4], bl[4];
                LDX4(bh, wb + kc * 32);
                LDX4(bl, wb + 34816 + kc * 32);
                MMAH(aH0, a[kc], bh[0], bh[1]);
                MMAH(aH1, a[kc], bh[2], bh[3]);
                MMAH(aL0, a[kc], bl[0], bl[1]);
                MMAH(aL1, a[kc], bl[2], bl[3]);
            }
            #pragma unroll
            for (int nch = 0; nch < 2; ++nch){
                const float* H = nch ? aH1 : aH0;
                const float* L = nch ? aL1 : aL0;
                int c = nh * 64 + np * 16 + nch * 8 + 2 * (lane & 3);
                float w0 = wls[c], w1v = wls[c+1], bb0 = b1s[c], bb1 = b1s[c+1];
                float v0 = fmaxf(H[0] + L[0] * INV2K + bb0 + ea_a * w0,  0.f);
                float v1 = fmaxf(H[1] + L[1] * INV2K + bb1 + ea_a * w1v, 0.f);
                *(u32*)(smc + AOFF + (u32)ra * 272 + (u32)c * 2) = h2pack(v0, v1);
                v0 = fmaxf(H[2] + L[2] * INV2K + bb0 + ea_b * w0,  0.f);
                v1 = fmaxf(H[3] + L[3] * INV2K + bb1 + ea_b * w1v, 0.f);
                *(u32*)(smc + AOFF + (u32)rb * 272 + (u32)c * 2) = h2pack(v0, v1);
            }
        }
        __syncthreads();   // all T written
        #pragma unroll
        for (int kc = 0; kc < 8; ++kc) LDX4(a[kc], afrag + kc * 32);
        __syncthreads();   // all T frags in regs; A region becomes fp32 stage

        // ---- layer 2 ----
        u32 w2b = smb + W2HOFF + (u32)(nh * 64) * 272 + lanemap;
        #pragma unroll
        for (int np = 0; np < 4; ++np){
            float aH0[4] = {0,0,0,0}, aH1[4] = {0,0,0,0};
            float aL0[4] = {0,0,0,0}, aL1[4] = {0,0,0,0};
            u32 wb = w2b + (u32)np * 16 * 272;
            #pragma unroll
            for (int kc = 0; kc < 8; ++kc){
                u32 bh[4], bl[4];
                LDX4(bh, wb + kc * 32);
                LDX4(bl, wb + 34816 + kc * 32);
                MMAH(aH0, a[kc], bh[0], bh[1]);
                MMAH(aH1, a[kc], bh[2], bh[3]);
                MMAH(aL0, a[kc], bl[0], bl[1]);
                MMAH(aL1, a[kc], bl[2], bl[3]);
            }
            #pragma unroll
            for (int nch = 0; nch < 2; ++nch){
                const float* H = nch ? aH1 : aH0;
                const float* L = nch ? aL1 : aL0;
                int c = nh * 64 + np * 16 + nch * 8 + 2 * (lane & 3);
                float bb0 = b2s[c], bb1 = b2s[c+1];
                stagef[ra * 136 + c]     = fmaxf(H[0] + L[0] * INV2K + bb0, 0.f);
                stagef[ra * 136 + c + 1] = fmaxf(H[1] + L[1] * INV2K + bb1, 0.f);
                stagef[rb * 136 + c]     = fmaxf(H[2] + L[2] * INV2K + bb0, 0.f);
                stagef[rb * 136 + c + 1] = fmaxf(H[3] + L[3] * INV2K + bb1, 0.f);
            }
        }
        __syncthreads();

        // ---- segmented flush (dst-sorted rows), 4 groups x 32 rows ----
        {
            int c = tid & 127, g = tid >> 7;
            int r0 = g * 32;
            float run = 0.f;
            int prev = sdst[r0];
            for (int r = 0; r < 32; ++r){
                int d = sdst[r0 + r];
                float v = stagef[(r0 + r) * 136 + c];
                if (d != prev){
                    if (prev >= 0) atomicAdd(&g_agg[(size_t)prev * HID + c], run);
                    run = 0.f;
                    prev = d;
                }
                run += v;
            }
            if (prev >= 0) atomicAdd(&g_agg[(size_t)prev * HID + c], run);
        }
        __syncthreads();
    }
}

// ---------------- node update (FFMA, persistent weights) ----------------
#define SMEM_UPD ((256*128 + 128*128 + 32*260) * 4 + 32 * 4)
__global__ __launch_bounds__(256, 1) void k_upd(float* __restrict__ h,
                                                const float* __restrict__ uw1, const float* __restrict__ ub1,
                                                const float* __restrict__ uw2, const float* __restrict__ ub2,
                                                int lvl){
    extern __shared__ float sm[];
    const int LDA = 260;
    float* W1s = sm;
    float* W2s = W1s + 256 * HID;
    float* As  = W2s + 128 * HID;
    int* snode = (int*)(As + 32 * LDA);

    int tid = threadIdx.x;
    int ti = tid & 15, tj = tid >> 4;
    int i0 = tj << 1, j0 = ti << 3;

    load_w_smem(W1s, uw1, 256, 256, tid);
    load_w_smem(W2s, uw2, 128, 128, tid);
    float4 b1a = *(const float4*)(ub1 + j0), b1b = *(const float4*)(ub1 + j0 + 4);
    float4 b2a = *(const float4*)(ub2 + j0), b2b = *(const float4*)(ub2 + j0 + 4);

    int cnt  = g_ncnt[lvl];
    int base = g_noff[lvl];
    int ntiles = (cnt + 31) >> 5;

    for (int t = blockIdx.x; t < ntiles; t += gridDim.x){
        __syncthreads();
        {
            int i = tid >> 3, sub = tid & 7;
            int p = t * 32 + i;
            int v = (p < cnt) ? g_nperm[base + p] : 0;
            float inv = g_inv[v];
            const float4* hr = (const float4*)(h + (size_t)v * HID);
            const float4* ar = (const float4*)(g_agg + (size_t)v * HID);
            #pragma unroll
            for (int c = 0; c < 8; ++c){
                int k4 = (sub << 3) + c;
                if (k4 < 32){
                    *(float4*)(As + i * LDA + (k4 << 2)) = hr[k4];
                } else {
                    float4 a = ar[k4 - 32];
                    a.x *= inv; a.y *= inv; a.z *= inv; a.w *= inv;
                    *(float4*)(As + i * LDA + (k4 << 2)) = a;
                }
            }
            if (sub == 0) snode[i] = (p < cnt) ? v : -1;
        }
        __syncthreads();
        u64 acc[2][4];
        acc_bias<2>(b1a, b1b, acc);
        mmK<260, 2>(As, W1s, 64, i0, j0, acc);
        __syncthreads();
        #pragma unroll
        for (int ii = 0; ii < 2; ++ii){
            float* trow = As + (i0 + ii) * LDA + j0;
            #pragma unroll
            for (int p = 0; p < 4; ++p){
                trow[2*p]   = fmaxf(lo2(acc[ii][p]), 0.f);
                trow[2*p+1] = fmaxf(hi2(acc[ii][p]), 0.f);
            }
        }
        __syncthreads();
        acc_bias<2>(b2a, b2b, acc);
        mmK<260, 2>(As, W2s, 32, i0, j0, acc);
        #pragma unroll
        for (int ii = 0; ii < 2; ++ii){
            int v = snode[i0 + ii];
            if (v >= 0){
                float* hr = h + (size_t)v * HID + j0;
                float f[8];
                #pragma unroll
                for (int p = 0; p < 4; ++p){
                    f[2*p]   = fmaxf(lo2(acc[ii][p]), 0.f);
                    f[2*p+1] = fmaxf(hi2(acc[ii][p]), 0.f);
                    *(float2*)(hr + (p << 1)) = make_float2(f[2*p], f[2*p+1]);
                }
                write_imgh(v, j0, f);
            }
        }
    }
}

// ---------------- host launch ----------------
extern "C" void kernel_launch(void* const* d_in, const int* in_sizes, int n_in,
                              void* d_out, int out_size){
    const float* x     = (const float*)d_in[0];
    const int*   ei    = (const int*)  d_in[1];
    const float* eattr = (const float*)d_in[2];
    const int*   depth = (const int*)  d_in[3];
    const float* pw    = (const float*)d_in[4];
    const float* pb    = (const float*)d_in[5];
    const float* mw1   = (const float*)d_in[6];
    const float* mb1   = (const float*)d_in[7];
    const float* mw2   = (const float*)d_in[8];
    const float* mb2   = (const float*)d_in[9];
    const float* uw1   = (const float*)d_in[10];
    const float* ub1   = (const float*)d_in[11];
    const float* uw2   = (const float*)d_in[12];
    const float* ub2   = (const float*)d_in[13];
    float* h = (float*)d_out;

    int N = in_sizes[3];
    int E = in_sizes[2];

    static int sms = 0;
    if (sms == 0){
        cudaDeviceGetAttribute(&sms, cudaDevAttrMultiProcessorCount, 0);
        if (sms <= 0) sms = 148;
        cudaFuncSetAttribute(k_proj, cudaFuncAttributeMaxDynamicSharedMemorySize, SMEM_PROJ);
        cudaFuncSetAttribute(k_msg,  cudaFuncAttributeMaxDynamicSharedMemorySize, SMEM_MSG);
        cudaFuncSetAttribute(k_upd,  cudaFuncAttributeMaxDynamicSharedMemorySize, SMEM_UPD);
    }

    k_zero<<<1024, 256>>>(N * HID, N);
    k_prep<<<128, 256>>>(mw1, mw2);

    int mx = (E > N) ? E : N;
    k_count<<<(mx + 255) / 256, 256>>>(ei, depth, N, E);
    k_nscan<<<1, 1>>>();
    k_snodes<<<(N + 255) / 256, 256>>>(depth, N);
    k_escan1<<<256, 256>>>(N);
    k_escan2<<<1, 256>>>();
    k_escan3<<<256, 256>>>(N);
    k_levels<<<1, 1>>>(N, E);
    k_sedges<<<(E + 255) / 256, 256>>>(ei, E);

    k_proj<<<(N + 63) / 64, 256, SMEM_PROJ>>>(x, pw, pb, h, N);

    for (int d = 1; d <= 4; ++d){
        k_msg<<<sms, 512, SMEM_MSG>>>(ei, eattr, mw1, mb1, mb2, E, d);
        k_upd<<<sms, 256, SMEM_UPD>>>(h, uw1, ub1, uw2, ub2, d);
    }
}

// round 11
// speedup vs baseline: 3.7505x; 1.5588x over previous
#include <cuda_runtime.h>
#include <cuda_fp16.h>

typedef unsigned int u32;
typedef unsigned long long u64;
typedef unsigned short u16;

#define HID 128
#define NMAX 50000
#define EMAX 500000

// ---------------- device scratch ----------------
__device__ float g_agg[(size_t)NMAX * HID];
__device__ float g_inv[NMAX];
__device__ int   g_indeg[NMAX];
__device__ int   g_nperm[NMAX];
__device__ int   g_rank[NMAX];
__device__ int   g_nodeoff[NMAX];
__device__ int   g_nodecur[NMAX];
__device__ int   g_partial[256];
__device__ int   g_ecnt[8], g_eoff[8];
__device__ int   g_ncnt[8], g_noff[8], g_ncur[8];
// sorted edge arrays (by level, then dst)
__device__ int   g_esrc[EMAX];
__device__ int   g_edst[EMAX];
__device__ float g_eatt[EMAX];
// fp16 image of h; fp16 scratch for upd layer-1 output
__device__ u16   g_hf[(size_t)NMAX * HID];
__device__ u16   g_tf[(size_t)(NMAX + 128) * HID];
// weight images, [n][k] row-major: fp16 hi, fp16 lo (lo pre-scaled by 2048)
__device__ u16   g_w1h[16384], g_w1l[16384], g_w2h[16384], g_w2l[16384];
__device__ u16   g_u1h[32768], g_u1l[32768], g_u2h[16384], g_u2l[16384];

// ---------------- helpers ----------------
static __device__ __forceinline__ u64 pk(float x, float y){
    u64 r; asm("mov.b64 %0, {%1, %2};" : "=l"(r) : "f"(x), "f"(y)); return r;
}
static __device__ __forceinline__ u64 pk2(float a){ return pk(a, a); }
static __device__ __forceinline__ u64 ffma2(u64 a, u64 b, u64 c){
    u64 d; asm("fma.rn.f32x2 %0, %1, %2, %3;" : "=l"(d) : "l"(a), "l"(b), "l"(c)); return d;
}
static __device__ __forceinline__ float lo2(u64 v){ return __uint_as_float((u32)v); }
static __device__ __forceinline__ float hi2(u64 v){ return __uint_as_float((u32)(v >> 32)); }
static __device__ __forceinline__ u32 h2pack(float f0, float f1){
    __half2 h = __floats2half2_rn(f0, f1);
    return *(u32*)&h;
}
static __device__ __forceinline__ u32 s2u(const void* p){
    u32 a; asm("{ .reg .u64 t; cvta.to.shared.u64 t, %1; cvt.u32.u64 %0, t; }" : "=r"(a) : "l"(p));
    return a;
}

#define LDX4(r, a) \
    asm volatile("ldmatrix.sync.aligned.m8n8.x4.shared.b16 {%0,%1,%2,%3}, [%4];" \
        : "=r"((r)[0]), "=r"((r)[1]), "=r"((r)[2]), "=r"((r)[3]) : "r"(a))

#define MMAH(d, a, b0, b1) \
    asm("mma.sync.aligned.m16n8k16.row.col.f32.f16.f16.f32 " \
        "{%0,%1,%2,%3}, {%4,%5,%6,%7}, {%8,%9}, {%0,%1,%2,%3};" \
        : "+f"((d)[0]), "+f"((d)[1]), "+f"((d)[2]), "+f"((d)[3]) \
        : "r"((a)[0]), "r"((a)[1]), "r"((a)[2]), "r"((a)[3]), "r"(b0), "r"(b1))

// ---------------- bucketing ----------------
__global__ void k_zero(int nagg, int N){
    int i  = blockIdx.x * blockDim.x + threadIdx.x;
    int st = gridDim.x * blockDim.x;
    for (int j = i; j < nagg; j += st) g_agg[j] = 0.f;
    for (int j = i; j < N;    j += st) g_indeg[j] = 0;
    if (i < 8) g_ncnt[i] = 0;
}

__global__ void k_count(const int* __restrict__ ei, const int* __restrict__ depth, int N, int E){
    __shared__ int scnt[8];
    int t = threadIdx.x;
    if (t < 8) scnt[t] = 0;
    __syncthreads();
    int i = blockIdx.x * blockDim.x + t;
    if (i < E) atomicAdd(&g_indeg[ei[E + i]], 1);
    if (i < N) atomicAdd(&scnt[depth[i]], 1);
    __syncthreads();
    if (t < 8 && scnt[t]) atomicAdd(&g_ncnt[t], scnt[t]);
}

__global__ void k_nscan(){
    int n = 0;
    for (int d = 0; d < 8; ++d){ g_noff[d] = n; g_ncur[d] = n; n += g_ncnt[d]; }
}

__global__ void k_snodes(const int* __restrict__ depth, int N){
    __shared__ int scnt[8], sbase[8];
    int t = threadIdx.x;
    if (t < 8) scnt[t] = 0;
    __syncthreads();
    int i = blockIdx.x * blockDim.x + t;
    int d = 0, pl = 0;
    if (i < N){ d = depth[i]; pl = atomicAdd(&scnt[d], 1); }
    __syncthreads();
    if (t < 8) sbase[t] = scnt[t] ? atomicAdd(&g_ncur[t], scnt[t]) : 0;
    __syncthreads();
    if (i < N){
        int pos = sbase[d] + pl;
        g_nperm[pos] = i;
        g_rank[i] = pos;
        int c = g_indeg[i];
        g_inv[i] = 1.0f / (float)(c > 0 ? c : 1);
    }
}

__global__ void k_escan1(int N){
    __shared__ int sh[256];
    int chunk = (N + 255) / 256;
    int t = threadIdx.x;
    int i = blockIdx.x * chunk + t;
    int v = 0;
    if (t < chunk && i < N) v = g_indeg[g_nperm[i]];
    sh[t] = v; __syncthreads();
    for (int s = 128; s > 0; s >>= 1){
        if (t < s) sh[t] += sh[t + s];
        __syncthreads();
    }
    if (t == 0) g_partial[blockIdx.x] = sh[0];
}
__global__ void k_escan2(){
    __shared__ int sh[256];
    int t = threadIdx.x;
    int orig = g_partial[t];
    sh[t] = orig; __syncthreads();
    for (int s = 1; s < 256; s <<= 1){
        int v = (t >= s) ? sh[t - s] : 0;
        __syncthreads();
        sh[t] += v;
        __syncthreads();
    }
    g_partial[t] = sh[t] - orig;
}
__global__ void k_escan3(int N){
    __shared__ int sh[256];
    int chunk = (N + 255) / 256;
    int t = threadIdx.x;
    int i = blockIdx.x * chunk + t;
    int orig = 0;
    if (t < chunk && i < N) orig = g_indeg[g_nperm[i]];
    sh[t] = orig; __syncthreads();
    for (int s = 1; s < 256; s <<= 1){
        int v = (t >= s) ? sh[t - s] : 0;
        __syncthreads();
        sh[t] += v;
        __syncthreads();
    }
    if (t < chunk && i < N){
        int excl = g_partial[blockIdx.x] + sh[t] - orig;
        g_nodeoff[i] = excl;
        g_nodecur[i] = excl;
    }
}
__global__ void k_levels(int N, int E){
    for (int d = 0; d < 8; ++d){
        int b0 = g_noff[d];
        int b1 = b0 + g_ncnt[d];
        int o0 = (b0 < N) ? g_nodeoff[b0] : E;
        int o1 = (b1 < N) ? g_nodeoff[b1] : E;
        g_eoff[d] = o0; g_ecnt[d] = o1 - o0;
    }
}
__global__ void k_sedges(const int* __restrict__ ei, const float* __restrict__ eattr, int E){
    int e = blockIdx.x * blockDim.x + threadIdx.x;
    if (e < E){
        int dst = ei[E + e];
        int pos = atomicAdd(&g_nodecur[g_rank[dst]], 1);
        g_esrc[pos] = ei[e];
        g_edst[pos] = dst;
        g_eatt[pos] = eattr[e];
    }
}

// ---------------- weight image prep: [n][k] = W[k][n], fp16 hi + 2^11-scaled lo ----------------
__global__ void k_prep(const float* __restrict__ mw1, const float* __restrict__ mw2,
                       const float* __restrict__ uw1, const float* __restrict__ uw2){
    int idx = blockIdx.x * blockDim.x + threadIdx.x;
    if (idx >= 81920) return;
    const float* W; u16 *H, *L; int n, k, kdim;
    if (idx < 32768){
        int mtx = idx >> 14, rem = idx & 16383;
        n = rem >> 7; k = rem & 127; kdim = 128;
        W = mtx ? mw2 : mw1; H = mtx ? g_w2h : g_w1h; L = mtx ? g_w2l : g_w1l;
    } else if (idx < 65536){
        int j = idx - 32768;
        n = j >> 8; k = j & 255; kdim = 256;
        W = uw1; H = g_u1h; L = g_u1l;
    } else {
        int j = idx - 65536;
        n = j >> 7; k = j & 127; kdim = 128;
        W = uw2; H = g_u2h; L = g_u2l;
    }
    float v = W[k * HID + n];
    __half hh = __float2half_rn(v);
    float hf = __half2float(hh);
    __half hl = __float2half_rn((v - hf) * 2048.0f);
    H[n * kdim + k] = *(u16*)&hh;
    L[n * kdim + k] = *(u16*)&hl;
}

// ---------------- FFMA GEMM pieces (proj) ----------------
template<int LDA, int RR>
static __device__ __forceinline__ void mmK(const float* __restrict__ A, const float* __restrict__ W,
                                           int K4, int i0, int j0, u64 acc[RR][4]){
    for (int c = 0; c < K4; ++c){
        float4 av[RR];
        #pragma unroll
        for (int ii = 0; ii < RR; ++ii)
            av[ii] = *(const float4*)(A + (i0 + ii) * LDA + (c << 2));
        const float* wr = W + (c << 2) * HID + j0;
        #pragma unroll
        for (int q = 0; q < 4; ++q){
            ulonglong2 wA = *(const ulonglong2*)(wr + q * HID);
            ulonglong2 wB = *(const ulonglong2*)(wr + q * HID + 4);
            #pragma unroll
            for (int ii = 0; ii < RR; ++ii){
                float aq = (q == 0) ? av[ii].x : (q == 1) ? av[ii].y : (q == 2) ? av[ii].z : av[ii].w;
                u64 a2 = pk2(aq);
                acc[ii][0] = ffma2(a2, wA.x, acc[ii][0]);
                acc[ii][1] = ffma2(a2, wA.y, acc[ii][1]);
                acc[ii][2] = ffma2(a2, wB.x, acc[ii][2]);
                acc[ii][3] = ffma2(a2, wB.y, acc[ii][3]);
            }
        }
    }
}

static __device__ __forceinline__ void write_imgh(int row, int j0, const float f[8]){
    u32 p0 = h2pack(f[0], f[1]);
    u32 p1 = h2pack(f[2], f[3]);
    u32 p2 = h2pack(f[4], f[5]);
    u32 p3 = h2pack(f[6], f[7]);
    *(uint4*)(&g_hf[(size_t)row * HID + j0]) = make_uint4(p0, p1, p2, p3);
}

// ---------------- projection ----------------
#define SMEM_PROJ ((64*132 + 128*128) * 4)
__global__ __launch_bounds__(256) void k_proj(const float* __restrict__ x, const float* __restrict__ pw,
                                              const float* __restrict__ pb, float* __restrict__ h, int N){
    extern __shared__ float sm[];
    const int LDA = 132;
    float* As = sm;
    float* Ws = sm + 64 * LDA;
    int tid = threadIdx.x;
    int r0  = blockIdx.x * 64;
    for (int i = tid; i < 4096; i += 256){
        int r = i >> 5, c4 = (i & 31) << 2;
        *(float4*)(Ws + r * HID + c4) = *(const float4*)(pw + (size_t)r * HID + c4);
    }
    {
        int i = tid >> 2, sub = tid & 3;
        int row = r0 + i;
        const float4* xr = (const float4*)(x + (size_t)(row < N ? row : 0) * HID);
        #pragma unroll
        for (int c = 0; c < 8; ++c){
            int k4 = (sub << 3) + c;
            *(float4*)(As + i * LDA + (k4 << 2)) = xr[k4];
        }
    }
    int ti = tid & 15, tj = tid >> 4;
    int i0 = tj << 2, j0 = ti << 3;
    float4 ba = *(const float4*)(pb + j0);
    float4 bb = *(const float4*)(pb + j0 + 4);
    __syncthreads();
    u64 acc[4][4];
    {
        u64 p0 = pk(ba.x, ba.y), p1 = pk(ba.z, ba.w);
        u64 p2 = pk(bb.x, bb.y), p3 = pk(bb.z, bb.w);
        #pragma unroll
        for (int ii = 0; ii < 4; ++ii){ acc[ii][0]=p0; acc[ii][1]=p1; acc[ii][2]=p2; acc[ii][3]=p3; }
    }
    mmK<132, 4>(As, Ws, 32, i0, j0, acc);
    #pragma unroll
    for (int ii = 0; ii < 4; ++ii){
        int row = r0 + i0 + ii;
        if (row < N){
            float* hr = h + (size_t)row * HID + j0;
            float f[8];
            #pragma unroll
            for (int p = 0; p < 4; ++p){
                f[2*p] = lo2(acc[ii][p]); f[2*p+1] = hi2(acc[ii][p]);
                *(float2*)(hr + (p << 1)) = make_float2(f[2*p], f[2*p+1]);
            }
            write_imgh(row, j0, f);
        }
    }
}

// ---------------- message MLP: HMMA fp16 2-product ----------------
#define AOFF   0
#define W1HOFF 69632
#define W2HOFF 139264
#define SDOFF  208896
#define SMEM_MSG 211456

__global__ __launch_bounds__(512, 1) void k_msg(const float* __restrict__ mw1, const float* __restrict__ mb1,
                                                const float* __restrict__ mb2, int lvl){
    extern __shared__ char smc[];
    u32 smb = s2u(smc);
    int tid = threadIdx.x, wid = tid >> 5, lane = tid & 31;
    const float INV2K = 1.0f / 2048.0f;

    int*   sdst   = (int*)  (smc + SDOFF);
    float* seat   = (float*)(smc + SDOFF + 512);
    float* b1s    = (float*)(smc + SDOFF + 1024);
    float* b2s    = (float*)(smc + SDOFF + 1536);
    float* wls    = (float*)(smc + SDOFF + 2048);
    float* stagef = (float*)(smc);

    for (int i = tid; i < 2048; i += 512){
        int n = i >> 4, kc = i & 15;
        u32 off = (u32)n * 272 + (u32)kc * 16;
        *(uint4*)(smc + W1HOFF + off)         = ((const uint4*)g_w1h)[i];
        *(uint4*)(smc + W1HOFF + 34816 + off) = ((const uint4*)g_w1l)[i];
        *(uint4*)(smc + W2HOFF + off)         = ((const uint4*)g_w2h)[i];
        *(uint4*)(smc + W2HOFF + 34816 + off) = ((const uint4*)g_w2l)[i];
    }
    if (tid < 128){
        b1s[tid] = mb1[tid];
        b2s[tid] = mb2[tid];
        wls[tid] = mw1[128 * HID + tid];
    }
    __syncthreads();

    int cnt  = g_ecnt[lvl];
    int base = g_eoff[lvl];
    int ntiles = (cnt + 127) >> 7;

    int rgrp = wid >> 1, nh = wid & 1;
    u32 afrag = smb + AOFF + (u32)(rgrp * 16 + (lane & 15)) * 272 + (u32)((lane >> 4) << 4);
    int ra = rgrp * 16 + (lane >> 2);
    int rb = ra + 8;
    u32 lanemap = (u32)(((lane >> 4) << 3) + (lane & 7)) * 272 + (u32)(((lane >> 3) & 1) << 4);

    for (int t = blockIdx.x; t < ntiles; t += gridDim.x){
        {
            int m = tid >> 2, q = tid & 3;
            int p = t * 128 + m;
            int src = 0;
            if (p < cnt) src = g_esrc[base + p];
            if (q == 0){
                sdst[m] = (p < cnt) ? g_edst[base + p] : -1;
                seat[m] = (p < cnt) ? g_eatt[base + p] : 0.f;
            }
            const uint4* hr = (const uint4*)(&g_hf[(size_t)src * HID]);
            #pragma unroll
            for (int j = 0; j < 4; ++j){
                int q4 = q * 4 + j;
                *(uint4*)(smc + AOFF + (u32)m * 272 + (u32)q4 * 16) = hr[q4];
            }
        }
        __syncthreads();

        u32 a[8][4];
        #pragma unroll
        for (int kc = 0; kc < 8; ++kc) LDX4(a[kc], afrag + kc * 32);
        float ea_a = seat[ra], ea_b = seat[rb];
        __syncthreads();

        // layer 1
        u32 w1b = smb + W1HOFF + (u32)(nh * 64) * 272 + lanemap;
        #pragma unroll
        for (int np = 0; np < 4; ++np){
            float aH0[4] = {0,0,0,0}, aH1[4] = {0,0,0,0};
            float aL0[4] = {0,0,0,0}, aL1[4] = {0,0,0,0};
            u32 wb = w1b + (u32)np * 16 * 272;
            #pragma unroll
            for (int kc = 0; kc < 8; ++kc){
                u32 bh[4], bl[4];
                LDX4(bh, wb + kc * 32);
                LDX4(bl, wb + 34816 + kc * 32);
                MMAH(aH0, a[kc], bh[0], bh[1]);
                MMAH(aH1, a[kc], bh[2], bh[3]);
                MMAH(aL0, a[kc], bl[0], bl[1]);
                MMAH(aL1, a[kc], bl[2], bl[3]);
            }
            #pragma unroll
            for (int nch = 0; nch < 2; ++nch){
                const float* H = nch ? aH1 : aH0;
                const float* L = nch ? aL1 : aL0;
                int c = nh * 64 + np * 16 + nch * 8 + 2 * (lane & 3);
                float w0 = wls[c], w1v = wls[c+1], bb0 = b1s[c], bb1 = b1s[c+1];
                float v0 = fmaxf(H[0] + L[0] * INV2K + bb0 + ea_a * w0,  0.f);
                float v1 = fmaxf(H[1] + L[1] * INV2K + bb1 + ea_a * w1v, 0.f);
                *(u32*)(smc + AOFF + (u32)ra * 272 + (u32)c * 2) = h2pack(v0, v1);
                v0 = fmaxf(H[2] + L[2] * INV2K + bb0 + ea_b * w0,  0.f);
                v1 = fmaxf(H[3] + L[3] * INV2K + bb1 + ea_b * w1v, 0.f);
                *(u32*)(smc + AOFF + (u32)rb * 272 + (u32)c * 2) = h2pack(v0, v1);
            }
        }
        __syncthreads();
        #pragma unroll
        for (int kc = 0; kc < 8; ++kc) LDX4(a[kc], afrag + kc * 32);
        __syncthreads();

        // layer 2
        u32 w2b = smb + W2HOFF + (u32)(nh * 64) * 272 + lanemap;
        #pragma unroll
        for (int np = 0; np < 4; ++np){
            float aH0[4] = {0,0,0,0}, aH1[4] = {0,0,0,0};
            float aL0[4] = {0,0,0,0}, aL1[4] = {0,0,0,0};
            u32 wb = w2b + (u32)np * 16 * 272;
            #pragma unroll
            for (int kc = 0; kc < 8; ++kc){
                u32 bh[4], bl[4];
                LDX4(bh, wb + kc * 32);
                LDX4(bl, wb + 34816 + kc * 32);
                MMAH(aH0, a[kc], bh[0], bh[1]);
                MMAH(aH1, a[kc], bh[2], bh[3]);
                MMAH(aL0, a[kc], bl[0], bl[1]);
                MMAH(aL1, a[kc], bl[2], bl[3]);
            }
            #pragma unroll
            for (int nch = 0; nch < 2; ++nch){
                const float* H = nch ? aH1 : aH0;
                const float* L = nch ? aL1 : aL0;
                int c = nh * 64 + np * 16 + nch * 8 + 2 * (lane & 3);
                float bb0 = b2s[c], bb1 = b2s[c+1];
                stagef[ra * 136 + c]     = fmaxf(H[0] + L[0] * INV2K + bb0, 0.f);
                stagef[ra * 136 + c + 1] = fmaxf(H[1] + L[1] * INV2K + bb1, 0.f);
                stagef[rb * 136 + c]     = fmaxf(H[2] + L[2] * INV2K + bb0, 0.f);
                stagef[rb * 136 + c + 1] = fmaxf(H[3] + L[3] * INV2K + bb1, 0.f);
            }
        }
        __syncthreads();

        {
            int c = tid & 127, g = tid >> 7;
            int r0 = g * 32;
            float run = 0.f;
            int prev = sdst[r0];
            for (int r = 0; r < 32; ++r){
                int d = sdst[r0 + r];
                float v = stagef[(r0 + r) * 136 + c];
                if (d != prev){
                    if (prev >= 0) atomicAdd(&g_agg[(size_t)prev * HID + c], run);
                    run = 0.f;
                    prev = d;
                }
                run += v;
            }
            if (prev >= 0) atomicAdd(&g_agg[(size_t)prev * HID + c], run);
        }
        __syncthreads();
    }
}

// ---------------- update layer 1: HMMA, K=256, T -> g_tf ----------------
// SMEM: A [128][528] at 0 (67584), W1h at 67584, W1l at 135168; b1s at 202752
#define U1_W 67584
#define U1_MISC 202752
#define SMEM_UPD1 (U1_MISC + 512)
__global__ __launch_bounds__(512, 1) void k_upd1(const float* __restrict__ h, const float* __restrict__ ub1, int lvl){
    extern __shared__ char smc[];
    u32 smb = s2u(smc);
    int tid = threadIdx.x, wid = tid >> 5, lane = tid & 31;
    const float INV2K = 1.0f / 2048.0f;
    float* b1s = (float*)(smc + U1_MISC);

    for (int i = tid; i < 4096; i += 512){
        int n = i >> 5, kc = i & 31;
        u32 off = (u32)n * 528 + (u32)kc * 16;
        *(uint4*)(smc + U1_W + off)         = ((const uint4*)g_u1h)[i];
        *(uint4*)(smc + U1_W + 67584 + off) = ((const uint4*)g_u1l)[i];
    }
    if (tid < 128) b1s[tid] = ub1[tid];
    __syncthreads();

    int cnt  = g_ncnt[lvl];
    int base = g_noff[lvl];
    int ntiles = (cnt + 127) >> 7;

    int rgrp = wid >> 1, nh = wid & 1;
    u32 afrag = smb + (u32)(rgrp * 16 + (lane & 15)) * 528 + (u32)((lane >> 4) << 4);
    int ra = rgrp * 16 + (lane >> 2);
    int rb = ra + 8;
    u32 lanemap = (u32)(((lane >> 4) << 3) + (lane & 7)) * 528 + (u32)(((lane >> 3) & 1) << 4);

    for (int t = blockIdx.x; t < ntiles; t += gridDim.x){
        __syncthreads();
        {   // gather A = [h fp16 (16 uint4) | agg*inv fp16 (16 uint4)]
            int m = tid >> 2, q = tid & 3;
            int p = t * 128 + m;
            int v = (p < cnt) ? g_nperm[base + p] : 0;
            float inv = g_inv[v];
            const uint4*  hr = (const uint4*)(&g_hf[(size_t)v * HID]);
            const float4* ar = (const float4*)(&g_agg[(size_t)v * HID]);
            #pragma unroll
            for (int j = 0; j < 4; ++j){
                int q4 = q * 4 + j;
                *(uint4*)(smc + (u32)m * 528 + (u32)q4 * 16) = hr[q4];
                float4 a0 = ar[2 * q4], a1 = ar[2 * q4 + 1];
                uint4 pv;
                pv.x = h2pack(a0.x * inv, a0.y * inv);
                pv.y = h2pack(a0.z * inv, a0.w * inv);
                pv.z = h2pack(a1.x * inv, a1.y * inv);
                pv.w = h2pack(a1.z * inv, a1.w * inv);
                *(uint4*)(smc + (u32)m * 528 + 256 + (u32)q4 * 16) = pv;
            }
        }
        __syncthreads();

        u32 w1b = smb + U1_W + (u32)(nh * 64) * 528 + lanemap;
        int tbase = base + t * 128;
        #pragma unroll
        for (int np = 0; np < 4; ++np){
            float aH0[4] = {0,0,0,0}, aH1[4] = {0,0,0,0};
            float aL0[4] = {0,0,0,0}, aL1[4] = {0,0,0,0};
            u32 wb = w1b + (u32)np * 16 * 528;
            #pragma unroll
            for (int kc = 0; kc < 16; ++kc){
                u32 a[4], bh[4], bl[4];
                LDX4(a,  afrag + kc * 32);
                LDX4(bh, wb + kc * 32);
                LDX4(bl, wb + 67584 + kc * 32);
                MMAH(aH0, a, bh[0], bh[1]);
                MMAH(aH1, a, bh[2], bh[3]);
                MMAH(aL0, a, bl[0], bl[1]);
                MMAH(aL1, a, bl[2], bl[3]);
            }
            #pragma unroll
            for (int nch = 0; nch < 2; ++nch){
                const float* H = nch ? aH1 : aH0;
                const float* L = nch ? aL1 : aL0;
                int c = nh * 64 + np * 16 + nch * 8 + 2 * (lane & 3);
                float bb0 = b1s[c], bb1 = b1s[c+1];
                float v0 = fmaxf(H[0] + L[0] * INV2K + bb0, 0.f);
                float v1 = fmaxf(H[1] + L[1] * INV2K + bb1, 0.f);
                *(u32*)(&g_tf[(size_t)(tbase + ra) * HID + c]) = h2pack(v0, v1);
                v0 = fmaxf(H[2] + L[2] * INV2K + bb0, 0.f);
                v1 = fmaxf(H[3] + L[3] * INV2K + bb1, 0.f);
                *(u32*)(&g_tf[(size_t)(tbase + rb) * HID + c]) = h2pack(v0, v1);
            }
        }
    }
}

// ---------------- update layer 2: HMMA, K=128, -> h + image ----------------
// SMEM: A [128][272] at 0 (34816), W2h at 34816, W2l at 69632; misc at 104448
#define U2_W 34816
#define U2_MISC 104448
#define SMEM_UPD2 (U2_MISC + 1024)
__global__ __launch_bounds__(512, 1) void k_upd2(float* __restrict__ h, const float* __restrict__ ub2, int lvl){
    extern __shared__ char smc[];
    u32 smb = s2u(smc);
    int tid = threadIdx.x, wid = tid >> 5, lane = tid & 31;
    const float INV2K = 1.0f / 2048.0f;
    int*   snode = (int*)(smc + U2_MISC);
    float* b2s   = (float*)(smc + U2_MISC + 512);

    for (int i = tid; i < 2048; i += 512){
        int n = i >> 4, kc = i & 15;
        u32 off = (u32)n * 272 + (u32)kc * 16;
        *(uint4*)(smc + U2_W + off)         = ((const uint4*)g_u2h)[i];
        *(uint4*)(smc + U2_W + 34816 + off) = ((const uint4*)g_u2l)[i];
    }
    if (tid < 128) b2s[tid] = ub2[tid];
    __syncthreads();

    int cnt  = g_ncnt[lvl];
    int base = g_noff[lvl];
    int ntiles = (cnt + 127) >> 7;

    int rgrp = wid >> 1, nh = wid & 1;
    u32 afrag = smb + (u32)(rgrp * 16 + (lane & 15)) * 272 + (u32)((lane >> 4) << 4);
    int ra = rgrp * 16 + (lane >> 2);
    int rb = ra + 8;
    u32 lanemap = (u32)(((lane >> 4) << 3) + (lane & 7)) * 272 + (u32)(((lane >> 3) & 1) << 4);

    for (int t = blockIdx.x; t < ntiles; t += gridDim.x){
        __syncthreads();
        {   // gather T rows (contiguous)
            int m = tid >> 2, q = tid & 3;
            int p = t * 128 + m;
            if (q == 0) snode[m] = (p < cnt) ? g_nperm[base + p] : -1;
            const uint4* tr = (const uint4*)(&g_tf[(size_t)(base + t * 128 + m) * HID]);
            #pragma unroll
            for (int j = 0; j < 4; ++j){
                int q4 = q * 4 + j;
                *(uint4*)(smc + (u32)m * 272 + (u32)q4 * 16) = tr[q4];
            }
        }
        __syncthreads();

        u32 a[8][4];
        #pragma unroll
        for (int kc = 0; kc < 8; ++kc) LDX4(a[kc], afrag + kc * 32);

        u32 w2b = smb + U2_W + (u32)(nh * 64) * 272 + lanemap;
        int na = snode[ra], nb = snode[rb];
        #pragma unroll
        for (int np = 0; np < 4; ++np){
            float aH0[4] = {0,0,0,0}, aH1[4] = {0,0,0,0};
            float aL0[4] = {0,0,0,0}, aL1[4] = {0,0,0,0};
            u32 wb = w2b + (u32)np * 16 * 272;
            #pragma unroll
            for (int kc = 0; kc < 8; ++kc){
                u32 bh[4], bl[4];
                LDX4(bh, wb + kc * 32);
                LDX4(bl, wb + 34816 + kc * 32);
                MMAH(aH0, a[kc], bh[0], bh[1]);
                MMAH(aH1, a[kc], bh[2], bh[3]);
                MMAH(aL0, a[kc], bl[0], bl[1]);
                MMAH(aL1, a[kc], bl[2], bl[3]);
            }
            #pragma unroll
            for (int nch = 0; nch < 2; ++nch){
                const float* H = nch ? aH1 : aH0;
                const float* L = nch ? aL1 : aL0;
                int c = nh * 64 + np * 16 + nch * 8 + 2 * (lane & 3);
                float bb0 = b2s[c], bb1 = b2s[c+1];
                float v0 = fmaxf(H[0] + L[0] * INV2K + bb0, 0.f);
                float v1 = fmaxf(H[1] + L[1] * INV2K + bb1, 0.f);
                if (na >= 0){
                    *(float2*)(h + (size_t)na * HID + c) = make_float2(v0, v1);
                    *(u32*)(&g_hf[(size_t)na * HID + c]) = h2pack(v0, v1);
                }
                v0 = fmaxf(H[2] + L[2] * INV2K + bb0, 0.f);
                v1 = fmaxf(H[3] + L[3] * INV2K + bb1, 0.f);
                if (nb >= 0){
                    *(float2*)(h + (size_t)nb * HID + c) = make_float2(v0, v1);
                    *(u32*)(&g_hf[(size_t)nb * HID + c]) = h2pack(v0, v1);
                }
            }
        }
    }
}

// ---------------- host launch ----------------
extern "C" void kernel_launch(void* const* d_in, const int* in_sizes, int n_in,
                              void* d_out, int out_size){
    const float* x     = (const float*)d_in[0];
    const int*   ei    = (const int*)  d_in[1];
    const float* eattr = (const float*)d_in[2];
    const int*   depth = (const int*)  d_in[3];
    const float* pw    = (const float*)d_in[4];
    const float* pb    = (const float*)d_in[5];
    const float* mw1   = (const float*)d_in[6];
    const float* mb1   = (const float*)d_in[7];
    const float* mw2   = (const float*)d_in[8];
    const float* mb2   = (const float*)d_in[9];
    const float* uw1   = (const float*)d_in[10];
    const float* ub1   = (const float*)d_in[11];
    const float* uw2   = (const float*)d_in[12];
    const float* ub2   = (const float*)d_in[13];
    float* h = (float*)d_out;

    int N = in_sizes[3];
    int E = in_sizes[2];

    static int sms = 0;
    if (sms == 0){
        cudaDeviceGetAttribute(&sms, cudaDevAttrMultiProcessorCount, 0);
        if (sms <= 0) sms = 148;
        cudaFuncSetAttribute(k_proj, cudaFuncAttributeMaxDynamicSharedMemorySize, SMEM_PROJ);
        cudaFuncSetAttribute(k_msg,  cudaFuncAttributeMaxDynamicSharedMemorySize, SMEM_MSG);
        cudaFuncSetAttribute(k_upd1, cudaFuncAttributeMaxDynamicSharedMemorySize, SMEM_UPD1);
        cudaFuncSetAttribute(k_upd2, cudaFuncAttributeMaxDynamicSharedMemorySize, SMEM_UPD2);
    }

    k_zero<<<1024, 256>>>(N * HID, N);
    k_prep<<<320, 256>>>(mw1, mw2, uw1, uw2);

    int mx = (E > N) ? E : N;
    k_count<<<(mx + 255) / 256, 256>>>(ei, depth, N, E);
    k_nscan<<<1, 1>>>();
    k_snodes<<<(N + 255) / 256, 256>>>(depth, N);
    k_escan1<<<256, 256>>>(N);
    k_escan2<<<1, 256>>>();
    k_escan3<<<256, 256>>>(N);
    k_levels<<<1, 1>>>(N, E);
    k_sedges<<<(E + 255) / 256, 256>>>(ei, eattr, E);

    k_proj<<<(N + 63) / 64, 256, SMEM_PROJ>>>(x, pw, pb, h, N);

    for (int d = 1; d <= 4; ++d){
        k_msg<<<sms, 512, SMEM_MSG>>>(mw1, mb1, mb2, d);
        k_upd1<<<sms, 512, SMEM_UPD1>>>(h, ub1, d);
        k_upd2<<<sms, 512, SMEM_UPD2>>>(h, ub2, d);
    }
}

// round 12
// speedup vs baseline: 4.7841x; 1.2756x over previous
#include <cuda_runtime.h>
#include <cuda_fp16.h>

typedef unsigned int u32;
typedef unsigned long long u64;
typedef unsigned short u16;

#define HID 128
#define NMAX 50000
#define EMAX 500000

// ---------------- device scratch ----------------
__device__ float g_agg[(size_t)NMAX * HID];
__device__ float g_inv[NMAX];
__device__ int   g_indeg[NMAX];
__device__ int   g_nperm[NMAX];
__device__ int   g_rank[NMAX];
__device__ int   g_nodeoff[NMAX];
__device__ int   g_nodecur[NMAX];
__device__ int   g_partial[256];
__device__ int   g_ecnt[8], g_eoff[8];
__device__ int   g_ncnt[8], g_noff[8], g_ncur[8];
// sorted edge arrays (by level, then dst)
__device__ int   g_esrc[EMAX];
__device__ int   g_edst[EMAX];
__device__ float g_eatt[EMAX];
// fp16 image of h
__device__ u16   g_hf[(size_t)NMAX * HID];
// weight images, [n][k] row-major, single fp16
__device__ u16   g_w1h[16384], g_w2h[16384];
__device__ u16   g_u1h[32768], g_u2h[16384];

// ---------------- helpers ----------------
static __device__ __forceinline__ u64 pk(float x, float y){
    u64 r; asm("mov.b64 %0, {%1, %2};" : "=l"(r) : "f"(x), "f"(y)); return r;
}
static __device__ __forceinline__ u64 pk2(float a){ return pk(a, a); }
static __device__ __forceinline__ u64 ffma2(u64 a, u64 b, u64 c){
    u64 d; asm("fma.rn.f32x2 %0, %1, %2, %3;" : "=l"(d) : "l"(a), "l"(b), "l"(c)); return d;
}
static __device__ __forceinline__ float lo2(u64 v){ return __uint_as_float((u32)v); }
static __device__ __forceinline__ float hi2(u64 v){ return __uint_as_float((u32)(v >> 32)); }
static __device__ __forceinline__ u32 h2pack(float f0, float f1){
    __half2 h = __floats2half2_rn(f0, f1);
    return *(u32*)&h;
}
static __device__ __forceinline__ u32 s2u(const void* p){
    u32 a; asm("{ .reg .u64 t; cvta.to.shared.u64 t, %1; cvt.u32.u64 %0, t; }" : "=r"(a) : "l"(p));
    return a;
}

#define LDX4(r, a) \
    asm volatile("ldmatrix.sync.aligned.m8n8.x4.shared.b16 {%0,%1,%2,%3}, [%4];" \
        : "=r"((r)[0]), "=r"((r)[1]), "=r"((r)[2]), "=r"((r)[3]) : "r"(a))

#define MMAH(d, a, b0, b1) \
    asm("mma.sync.aligned.m16n8k16.row.col.f32.f16.f16.f32 " \
        "{%0,%1,%2,%3}, {%4,%5,%6,%7}, {%8,%9}, {%0,%1,%2,%3};" \
        : "+f"((d)[0]), "+f"((d)[1]), "+f"((d)[2]), "+f"((d)[3]) \
        : "r"((a)[0]), "r"((a)[1]), "r"((a)[2]), "r"((a)[3]), "r"(b0), "r"(b1))

#define PAIR_BAR(id) asm volatile("bar.sync %0, 64;" :: "r"(id) : "memory")

// ---------------- bucketing ----------------
__global__ void k_zero(int nagg, int N){
    int i  = blockIdx.x * blockDim.x + threadIdx.x;
    int st = gridDim.x * blockDim.x;
    for (int j = i; j < nagg; j += st) g_agg[j] = 0.f;
    for (int j = i; j < N;    j += st) g_indeg[j] = 0;
    if (i < 8) g_ncnt[i] = 0;
}

__global__ void k_count(const int* __restrict__ ei, const int* __restrict__ depth, int N, int E){
    __shared__ int scnt[8];
    int t = threadIdx.x;
    if (t < 8) scnt[t] = 0;
    __syncthreads();
    int i = blockIdx.x * blockDim.x + t;
    if (i < E) atomicAdd(&g_indeg[ei[E + i]], 1);
    if (i < N) atomicAdd(&scnt[depth[i]], 1);
    __syncthreads();
    if (t < 8 && scnt[t]) atomicAdd(&g_ncnt[t], scnt[t]);
}

__global__ void k_nscan(){
    int t = threadIdx.x;
    if (t < 8){
        int s = 0;
        #pragma unroll
        for (int d = 0; d < 8; ++d)
            if (d < t) s += g_ncnt[d];
        g_noff[t] = s; g_ncur[t] = s;
    }
}

__global__ void k_snodes(const int* __restrict__ depth, int N){
    __shared__ int scnt[8], sbase[8];
    int t = threadIdx.x;
    if (t < 8) scnt[t] = 0;
    __syncthreads();
    int i = blockIdx.x * blockDim.x + t;
    int d = 0, pl = 0;
    if (i < N){ d = depth[i]; pl = atomicAdd(&scnt[d], 1); }
    __syncthreads();
    if (t < 8) sbase[t] = scnt[t] ? atomicAdd(&g_ncur[t], scnt[t]) : 0;
    __syncthreads();
    if (i < N){
        int pos = sbase[d] + pl;
        g_nperm[pos] = i;
        g_rank[i] = pos;
        int c = g_indeg[i];
        g_inv[i] = 1.0f / (float)(c > 0 ? c : 1);
    }
}

__global__ void k_escan1(int N){
    __shared__ int sh[256];
    int chunk = (N + 255) / 256;
    int t = threadIdx.x;
    int i = blockIdx.x * chunk + t;
    int v = 0;
    if (t < chunk && i < N) v = g_indeg[g_nperm[i]];
    sh[t] = v; __syncthreads();
    for (int s = 128; s > 0; s >>= 1){
        if (t < s) sh[t] += sh[t + s];
        __syncthreads();
    }
    if (t == 0) g_partial[blockIdx.x] = sh[0];
}
__global__ void k_escan2(){
    __shared__ int sh[256];
    int t = threadIdx.x;
    int orig = g_partial[t];
    sh[t] = orig; __syncthreads();
    for (int s = 1; s < 256; s <<= 1){
        int v = (t >= s) ? sh[t - s] : 0;
        __syncthreads();
        sh[t] += v;
        __syncthreads();
    }
    g_partial[t] = sh[t] - orig;
}
__global__ void k_escan3(int N){
    __shared__ int sh[256];
    int chunk = (N + 255) / 256;
    int t = threadIdx.x;
    int i = blockIdx.x * chunk + t;
    int orig = 0;
    if (t < chunk && i < N) orig = g_indeg[g_nperm[i]];
    sh[t] = orig; __syncthreads();
    for (int s = 1; s < 256; s <<= 1){
        int v = (t >= s) ? sh[t - s] : 0;
        __syncthreads();
        sh[t] += v;
        __syncthreads();
    }
    if (t < chunk && i < N){
        int excl = g_partial[blockIdx.x] + sh[t] - orig;
        g_nodeoff[i] = excl;
        g_nodecur[i] = excl;
    }
}
__global__ void k_levels(int N, int E){
    int t = threadIdx.x;
    if (t < 8){
        int b0 = g_noff[t];
        int b1 = b0 + g_ncnt[t];
        int o0 = (b0 < N) ? g_nodeoff[b0] : E;
        int o1 = (b1 < N) ? g_nodeoff[b1] : E;
        g_eoff[t] = o0; g_ecnt[t] = o1 - o0;
    }
}
__global__ void k_sedges(const int* __restrict__ ei, const float* __restrict__ eattr, int E){
    int e = blockIdx.x * blockDim.x + threadIdx.x;
    if (e < E){
        int dst = ei[E + e];
        int pos = atomicAdd(&g_nodecur[g_rank[dst]], 1);
        g_esrc[pos] = ei[e];
        g_edst[pos] = dst;
        g_eatt[pos] = eattr[e];
    }
}

// ---------------- weight image prep: [n][k] = W[k][n], single fp16 ----------------
__global__ void k_prep(const float* __restrict__ mw1, const float* __restrict__ mw2,
                       const float* __restrict__ uw1, const float* __restrict__ uw2){
    int idx = blockIdx.x * blockDim.x + threadIdx.x;
    if (idx >= 81920) return;
    const float* W; u16 *H; int n, k, kdim;
    if (idx < 32768){
        int mtx = idx >> 14, rem = idx & 16383;
        n = rem >> 7; k = rem & 127; kdim = 128;
        W = mtx ? mw2 : mw1; H = mtx ? g_w2h : g_w1h;
    } else if (idx < 65536){
        int j = idx - 32768;
        n = j >> 8; k = j & 255; kdim = 256;
        W = uw1; H = g_u1h;
    } else {
        int j = idx - 65536;
        n = j >> 7; k = j & 127; kdim = 128;
        W = uw2; H = g_u2h;
    }
    float v = W[k * HID + n];
    __half hh = __float2half_rn(v);
    H[n * kdim + k] = *(u16*)&hh;
}

// ---------------- FFMA GEMM pieces (proj) ----------------
template<int LDA, int RR>
static __device__ __forceinline__ void mmK(const float* __restrict__ A, const float* __restrict__ W,
                                           int K4, int i0, int j0, u64 acc[RR][4]){
    for (int c = 0; c < K4; ++c){
        float4 av[RR];
        #pragma unroll
        for (int ii = 0; ii < RR; ++ii)
            av[ii] = *(const float4*)(A + (i0 + ii) * LDA + (c << 2));
        const float* wr = W + (c << 2) * HID + j0;
        #pragma unroll
        for (int q = 0; q < 4; ++q){
            ulonglong2 wA = *(const ulonglong2*)(wr + q * HID);
            ulonglong2 wB = *(const ulonglong2*)(wr + q * HID + 4);
            #pragma unroll
            for (int ii = 0; ii < RR; ++ii){
                float aq = (q == 0) ? av[ii].x : (q == 1) ? av[ii].y : (q == 2) ? av[ii].z : av[ii].w;
                u64 a2 = pk2(aq);
                acc[ii][0] = ffma2(a2, wA.x, acc[ii][0]);
                acc[ii][1] = ffma2(a2, wA.y, acc[ii][1]);
                acc[ii][2] = ffma2(a2, wB.x, acc[ii][2]);
                acc[ii][3] = ffma2(a2, wB.y, acc[ii][3]);
            }
        }
    }
}

static __device__ __forceinline__ void write_imgh(int row, int j0, const float f[8]){
    u32 p0 = h2pack(f[0], f[1]);
    u32 p1 = h2pack(f[2], f[3]);
    u32 p2 = h2pack(f[4], f[5]);
    u32 p3 = h2pack(f[6], f[7]);
    *(uint4*)(&g_hf[(size_t)row * HID + j0]) = make_uint4(p0, p1, p2, p3);
}

// ---------------- projection ----------------
#define SMEM_PROJ ((64*132 + 128*128) * 4)
__global__ __launch_bounds__(256) void k_proj(const float* __restrict__ x, const float* __restrict__ pw,
                                              const float* __restrict__ pb, float* __restrict__ h, int N){
    extern __shared__ float sm[];
    const int LDA = 132;
    float* As = sm;
    float* Ws = sm + 64 * LDA;
    int tid = threadIdx.x;
    int r0  = blockIdx.x * 64;
    for (int i = tid; i < 4096; i += 256){
        int r = i >> 5, c4 = (i & 31) << 2;
        *(float4*)(Ws + r * HID + c4) = *(const float4*)(pw + (size_t)r * HID + c4);
    }
    {
        int i = tid >> 2, sub = tid & 3;
        int row = r0 + i;
        const float4* xr = (const float4*)(x + (size_t)(row < N ? row : 0) * HID);
        #pragma unroll
        for (int c = 0; c < 8; ++c){
            int k4 = (sub << 3) + c;
            *(float4*)(As + i * LDA + (k4 << 2)) = xr[k4];
        }
    }
    int ti = tid & 15, tj = tid >> 4;
    int i0 = tj << 2, j0 = ti << 3;
    float4 ba = *(const float4*)(pb + j0);
    float4 bb = *(const float4*)(pb + j0 + 4);
    __syncthreads();
    u64 acc[4][4];
    {
        u64 p0 = pk(ba.x, ba.y), p1 = pk(ba.z, ba.w);
        u64 p2 = pk(bb.x, bb.y), p3 = pk(bb.z, bb.w);
        #pragma unroll
        for (int ii = 0; ii < 4; ++ii){ acc[ii][0]=p0; acc[ii][1]=p1; acc[ii][2]=p2; acc[ii][3]=p3; }
    }
    mmK<132, 4>(As, Ws, 32, i0, j0, acc);
    #pragma unroll
    for (int ii = 0; ii < 4; ++ii){
        int row = r0 + i0 + ii;
        if (row < N){
            float* hr = h + (size_t)row * HID + j0;
            float f[8];
            #pragma unroll
            for (int p = 0; p < 4; ++p){
                f[2*p] = lo2(acc[ii][p]); f[2*p+1] = hi2(acc[ii][p]);
                *(float2*)(hr + (p << 1)) = make_float2(f[2*p], f[2*p+1]);
            }
            write_imgh(row, j0, f);
        }
    }
}

// ---------------- message MLP: HMMA fp16 (single-fp16 weights) ----------------
// SMEM: A fp16 [128][272] at 0; stage f32 [128][136] overlays 0..69631
// W1 at 69632 (34816), W2 at 104448 (34816); misc at 139264
#define MW1OFF 69632
#define MW2OFF 104448
#define MSDOFF 139264
#define SMEM_MSG (MSDOFF + 2560)

__global__ __launch_bounds__(512, 1) void k_msg(const float* __restrict__ mw1, const float* __restrict__ mb1,
                                                const float* __restrict__ mb2, int lvl){
    extern __shared__ char smc[];
    u32 smb = s2u(smc);
    int tid = threadIdx.x, wid = tid >> 5, lane = tid & 31;

    int*   sdst   = (int*)  (smc + MSDOFF);
    float* seat   = (float*)(smc + MSDOFF + 512);
    float* b1s    = (float*)(smc + MSDOFF + 1024);
    float* b2s    = (float*)(smc + MSDOFF + 1536);
    float* wls    = (float*)(smc + MSDOFF + 2048);
    float* stagef = (float*)(smc);

    for (int i = tid; i < 2048; i += 512){
        int n = i >> 4, kc = i & 15;
        u32 off = (u32)n * 272 + (u32)kc * 16;
        *(uint4*)(smc + MW1OFF + off) = ((const uint4*)g_w1h)[i];
        *(uint4*)(smc + MW2OFF + off) = ((const uint4*)g_w2h)[i];
    }
    if (tid < 128){
        b1s[tid] = mb1[tid];
        b2s[tid] = mb2[tid];
        wls[tid] = mw1[128 * HID + tid];
    }
    __syncthreads();

    int cnt  = g_ecnt[lvl];
    int base = g_eoff[lvl];
    int ntiles = (cnt + 127) >> 7;

    int rgrp = wid >> 1, nh = wid & 1;
    u32 afrag = smb + (u32)(rgrp * 16 + (lane & 15)) * 272 + (u32)((lane >> 4) << 4);
    int ra = rgrp * 16 + (lane >> 2);
    int rb = ra + 8;
    u32 lanemap = (u32)(((lane >> 4) << 3) + (lane & 7)) * 272 + (u32)(((lane >> 3) & 1) << 4);

    for (int t = blockIdx.x; t < ntiles; t += gridDim.x){
        {
            int m = tid >> 2, q = tid & 3;
            int p = t * 128 + m;
            int src = 0;
            if (p < cnt) src = g_esrc[base + p];
            if (q == 0){
                sdst[m] = (p < cnt) ? g_edst[base + p] : -1;
                seat[m] = (p < cnt) ? g_eatt[base + p] : 0.f;
            }
            const uint4* hr = (const uint4*)(&g_hf[(size_t)src * HID]);
            #pragma unroll
            for (int j = 0; j < 4; ++j){
                int q4 = q * 4 + j;
                *(uint4*)(smc + (u32)m * 272 + (u32)q4 * 16) = hr[q4];
            }
        }
        __syncthreads();

        u32 a[8][4];
        #pragma unroll
        for (int kc = 0; kc < 8; ++kc) LDX4(a[kc], afrag + kc * 32);
        float ea_a = seat[ra], ea_b = seat[rb];
        __syncthreads();

        // layer 1
        u32 w1b = smb + MW1OFF + (u32)(nh * 64) * 272 + lanemap;
        #pragma unroll
        for (int np = 0; np < 4; ++np){
            float aH0[4] = {0,0,0,0}, aH1[4] = {0,0,0,0};
            u32 wb = w1b + (u32)np * 16 * 272;
            #pragma unroll
            for (int kc = 0; kc < 8; ++kc){
                u32 bh[4];
                LDX4(bh, wb + kc * 32);
                MMAH(aH0, a[kc], bh[0], bh[1]);
                MMAH(aH1, a[kc], bh[2], bh[3]);
            }
            #pragma unroll
            for (int nch = 0; nch < 2; ++nch){
                const float* H = nch ? aH1 : aH0;
                int c = nh * 64 + np * 16 + nch * 8 + 2 * (lane & 3);
                float w0 = wls[c], w1v = wls[c+1], bb0 = b1s[c], bb1 = b1s[c+1];
                float v0 = fmaxf(H[0] + bb0 + ea_a * w0,  0.f);
                float v1 = fmaxf(H[1] + bb1 + ea_a * w1v, 0.f);
                *(u32*)(smc + (u32)ra * 272 + (u32)c * 2) = h2pack(v0, v1);
                v0 = fmaxf(H[2] + bb0 + ea_b * w0,  0.f);
                v1 = fmaxf(H[3] + bb1 + ea_b * w1v, 0.f);
                *(u32*)(smc + (u32)rb * 272 + (u32)c * 2) = h2pack(v0, v1);
            }
        }
        __syncthreads();
        #pragma unroll
        for (int kc = 0; kc < 8; ++kc) LDX4(a[kc], afrag + kc * 32);
        __syncthreads();

        // layer 2
        u32 w2b = smb + MW2OFF + (u32)(nh * 64) * 272 + lanemap;
        #pragma unroll
        for (int np = 0; np < 4; ++np){
            float aH0[4] = {0,0,0,0}, aH1[4] = {0,0,0,0};
            u32 wb = w2b + (u32)np * 16 * 272;
            #pragma unroll
            for (int kc = 0; kc < 8; ++kc){
                u32 bh[4];
                LDX4(bh, wb + kc * 32);
                MMAH(aH0, a[kc], bh[0], bh[1]);
                MMAH(aH1, a[kc], bh[2], bh[3]);
            }
            #pragma unroll
            for (int nch = 0; nch < 2; ++nch){
                const float* H = nch ? aH1 : aH0;
                int c = nh * 64 + np * 16 + nch * 8 + 2 * (lane & 3);
                float bb0 = b2s[c], bb1 = b2s[c+1];
                stagef[ra * 136 + c]     = fmaxf(H[0] + bb0, 0.f);
                stagef[ra * 136 + c + 1] = fmaxf(H[1] + bb1, 0.f);
                stagef[rb * 136 + c]     = fmaxf(H[2] + bb0, 0.f);
                stagef[rb * 136 + c + 1] = fmaxf(H[3] + bb1, 0.f);
            }
        }
        __syncthreads();

        {
            int c = tid & 127, g = tid >> 7;
            int r0 = g * 32;
            float run = 0.f;
            int prev = sdst[r0];
            for (int r = 0; r < 32; ++r){
                int d = sdst[r0 + r];
                float v = stagef[(r0 + r) * 136 + c];
                if (d != prev){
                    if (prev >= 0) atomicAdd(&g_agg[(size_t)prev * HID + c], run);
                    run = 0.f;
                    prev = d;
                }
                run += v;
            }
            if (prev >= 0) atomicAdd(&g_agg[(size_t)prev * HID + c], run);
        }
        __syncthreads();
    }
}

// ---------------- fused node update: HMMA, K=256 then K=128, per-tile in one block ----------------
// SMEM: A [128][528] at 0 (67584); T [128][272] at 67584 (34816);
// U1 at 102400 (67584); U2 at 169984 (34816); misc at 204800 (snode 512, b1 512, b2 512)
#define UT   67584
#define UW1  102400
#define UW2  169984
#define UMISC 204800
#define SMEM_UPD (UMISC + 1536)

__global__ __launch_bounds__(512, 1) void k_upd(float* __restrict__ h, const float* __restrict__ ub1,
                                                const float* __restrict__ ub2, int lvl){
    extern __shared__ char smc[];
    u32 smb = s2u(smc);
    int tid = threadIdx.x, wid = tid >> 5, lane = tid & 31;
    int*   snode = (int*)(smc + UMISC);
    float* b1s   = (float*)(smc + UMISC + 512);
    float* b2s   = (float*)(smc + UMISC + 1024);

    for (int i = tid; i < 4096; i += 512){
        int n = i >> 5, kc = i & 31;
        *(uint4*)(smc + UW1 + (u32)n * 528 + (u32)kc * 16) = ((const uint4*)g_u1h)[i];
    }
    for (int i = tid; i < 2048; i += 512){
        int n = i >> 4, kc = i & 15;
        *(uint4*)(smc + UW2 + (u32)n * 272 + (u32)kc * 16) = ((const uint4*)g_u2h)[i];
    }
    if (tid < 128){ b1s[tid] = ub1[tid]; b2s[tid] = ub2[tid]; }
    __syncthreads();

    int cnt  = g_ncnt[lvl];
    int base = g_noff[lvl];
    int ntiles = (cnt + 127) >> 7;

    int rgrp = wid >> 1, nh = wid & 1;
    u32 afrag1 = smb + (u32)(rgrp * 16 + (lane & 15)) * 528 + (u32)((lane >> 4) << 4);
    u32 afrag2 = smb + UT + (u32)(rgrp * 16 + (lane & 15)) * 272 + (u32)((lane >> 4) << 4);
    int ra = rgrp * 16 + (lane >> 2);
    int rb = ra + 8;
    u32 lanemap1 = (u32)(((lane >> 4) << 3) + (lane & 7)) * 528 + (u32)(((lane >> 3) & 1) << 4);
    u32 lanemap2 = (u32)(((lane >> 4) << 3) + (lane & 7)) * 272 + (u32)(((lane >> 3) & 1) << 4);

    for (int t = blockIdx.x; t < ntiles; t += gridDim.x){
        __syncthreads();
        {   // gather A = [h fp16 (16 uint4) | agg*inv fp16 (16 uint4)]
            int m = tid >> 2, q = tid & 3;
            int p = t * 128 + m;
            int v = (p < cnt) ? g_nperm[base + p] : 0;
            float inv = g_inv[v];
            if (q == 0) snode[m] = (p < cnt) ? v : -1;
            const uint4*  hr = (const uint4*)(&g_hf[(size_t)v * HID]);
            const float4* ar = (const float4*)(&g_agg[(size_t)v * HID]);
            #pragma unroll
            for (int j = 0; j < 4; ++j){
                int q4 = q * 4 + j;
                *(uint4*)(smc + (u32)m * 528 + (u32)q4 * 16) = hr[q4];
                float4 a0 = ar[2 * q4], a1 = ar[2 * q4 + 1];
                uint4 pv;
                pv.x = h2pack(a0.x * inv, a0.y * inv);
                pv.y = h2pack(a0.z * inv, a0.w * inv);
                pv.z = h2pack(a1.x * inv, a1.y * inv);
                pv.w = h2pack(a1.z * inv, a1.w * inv);
                *(uint4*)(smc + (u32)m * 528 + 256 + (u32)q4 * 16) = pv;
            }
        }
        __syncthreads();

        // layer 1 (K = 256)
        u32 a1[16][4];
        #pragma unroll
        for (int kc = 0; kc < 16; ++kc) LDX4(a1[kc], afrag1 + kc * 32);

        u32 w1b = smb + UW1 + (u32)(nh * 64) * 528 + lanemap1;
        #pragma unroll
        for (int np = 0; np < 4; ++np){
            float aH0[4] = {0,0,0,0}, aH1[4] = {0,0,0,0};
            u32 wb = w1b + (u32)np * 16 * 528;
            #pragma unroll
            for (int kc = 0; kc < 16; ++kc){
                u32 bh[4];
                LDX4(bh, wb + kc * 32);
                MMAH(aH0, a1[kc], bh[0], bh[1]);
                MMAH(aH1, a1[kc], bh[2], bh[3]);
            }
            #pragma unroll
            for (int nch = 0; nch < 2; ++nch){
                const float* H = nch ? aH1 : aH0;
                int c = nh * 64 + np * 16 + nch * 8 + 2 * (lane & 3);
                float bb0 = b1s[c], bb1 = b1s[c+1];
                float v0 = fmaxf(H[0] + bb0, 0.f);
                float v1 = fmaxf(H[1] + bb1, 0.f);
                *(u32*)(smc + UT + (u32)ra * 272 + (u32)c * 2) = h2pack(v0, v1);
                v0 = fmaxf(H[2] + bb0, 0.f);
                v1 = fmaxf(H[3] + bb1, 0.f);
                *(u32*)(smc + UT + (u32)rb * 272 + (u32)c * 2) = h2pack(v0, v1);
            }
        }
        PAIR_BAR(rgrp + 1);   // warp pair (both nh halves of these 16 rows) synced

        // layer 2 (K = 128)
        u32 a2[8][4];
        #pragma unroll
        for (int kc = 0; kc < 8; ++kc) LDX4(a2[kc], afrag2 + kc * 32);

        u32 w2b = smb + UW2 + (u32)(nh * 64) * 272 + lanemap2;
        int na = snode[ra], nb = snode[rb];
        #pragma unroll
        for (int np = 0; np < 4; ++np){
            float aH0[4] = {0,0,0,0}, aH1[4] = {0,0,0,0};
            u32 wb = w2b + (u32)np * 16 * 272;
            #pragma unroll
            for (int kc = 0; kc < 8; ++kc){
                u32 bh[4];
                LDX4(bh, wb + kc * 32);
                MMAH(aH0, a2[kc], bh[0], bh[1]);
                MMAH(aH1, a2[kc], bh[2], bh[3]);
            }
            #pragma unroll
            for (int nch = 0; nch < 2; ++nch){
                const float* H = nch ? aH1 : aH0;
                int c = nh * 64 + np * 16 + nch * 8 + 2 * (lane & 3);
                float bb0 = b2s[c], bb1 = b2s[c+1];
                float v0 = fmaxf(H[0] + bb0, 0.f);
                float v1 = fmaxf(H[1] + bb1, 0.f);
                if (na >= 0){
                    *(float2*)(h + (size_t)na * HID + c) = make_float2(v0, v1);
                    *(u32*)(&g_hf[(size_t)na * HID + c]) = h2pack(v0, v1);
                }
                v0 = fmaxf(H[2] + bb0, 0.f);
                v1 = fmaxf(H[3] + bb1, 0.f);
                if (nb >= 0){
                    *(float2*)(h + (size_t)nb * HID + c) = make_float2(v0, v1);
                    *(u32*)(&g_hf[(size_t)nb * HID + c]) = h2pack(v0, v1);
                }
            }
        }
    }
}

// ---------------- host launch ----------------
extern "C" void kernel_launch(void* const* d_in, const int* in_sizes, int n_in,
                              void* d_out, int out_size){
    const float* x     = (const float*)d_in[0];
    const int*   ei    = (const int*)  d_in[1];
    const float* eattr = (const float*)d_in[2];
    const int*   depth = (const int*)  d_in[3];
    const float* pw    = (const float*)d_in[4];
    const float* pb    = (const float*)d_in[5];
    const float* mw1   = (const float*)d_in[6];
    const float* mb1   = (const float*)d_in[7];
    const float* mw2   = (const float*)d_in[8];
    const float* mb2   = (const float*)d_in[9];
    const float* uw1   = (const float*)d_in[10];
    const float* ub1   = (const float*)d_in[11];
    const float* uw2   = (const float*)d_in[12];
    const float* ub2   = (const float*)d_in[13];
    float* h = (float*)d_out;

    int N = in_sizes[3];
    int E = in_sizes[2];

    static int sms = 0;
    if (sms == 0){
        cudaDeviceGetAttribute(&sms, cudaDevAttrMultiProcessorCount, 0);
        if (sms <= 0) sms = 148;
        cudaFuncSetAttribute(k_proj, cudaFuncAttributeMaxDynamicSharedMemorySize, SMEM_PROJ);
        cudaFuncSetAttribute(k_msg,  cudaFuncAttributeMaxDynamicSharedMemorySize, SMEM_MSG);
        cudaFuncSetAttribute(k_upd,  cudaFuncAttributeMaxDynamicSharedMemorySize, SMEM_UPD);
    }

    k_zero<<<1024, 256>>>(N * HID, N);
    k_prep<<<320, 256>>>(mw1, mw2, uw1, uw2);

    int mx = (E > N) ? E : N;
    k_count<<<(mx + 255) / 256, 256>>>(ei, depth, N, E);
    k_nscan<<<1, 32>>>();
    k_snodes<<<(N + 255) / 256, 256>>>(depth, N);
    k_escan1<<<256, 256>>>(N);
    k_escan2<<<1, 256>>>();
    k_escan3<<<256, 256>>>(N);
    k_levels<<<1, 32>>>(N, E);
    k_sedges<<<(E + 255) / 256, 256>>>(ei, eattr, E);

    k_proj<<<(N + 63) / 64, 256, SMEM_PROJ>>>(x, pw, pb, h, N);

    for (int d = 1; d <= 4; ++d){
        k_msg<<<sms, 512, SMEM_MSG>>>(mw1, mb1, mb2, d);
        k_upd<<<sms, 512, SMEM_UPD>>>(h, ub1, ub2, d);
    }
}

// round 13
// speedup vs baseline: 5.0463x; 1.0548x over previous
#include <cuda_runtime.h>
#include <cuda_fp16.h>

typedef unsigned int u32;
typedef unsigned long long u64;
typedef unsigned short u16;

#define HID 128
#define NMAX 50000
#define EMAX 500000

// ---------------- device scratch ----------------
__device__ float g_agg[(size_t)NMAX * HID];
__device__ float g_inv[NMAX];
__device__ int   g_indeg[NMAX];
__device__ int   g_nperm[NMAX];
__device__ int   g_rank[NMAX];
__device__ int   g_nodeoff[NMAX];
__device__ int   g_nodecur[NMAX];
__device__ int   g_partial[256];
__device__ int   g_ncnt[8], g_noff[8], g_ncur[8];
// sorted edge arrays (by level, then dst)
__device__ int   g_esrc[EMAX];
__device__ int   g_edst[EMAX];
__device__ float g_eatt[EMAX];
// fp16 image of h
__device__ u16   g_hf[(size_t)NMAX * HID];
// weight images, [n][k] row-major, single fp16
__device__ u16   g_w1h[16384], g_w2h[16384];
__device__ u16   g_u1h[32768], g_u2h[16384];

// ---------------- helpers ----------------
static __device__ __forceinline__ u64 pk(float x, float y){
    u64 r; asm("mov.b64 %0, {%1, %2};" : "=l"(r) : "f"(x), "f"(y)); return r;
}
static __device__ __forceinline__ u64 pk2(float a){ return pk(a, a); }
static __device__ __forceinline__ u64 ffma2(u64 a, u64 b, u64 c){
    u64 d; asm("fma.rn.f32x2 %0, %1, %2, %3;" : "=l"(d) : "l"(a), "l"(b), "l"(c)); return d;
}
static __device__ __forceinline__ float lo2(u64 v){ return __uint_as_float((u32)v); }
static __device__ __forceinline__ float hi2(u64 v){ return __uint_as_float((u32)(v >> 32)); }
static __device__ __forceinline__ u32 h2pack(float f0, float f1){
    __half2 h = __floats2half2_rn(f0, f1);
    return *(u32*)&h;
}
static __device__ __forceinline__ u32 s2u(const void* p){
    u32 a; asm("{ .reg .u64 t; cvta.to.shared.u64 t, %1; cvt.u32.u64 %0, t; }" : "=r"(a) : "l"(p));
    return a;
}

#define LDX4(r, a) \
    asm volatile("ldmatrix.sync.aligned.m8n8.x4.shared.b16 {%0,%1,%2,%3}, [%4];" \
        : "=r"((r)[0]), "=r"((r)[1]), "=r"((r)[2]), "=r"((r)[3]) : "r"(a))

#define MMAH(d, a, b0, b1) \
    asm("mma.sync.aligned.m16n8k16.row.col.f32.f16.f16.f32 " \
        "{%0,%1,%2,%3}, {%4,%5,%6,%7}, {%8,%9}, {%0,%1,%2,%3};" \
        : "+f"((d)[0]), "+f"((d)[1]), "+f"((d)[2]), "+f"((d)[3]) \
        : "r"((a)[0]), "r"((a)[1]), "r"((a)[2]), "r"((a)[3]), "r"(b0), "r"(b1))

#define PAIR_BAR(id) asm volatile("bar.sync %0, 64;" :: "r"(id) : "memory")

// ---------------- bucketing ----------------
__global__ void k_zero(int nagg, int N){
    int i  = blockIdx.x * blockDim.x + threadIdx.x;
    int st = gridDim.x * blockDim.x;
    for (int j = i; j < nagg; j += st) g_agg[j] = 0.f;
    for (int j = i; j < N;    j += st) g_indeg[j] = 0;
    if (i < 8) g_ncnt[i] = 0;
}

__global__ void k_count(const int* __restrict__ ei, const int* __restrict__ depth, int N, int E){
    __shared__ int scnt[8];
    int t = threadIdx.x;
    if (t < 8) scnt[t] = 0;
    __syncthreads();
    int i = blockIdx.x * blockDim.x + t;
    if (i < E) atomicAdd(&g_indeg[ei[E + i]], 1);
    if (i < N) atomicAdd(&scnt[depth[i]], 1);
    __syncthreads();
    if (t < 8 && scnt[t]) atomicAdd(&g_ncnt[t], scnt[t]);
}

__global__ void k_nscan(){
    int t = threadIdx.x;
    if (t < 8){
        int s = 0;
        #pragma unroll
        for (int d = 0; d < 8; ++d)
            if (d < t) s += g_ncnt[d];
        g_noff[t] = s; g_ncur[t] = s;
    }
}

__global__ void k_snodes(const int* __restrict__ depth, int N){
    __shared__ int scnt[8], sbase[8];
    int t = threadIdx.x;
    if (t < 8) scnt[t] = 0;
    __syncthreads();
    int i = blockIdx.x * blockDim.x + t;
    int d = 0, pl = 0;
    if (i < N){ d = depth[i]; pl = atomicAdd(&scnt[d], 1); }
    __syncthreads();
    if (t < 8) sbase[t] = scnt[t] ? atomicAdd(&g_ncur[t], scnt[t]) : 0;
    __syncthreads();
    if (i < N){
        int pos = sbase[d] + pl;
        g_nperm[pos] = i;
        g_rank[i] = pos;
        int c = g_indeg[i];
        g_inv[i] = 1.0f / (float)(c > 0 ? c : 1);
    }
}

__global__ void k_escan1(int N){
    __shared__ int sh[256];
    int chunk = (N + 255) / 256;
    int t = threadIdx.x;
    int i = blockIdx.x * chunk + t;
    int v = 0;
    if (t < chunk && i < N) v = g_indeg[g_nperm[i]];
    sh[t] = v; __syncthreads();
    for (int s = 128; s > 0; s >>= 1){
        if (t < s) sh[t] += sh[t + s];
        __syncthreads();
    }
    if (t == 0) g_partial[blockIdx.x] = sh[0];
}
__global__ void k_escan2(){
    __shared__ int sh[256];
    int t = threadIdx.x;
    int orig = g_partial[t];
    sh[t] = orig; __syncthreads();
    for (int s = 1; s < 256; s <<= 1){
        int v = (t >= s) ? sh[t - s] : 0;
        __syncthreads();
        sh[t] += v;
        __syncthreads();
    }
    g_partial[t] = sh[t] - orig;
}
__global__ void k_escan3(int N){
    __shared__ int sh[256];
    int chunk = (N + 255) / 256;
    int t = threadIdx.x;
    int i = blockIdx.x * chunk + t;
    int orig = 0;
    if (t < chunk && i < N) orig = g_indeg[g_nperm[i]];
    sh[t] = orig; __syncthreads();
    for (int s = 1; s < 256; s <<= 1){
        int v = (t >= s) ? sh[t - s] : 0;
        __syncthreads();
        sh[t] += v;
        __syncthreads();
    }
    if (t < chunk && i < N){
        int excl = g_partial[blockIdx.x] + sh[t] - orig;
        g_nodeoff[i] = excl;
        g_nodecur[i] = excl;
    }
}
__global__ void k_sedges(const int* __restrict__ ei, const float* __restrict__ eattr, int E){
    int e = blockIdx.x * blockDim.x + threadIdx.x;
    if (e < E){
        int dst = ei[E + e];
        int pos = atomicAdd(&g_nodecur[g_rank[dst]], 1);
        g_esrc[pos] = ei[e];
        g_edst[pos] = dst;
        g_eatt[pos] = eattr[e];
    }
}

// ---------------- weight image prep: [n][k] = W[k][n], single fp16 ----------------
__global__ void k_prep(const float* __restrict__ mw1, const float* __restrict__ mw2,
                       const float* __restrict__ uw1, const float* __restrict__ uw2){
    int idx = blockIdx.x * blockDim.x + threadIdx.x;
    if (idx >= 81920) return;
    const float* W; u16 *H; int n, k, kdim;
    if (idx < 32768){
        int mtx = idx >> 14, rem = idx & 16383;
        n = rem >> 7; k = rem & 127; kdim = 128;
        W = mtx ? mw2 : mw1; H = mtx ? g_w2h : g_w1h;
    } else if (idx < 65536){
        int j = idx - 32768;
        n = j >> 8; k = j & 255; kdim = 256;
        W = uw1; H = g_u1h;
    } else {
        int j = idx - 65536;
        n = j >> 7; k = j & 127; kdim = 128;
        W = uw2; H = g_u2h;
    }
    float v = W[k * HID + n];
    __half hh = __float2half_rn(v);
    H[n * kdim + k] = *(u16*)&hh;
}

// ---------------- FFMA GEMM pieces (proj) ----------------
template<int LDA, int RR>
static __device__ __forceinline__ void mmK(const float* __restrict__ A, const float* __restrict__ W,
                                           int K4, int i0, int j0, u64 acc[RR][4]){
    for (int c = 0; c < K4; ++c){
        float4 av[RR];
        #pragma unroll
        for (int ii = 0; ii < RR; ++ii)
            av[ii] = *(const float4*)(A + (i0 + ii) * LDA + (c << 2));
        const float* wr = W + (c << 2) * HID + j0;
        #pragma unroll
        for (int q = 0; q < 4; ++q){
            ulonglong2 wA = *(const ulonglong2*)(wr + q * HID);
            ulonglong2 wB = *(const ulonglong2*)(wr + q * HID + 4);
            #pragma unroll
            for (int ii = 0; ii < RR; ++ii){
                float aq = (q == 0) ? av[ii].x : (q == 1) ? av[ii].y : (q == 2) ? av[ii].z : av[ii].w;
                u64 a2 = pk2(aq);
                acc[ii][0] = ffma2(a2, wA.x, acc[ii][0]);
                acc[ii][1] = ffma2(a2, wA.y, acc[ii][1]);
                acc[ii][2] = ffma2(a2, wB.x, acc[ii][2]);
                acc[ii][3] = ffma2(a2, wB.y, acc[ii][3]);
            }
        }
    }
}

static __device__ __forceinline__ void write_imgh(int row, int j0, const float f[8]){
    u32 p0 = h2pack(f[0], f[1]);
    u32 p1 = h2pack(f[2], f[3]);
    u32 p2 = h2pack(f[4], f[5]);
    u32 p3 = h2pack(f[6], f[7]);
    *(uint4*)(&g_hf[(size_t)row * HID + j0]) = make_uint4(p0, p1, p2, p3);
}

// ---------------- projection ----------------
#define SMEM_PROJ ((64*132 + 128*128) * 4)
__global__ __launch_bounds__(256) void k_proj(const float* __restrict__ x, const float* __restrict__ pw,
                                              const float* __restrict__ pb, float* __restrict__ h, int N){
    extern __shared__ float sm[];
    const int LDA = 132;
    float* As = sm;
    float* Ws = sm + 64 * LDA;
    int tid = threadIdx.x;
    int r0  = blockIdx.x * 64;
    for (int i = tid; i < 4096; i += 256){
        int r = i >> 5, c4 = (i & 31) << 2;
        *(float4*)(Ws + r * HID + c4) = *(const float4*)(pw + (size_t)r * HID + c4);
    }
    {
        int i = tid >> 2, sub = tid & 3;
        int row = r0 + i;
        const float4* xr = (const float4*)(x + (size_t)(row < N ? row : 0) * HID);
        #pragma unroll
        for (int c = 0; c < 8; ++c){
            int k4 = (sub << 3) + c;
            *(float4*)(As + i * LDA + (k4 << 2)) = xr[k4];
        }
    }
    int ti = tid & 15, tj = tid >> 4;
    int i0 = tj << 2, j0 = ti << 3;
    float4 ba = *(const float4*)(pb + j0);
    float4 bb = *(const float4*)(pb + j0 + 4);
    __syncthreads();
    u64 acc[4][4];
    {
        u64 p0 = pk(ba.x, ba.y), p1 = pk(ba.z, ba.w);
        u64 p2 = pk(bb.x, bb.y), p3 = pk(bb.z, bb.w);
        #pragma unroll
        for (int ii = 0; ii < 4; ++ii){ acc[ii][0]=p0; acc[ii][1]=p1; acc[ii][2]=p2; acc[ii][3]=p3; }
    }
    mmK<132, 4>(As, Ws, 32, i0, j0, acc);
    #pragma unroll
    for (int ii = 0; ii < 4; ++ii){
        int row = r0 + i0 + ii;
        if (row < N){
            float* hr = h + (size_t)row * HID + j0;
            float f[8];
            #pragma unroll
            for (int p = 0; p < 4; ++p){
                f[2*p] = lo2(acc[ii][p]); f[2*p+1] = hi2(acc[ii][p]);
                *(float2*)(hr + (p << 1)) = make_float2(f[2*p], f[2*p+1]);
            }
            write_imgh(row, j0, f);
        }
    }
}

// ---------------- message MLP: HMMA fp16, warp-owns-rows, 2 blocks/SM ----------------
// SMEM: A/T/stage fp16 [128][272] at 0 (34816); W1 at 34816; W2 at 69632; misc at 104448
#define MW1OFF 34816
#define MW2OFF 69632
#define MSDOFF 104448
#define SMEM_MSG (MSDOFF + 2560)

__global__ __launch_bounds__(256, 2) void k_msg(const float* __restrict__ mw1, const float* __restrict__ mb1,
                                                const float* __restrict__ mb2, int N, int E, int lvl){
    extern __shared__ char smc[];
    u32 smb = s2u(smc);
    int tid = threadIdx.x, wid = tid >> 5, lane = tid & 31;

    int*   sdst = (int*)  (smc + MSDOFF);
    float* seat = (float*)(smc + MSDOFF + 512);
    float* b1s  = (float*)(smc + MSDOFF + 1024);
    float* b2s  = (float*)(smc + MSDOFF + 1536);
    float* wls  = (float*)(smc + MSDOFF + 2048);

    for (int i = tid; i < 2048; i += 256){
        int n = i >> 4, kc = i & 15;
        u32 off = (u32)n * 272 + (u32)kc * 16;
        *(uint4*)(smc + MW1OFF + off) = ((const uint4*)g_w1h)[i];
        *(uint4*)(smc + MW2OFF + off) = ((const uint4*)g_w2h)[i];
    }
    if (tid < 128){
        b1s[tid] = mb1[tid];
        b2s[tid] = mb2[tid];
        wls[tid] = mw1[128 * HID + tid];
    }
    __syncthreads();

    // level edge range from node offsets
    int b0 = g_noff[lvl];
    int ncount = g_ncnt[lvl];
    int b1 = b0 + ncount;
    int base = (b0 < N) ? g_nodeoff[b0] : E;
    int eend = (b1 < N) ? g_nodeoff[b1] : E;
    int cnt = eend - base;
    int ntiles = (cnt + 127) >> 7;

    // warp owns rows wid*16..+15, full 128 cols
    u32 afrag = smb + (u32)(wid * 16 + (lane & 15)) * 272 + (u32)((lane >> 4) << 4);
    int ra = wid * 16 + (lane >> 2);
    int rb = ra + 8;
    u32 lanemap = (u32)(((lane >> 4) << 3) + (lane & 7)) * 272 + (u32)(((lane >> 3) & 1) << 4);

    for (int t = blockIdx.x; t < ntiles; t += gridDim.x){
        {   // gather: 2 threads per row, 8 uint4 each
            int m = tid >> 1, q = tid & 1;
            int p = t * 128 + m;
            int src = 0;
            if (p < cnt) src = g_esrc[base + p];
            if (q == 0){
                sdst[m] = (p < cnt) ? g_edst[base + p] : -1;
                seat[m] = (p < cnt) ? g_eatt[base + p] : 0.f;
            }
            const uint4* hr = (const uint4*)(&g_hf[(size_t)src * HID]);
            #pragma unroll
            for (int j = 0; j < 8; ++j){
                int q8 = q * 8 + j;
                *(uint4*)(smc + (u32)m * 272 + (u32)q8 * 16) = hr[q8];
            }
        }
        __syncthreads();

        u32 a[8][4];
        #pragma unroll
        for (int kc = 0; kc < 8; ++kc) LDX4(a[kc], afrag + kc * 32);
        float ea_a = seat[ra], ea_b = seat[rb];
        __syncwarp();

        // layer 1: all 8 col groups, T written into own rows (overwrites A)
        u32 w1b = smb + MW1OFF + lanemap;
        #pragma unroll
        for (int np = 0; np < 8; ++np){
            float aH0[4] = {0,0,0,0}, aH1[4] = {0,0,0,0};
            u32 wb = w1b + (u32)np * 16 * 272;
            #pragma unroll
            for (int kc = 0; kc < 8; ++kc){
                u32 bh[4];
                LDX4(bh, wb + kc * 32);
                MMAH(aH0, a[kc], bh[0], bh[1]);
                MMAH(aH1, a[kc], bh[2], bh[3]);
            }
            #pragma unroll
            for (int nch = 0; nch < 2; ++nch){
                const float* H = nch ? aH1 : aH0;
                int c = np * 16 + nch * 8 + 2 * (lane & 3);
                float w0 = wls[c], w1v = wls[c+1], bb0 = b1s[c], bb1 = b1s[c+1];
                float v0 = fmaxf(H[0] + bb0 + ea_a * w0,  0.f);
                float v1 = fmaxf(H[1] + bb1 + ea_a * w1v, 0.f);
                *(u32*)(smc + (u32)ra * 272 + (u32)c * 2) = h2pack(v0, v1);
                v0 = fmaxf(H[2] + bb0 + ea_b * w0,  0.f);
                v1 = fmaxf(H[3] + bb1 + ea_b * w1v, 0.f);
                *(u32*)(smc + (u32)rb * 272 + (u32)c * 2) = h2pack(v0, v1);
            }
        }
        __syncwarp();
        #pragma unroll
        for (int kc = 0; kc < 8; ++kc) LDX4(a[kc], afrag + kc * 32);
        __syncwarp();

        // layer 2: stage (half2) written into own rows (overwrites T)
        u32 w2b = smb + MW2OFF + lanemap;
        #pragma unroll
        for (int np = 0; np < 8; ++np){
            float aH0[4] = {0,0,0,0}, aH1[4] = {0,0,0,0};
            u32 wb = w2b + (u32)np * 16 * 272;
            #pragma unroll
            for (int kc = 0; kc < 8; ++kc){
                u32 bh[4];
                LDX4(bh, wb + kc * 32);
                MMAH(aH0, a[kc], bh[0], bh[1]);
                MMAH(aH1, a[kc], bh[2], bh[3]);
            }
            #pragma unroll
            for (int nch = 0; nch < 2; ++nch){
                const float* H = nch ? aH1 : aH0;
                int c = np * 16 + nch * 8 + 2 * (lane & 3);
                float bb0 = b2s[c], bb1 = b2s[c+1];
                float v0 = fmaxf(H[0] + bb0, 0.f);
                float v1 = fmaxf(H[1] + bb1, 0.f);
                *(u32*)(smc + (u32)ra * 272 + (u32)c * 2) = h2pack(v0, v1);
                v0 = fmaxf(H[2] + bb0, 0.f);
                v1 = fmaxf(H[3] + bb1, 0.f);
                *(u32*)(smc + (u32)rb * 272 + (u32)c * 2) = h2pack(v0, v1);
            }
        }
        __syncthreads();

        // segmented flush (dst-sorted rows): 4 groups x 32 rows, half2 cols
        {
            int c2 = tid & 63, g = tid >> 6;
            int r0 = g * 32;
            float run0 = 0.f, run1 = 0.f;
            int prev = sdst[r0];
            for (int r = 0; r < 32; ++r){
                int rr = r0 + r;
                int d = sdst[rr];
                u32 pv = *(u32*)(smc + (u32)rr * 272 + (u32)c2 * 4);
                __half2 hv = *(__half2*)&pv;
                float2 fv = __half22float2(hv);
                if (d != prev){
                    if (prev >= 0){
                        atomicAdd(&g_agg[(size_t)prev * HID + 2*c2],     run0);
                        atomicAdd(&g_agg[(size_t)prev * HID + 2*c2 + 1], run1);
                    }
                    run0 = 0.f; run1 = 0.f;
                    prev = d;
                }
                run0 += fv.x; run1 += fv.y;
            }
            if (prev >= 0){
                atomicAdd(&g_agg[(size_t)prev * HID + 2*c2],     run0);
                atomicAdd(&g_agg[(size_t)prev * HID + 2*c2 + 1], run1);
            }
        }
        __syncthreads();
    }
}

// ---------------- fused node update: HMMA, K=256 then K=128 ----------------
// SMEM: A [128][528] at 0 (67584); T [128][272] at 67584 (34816);
// U1 at 102400 (67584); U2 at 169984 (34816); misc at 204800
#define UT   67584
#define UW1  102400
#define UW2  169984
#define UMISC 204800
#define SMEM_UPD (UMISC + 1536)

__global__ __launch_bounds__(512, 1) void k_upd(float* __restrict__ h, const float* __restrict__ ub1,
                                                const float* __restrict__ ub2, int lvl){
    extern __shared__ char smc[];
    u32 smb = s2u(smc);
    int tid = threadIdx.x, wid = tid >> 5, lane = tid & 31;
    int*   snode = (int*)(smc + UMISC);
    float* b1s   = (float*)(smc + UMISC + 512);
    float* b2s   = (float*)(smc + UMISC + 1024);

    for (int i = tid; i < 4096; i += 512){
        int n = i >> 5, kc = i & 31;
        *(uint4*)(smc + UW1 + (u32)n * 528 + (u32)kc * 16) = ((const uint4*)g_u1h)[i];
    }
    for (int i = tid; i < 2048; i += 512){
        int n = i >> 4, kc = i & 15;
        *(uint4*)(smc + UW2 + (u32)n * 272 + (u32)kc * 16) = ((const uint4*)g_u2h)[i];
    }
    if (tid < 128){ b1s[tid] = ub1[tid]; b2s[tid] = ub2[tid]; }
    __syncthreads();

    int cnt  = g_ncnt[lvl];
    int base = g_noff[lvl];
    int ntiles = (cnt + 127) >> 7;

    int rgrp = wid >> 1, nh = wid & 1;
    u32 afrag1 = smb + (u32)(rgrp * 16 + (lane & 15)) * 528 + (u32)((lane >> 4) << 4);
    u32 afrag2 = smb + UT + (u32)(rgrp * 16 + (lane & 15)) * 272 + (u32)((lane >> 4) << 4);
    int ra = rgrp * 16 + (lane >> 2);
    int rb = ra + 8;
    u32 lanemap1 = (u32)(((lane >> 4) << 3) + (lane & 7)) * 528 + (u32)(((lane >> 3) & 1) << 4);
    u32 lanemap2 = (u32)(((lane >> 4) << 3) + (lane & 7)) * 272 + (u32)(((lane >> 3) & 1) << 4);

    for (int t = blockIdx.x; t < ntiles; t += gridDim.x){
        __syncthreads();
        {   // gather A = [h fp16 | agg*inv fp16]
            int m = tid >> 2, q = tid & 3;
            int p = t * 128 + m;
            int v = (p < cnt) ? g_nperm[base + p] : 0;
            float inv = g_inv[v];
            if (q == 0) snode[m] = (p < cnt) ? v : -1;
            const uint4*  hr = (const uint4*)(&g_hf[(size_t)v * HID]);
            const float4* ar = (const float4*)(&g_agg[(size_t)v * HID]);
            #pragma unroll
            for (int j = 0; j < 4; ++j){
                int q4 = q * 4 + j;
                *(uint4*)(smc + (u32)m * 528 + (u32)q4 * 16) = hr[q4];
                float4 a0 = ar[2 * q4], a1 = ar[2 * q4 + 1];
                uint4 pv;
                pv.x = h2pack(a0.x * inv, a0.y * inv);
                pv.y = h2pack(a0.z * inv, a0.w * inv);
                pv.z = h2pack(a1.x * inv, a1.y * inv);
                pv.w = h2pack(a1.z * inv, a1.w * inv);
                *(uint4*)(smc + (u32)m * 528 + 256 + (u32)q4 * 16) = pv;
            }
        }
        __syncthreads();

        // layer 1 (K = 256)
        u32 a1[16][4];
        #pragma unroll
        for (int kc = 0; kc < 16; ++kc) LDX4(a1[kc], afrag1 + kc * 32);

        u32 w1b = smb + UW1 + (u32)(nh * 64) * 528 + lanemap1;
        #pragma unroll
        for (int np = 0; np < 4; ++np){
            float aH0[4] = {0,0,0,0}, aH1[4] = {0,0,0,0};
            u32 wb = w1b + (u32)np * 16 * 528;
            #pragma unroll
            for (int kc = 0; kc < 16; ++kc){
                u32 bh[4];
                LDX4(bh, wb + kc * 32);
                MMAH(aH0, a1[kc], bh[0], bh[1]);
                MMAH(aH1, a1[kc], bh[2], bh[3]);
            }
            #pragma unroll
            for (int nch = 0; nch < 2; ++nch){
                const float* H = nch ? aH1 : aH0;
                int c = nh * 64 + np * 16 + nch * 8 + 2 * (lane & 3);
                float bb0 = b1s[c], bb1 = b1s[c+1];
                float v0 = fmaxf(H[0] + bb0, 0.f);
                float v1 = fmaxf(H[1] + bb1, 0.f);
                *(u32*)(smc + UT + (u32)ra * 272 + (u32)c * 2) = h2pack(v0, v1);
                v0 = fmaxf(H[2] + bb0, 0.f);
                v1 = fmaxf(H[3] + bb1, 0.f);
                *(u32*)(smc + UT + (u32)rb * 272 + (u32)c * 2) = h2pack(v0, v1);
            }
        }
        PAIR_BAR(rgrp + 1);

        // layer 2 (K = 128)
        u32 a2[8][4];
        #pragma unroll
        for (int kc = 0; kc < 8; ++kc) LDX4(a2[kc], afrag2 + kc * 32);

        u32 w2b = smb + UW2 + (u32)(nh * 64) * 272 + lanemap2;
        int na = snode[ra], nb = snode[rb];
        #pragma unroll
        for (int np = 0; np < 4; ++np){
            float aH0[4] = {0,0,0,0}, aH1[4] = {0,0,0,0};
            u32 wb = w2b + (u32)np * 16 * 272;
            #pragma unroll
            for (int kc = 0; kc < 8; ++kc){
                u32 bh[4];
                LDX4(bh, wb + kc * 32);
                MMAH(aH0, a2[kc], bh[0], bh[1]);
                MMAH(aH1, a2[kc], bh[2], bh[3]);
            }
            #pragma unroll
            for (int nch = 0; nch < 2; ++nch){
                const float* H = nch ? aH1 : aH0;
                int c = nh * 64 + np * 16 + nch * 8 + 2 * (lane & 3);
                float bb0 = b2s[c], bb1 = b2s[c+1];
                float v0 = fmaxf(H[0] + bb0, 0.f);
                float v1 = fmaxf(H[1] + bb1, 0.f);
                if (na >= 0){
                    *(float2*)(h + (size_t)na * HID + c) = make_float2(v0, v1);
                    *(u32*)(&g_hf[(size_t)na * HID + c]) = h2pack(v0, v1);
                }
                v0 = fmaxf(H[2] + bb0, 0.f);
                v1 = fmaxf(H[3] + bb1, 0.f);
                if (nb >= 0){
                    *(float2*)(h + (size_t)nb * HID + c) = make_float2(v0, v1);
                    *(u32*)(&g_hf[(size_t)nb * HID + c]) = h2pack(v0, v1);
                }
            }
        }
    }
}

// ---------------- host launch ----------------
extern "C" void kernel_launch(void* const* d_in, const int* in_sizes, int n_in,
                              void* d_out, int out_size){
    const float* x     = (const float*)d_in[0];
    const int*   ei    = (const int*)  d_in[1];
    const float* eattr = (const float*)d_in[2];
    const int*   depth = (const int*)  d_in[3];
    const float* pw    = (const float*)d_in[4];
    const float* pb    = (const float*)d_in[5];
    const float* mw1   = (const float*)d_in[6];
    const float* mb1   = (const float*)d_in[7];
    const float* mw2   = (const float*)d_in[8];
    const float* mb2   = (const float*)d_in[9];
    const float* uw1   = (const float*)d_in[10];
    const float* ub1   = (const float*)d_in[11];
    const float* uw2   = (const float*)d_in[12];
    const float* ub2   = (const float*)d_in[13];
    float* h = (float*)d_out;

    int N = in_sizes[3];
    int E = in_sizes[2];

    static int sms = 0;
    if (sms == 0){
        cudaDeviceGetAttribute(&sms, cudaDevAttrMultiProcessorCount, 0);
        if (sms <= 0) sms = 148;
        cudaFuncSetAttribute(k_proj, cudaFuncAttributeMaxDynamicSharedMemorySize, SMEM_PROJ);
        cudaFuncSetAttribute(k_msg,  cudaFuncAttributeMaxDynamicSharedMemorySize, SMEM_MSG);
        cudaFuncSetAttribute(k_upd,  cudaFuncAttributeMaxDynamicSharedMemorySize, SMEM_UPD);
    }

    k_zero<<<1024, 256>>>(N * HID, N);
    k_prep<<<320, 256>>>(mw1, mw2, uw1, uw2);

    int mx = (E > N) ? E : N;
    k_count<<<(mx + 255) / 256, 256>>>(ei, depth, N, E);
    k_nscan<<<1, 32>>>();
    k_snodes<<<(N + 255) / 256, 256>>>(depth, N);
    k_escan1<<<256, 256>>>(N);
    k_escan2<<<1, 256>>>();
    k_escan3<<<256, 256>>>(N);
    k_sedges<<<(E + 255) / 256, 256>>>(ei, eattr, E);

    k_proj<<<(N + 63) / 64, 256, SMEM_PROJ>>>(x, pw, pb, h, N);

    for (int d = 1; d <= 4; ++d){
        k_msg<<<2 * sms, 256, SMEM_MSG>>>(mw1, mb1, mb2, N, E, d);
        k_upd<<<sms, 512, SMEM_UPD>>>(h, ub1, ub2, d);
    }
}

// round 14
// speedup vs baseline: 6.4552x; 1.2792x over previous
#include <cuda_runtime.h>
#include <cuda_fp16.h>

typedef unsigned int u32;
typedef unsigned long long u64;
typedef unsigned short u16;

#define HID 128
#define NMAX 50000
#define EMAX 500000

// ---------------- device scratch ----------------
__device__ float g_agg[(size_t)NMAX * HID];
__device__ float g_inv[NMAX];
__device__ int   g_indeg[NMAX];
__device__ int   g_nperm[NMAX];
__device__ int   g_rank[NMAX];
__device__ int   g_nodeoff[NMAX];
__device__ int   g_nodecur[NMAX];
__device__ int   g_partial[256];
__device__ int   g_ncnt[8], g_noff[8], g_ncur[8];
// sorted edge arrays (by level, then dst)
__device__ int   g_esrc[EMAX];
__device__ int   g_edst[EMAX];
__device__ float g_eatt[EMAX];
// fp16 image of h
__device__ u16   g_hf[(size_t)NMAX * HID];
// weight images, [n][k] row-major, single fp16
__device__ u16   g_w1h[16384], g_w2h[16384];
__device__ u16   g_u1h[32768], g_u2h[16384];
__device__ u16   g_pwh[16384];

// ---------------- helpers ----------------
static __device__ __forceinline__ u32 h2pack(float f0, float f1){
    __half2 h = __floats2half2_rn(f0, f1);
    return *(u32*)&h;
}
static __device__ __forceinline__ u32 s2u(const void* p){
    u32 a; asm("{ .reg .u64 t; cvta.to.shared.u64 t, %1; cvt.u32.u64 %0, t; }" : "=r"(a) : "l"(p));
    return a;
}

#define LDX4(r, a) \
    asm volatile("ldmatrix.sync.aligned.m8n8.x4.shared.b16 {%0,%1,%2,%3}, [%4];" \
        : "=r"((r)[0]), "=r"((r)[1]), "=r"((r)[2]), "=r"((r)[3]) : "r"(a))

#define MMAH(d, a, b0, b1) \
    asm("mma.sync.aligned.m16n8k16.row.col.f32.f16.f16.f32 " \
        "{%0,%1,%2,%3}, {%4,%5,%6,%7}, {%8,%9}, {%0,%1,%2,%3};" \
        : "+f"((d)[0]), "+f"((d)[1]), "+f"((d)[2]), "+f"((d)[3]) \
        : "r"((a)[0]), "r"((a)[1]), "r"((a)[2]), "r"((a)[3]), "r"(b0), "r"(b1))

#define PAIR_BAR(id) asm volatile("bar.sync %0, 64;" :: "r"(id) : "memory")

// ---------------- bucketing ----------------
__global__ void k_zero(int nagg, int N){
    int i  = blockIdx.x * blockDim.x + threadIdx.x;
    int st = gridDim.x * blockDim.x;
    for (int j = i; j < nagg; j += st) g_agg[j] = 0.f;
    for (int j = i; j < N;    j += st) g_indeg[j] = 0;
    if (i < 8) g_ncnt[i] = 0;
}

__global__ void k_count(const int* __restrict__ ei, const int* __restrict__ depth, int N, int E){
    __shared__ int scnt[8];
    int t = threadIdx.x;
    if (t < 8) scnt[t] = 0;
    __syncthreads();
    int i = blockIdx.x * blockDim.x + t;
    if (i < E) atomicAdd(&g_indeg[ei[E + i]], 1);
    if (i < N) atomicAdd(&scnt[depth[i]], 1);
    __syncthreads();
    if (t < 8 && scnt[t]) atomicAdd(&g_ncnt[t], scnt[t]);
}

__global__ void k_nscan(){
    int t = threadIdx.x;
    if (t < 8){
        int s = 0;
        #pragma unroll
        for (int d = 0; d < 8; ++d)
            if (d < t) s += g_ncnt[d];
        g_noff[t] = s; g_ncur[t] = s;
    }
}

__global__ void k_snodes(const int* __restrict__ depth, int N){
    __shared__ int scnt[8], sbase[8];
    int t = threadIdx.x;
    if (t < 8) scnt[t] = 0;
    __syncthreads();
    int i = blockIdx.x * blockDim.x + t;
    int d = 0, pl = 0;
    if (i < N){ d = depth[i]; pl = atomicAdd(&scnt[d], 1); }
    __syncthreads();
    if (t < 8) sbase[t] = scnt[t] ? atomicAdd(&g_ncur[t], scnt[t]) : 0;
    __syncthreads();
    if (i < N){
        int pos = sbase[d] + pl;
        g_nperm[pos] = i;
        g_rank[i] = pos;
        int c = g_indeg[i];
        g_inv[i] = 1.0f / (float)(c > 0 ? c : 1);
    }
}

__global__ void k_escan1(int N){
    __shared__ int sh[256];
    int chunk = (N + 255) / 256;
    int t = threadIdx.x;
    int i = blockIdx.x * chunk + t;
    int v = 0;
    if (t < chunk && i < N) v = g_indeg[g_nperm[i]];
    sh[t] = v; __syncthreads();
    for (int s = 128; s > 0; s >>= 1){
        if (t < s) sh[t] += sh[t + s];
        __syncthreads();
    }
    if (t == 0) g_partial[blockIdx.x] = sh[0];
}
__global__ void k_escan2(){
    __shared__ int sh[256];
    int t = threadIdx.x;
    int orig = g_partial[t];
    sh[t] = orig; __syncthreads();
    for (int s = 1; s < 256; s <<= 1){
        int v = (t >= s) ? sh[t - s] : 0;
        __syncthreads();
        sh[t] += v;
        __syncthreads();
    }
    g_partial[t] = sh[t] - orig;
}
__global__ void k_escan3(int N){
    __shared__ int sh[256];
    int chunk = (N + 255) / 256;
    int t = threadIdx.x;
    int i = blockIdx.x * chunk + t;
    int orig = 0;
    if (t < chunk && i < N) orig = g_indeg[g_nperm[i]];
    sh[t] = orig; __syncthreads();
    for (int s = 1; s < 256; s <<= 1){
        int v = (t >= s) ? sh[t - s] : 0;
        __syncthreads();
        sh[t] += v;
        __syncthreads();
    }
    if (t < chunk && i < N){
        int excl = g_partial[blockIdx.x] + sh[t] - orig;
        g_nodeoff[i] = excl;
        g_nodecur[i] = excl;
    }
}
__global__ void k_sedges(const int* __restrict__ ei, const float* __restrict__ eattr, int E){
    int e = blockIdx.x * blockDim.x + threadIdx.x;
    if (e < E){
        int dst = ei[E + e];
        int pos = atomicAdd(&g_nodecur[g_rank[dst]], 1);
        g_esrc[pos] = ei[e];
        g_edst[pos] = dst;
        g_eatt[pos] = eattr[e];
    }
}

// ---------------- weight image prep: [n][k] = W[k][n], single fp16 ----------------
__global__ void k_prep(const float* __restrict__ mw1, const float* __restrict__ mw2,
                       const float* __restrict__ uw1, const float* __restrict__ uw2,
                       const float* __restrict__ pw){
    int idx = blockIdx.x * blockDim.x + threadIdx.x;
    if (idx >= 98304) return;
    const float* W; u16 *H; int n, k, kdim;
    if (idx < 32768){
        int mtx = idx >> 14, rem = idx & 16383;
        n = rem >> 7; k = rem & 127; kdim = 128;
        W = mtx ? mw2 : mw1; H = mtx ? g_w2h : g_w1h;
    } else if (idx < 65536){
        int j = idx - 32768;
        n = j >> 8; k = j & 255; kdim = 256;
        W = uw1; H = g_u1h;
    } else if (idx < 81920){
        int j = idx - 65536;
        n = j >> 7; k = j & 127; kdim = 128;
        W = uw2; H = g_u2h;
    } else {
        int j = idx - 81920;
        n = j >> 7; k = j & 127; kdim = 128;
        W = pw; H = g_pwh;
    }
    float v = W[k * HID + n];
    __half hh = __float2half_rn(v);
    H[n * kdim + k] = *(u16*)&hh;
}

// ---------------- projection: HMMA fp16, warp-owns-rows ----------------
// SMEM: A fp16 [128][272] at 0 (34816); W at 34816 (34816); bias at 69632
#define PW_OFF 34816
#define PMISC  69632
#define SMEM_PROJ (PMISC + 512)
__global__ __launch_bounds__(256, 2) void k_proj(const float* __restrict__ x, const float* __restrict__ pb,
                                                 float* __restrict__ h, int N){
    extern __shared__ char smc[];
    u32 smb = s2u(smc);
    int tid = threadIdx.x, wid = tid >> 5, lane = tid & 31;
    float* bs = (float*)(smc + PMISC);

    for (int i = tid; i < 2048; i += 256){
        int n = i >> 4, kc = i & 15;
        *(uint4*)(smc + PW_OFF + (u32)n * 272 + (u32)kc * 16) = ((const uint4*)g_pwh)[i];
    }
    if (tid < 128) bs[tid] = pb[tid];
    __syncthreads();

    int ntiles = (N + 127) >> 7;
    u32 afrag = smb + (u32)(wid * 16 + (lane & 15)) * 272 + (u32)((lane >> 4) << 4);
    int ra = wid * 16 + (lane >> 2);
    int rb = ra + 8;
    u32 lanemap = (u32)(((lane >> 4) << 3) + (lane & 7)) * 272 + (u32)(((lane >> 3) & 1) << 4);

    for (int t = blockIdx.x; t < ntiles; t += gridDim.x){
        {   // gather x fp32 -> fp16
            int m = tid >> 1, q = tid & 1;
            int row = t * 128 + m;
            const float4* xr = (const float4*)(x + (size_t)(row < N ? row : 0) * HID) + q * 16;
            #pragma unroll
            for (int j = 0; j < 8; ++j){
                float4 v0 = xr[2*j], v1 = xr[2*j + 1];
                uint4 pv;
                pv.x = h2pack(v0.x, v0.y);
                pv.y = h2pack(v0.z, v0.w);
                pv.z = h2pack(v1.x, v1.y);
                pv.w = h2pack(v1.z, v1.w);
                *(uint4*)(smc + (u32)m * 272 + (u32)(q * 8 + j) * 16) = pv;
            }
        }
        __syncthreads();

        u32 a[8][4];
        #pragma unroll
        for (int kc = 0; kc < 8; ++kc) LDX4(a[kc], afrag + kc * 32);
        __syncwarp();

        u32 wb0 = smb + PW_OFF + lanemap;
        int rga = t * 128 + ra, rgb = t * 128 + rb;
        #pragma unroll
        for (int np = 0; np < 8; ++np){
            float aH0[4] = {0,0,0,0}, aH1[4] = {0,0,0,0};
            u32 wb = wb0 + (u32)np * 16 * 272;
            #pragma unroll
            for (int kc = 0; kc < 8; ++kc){
                u32 bh[4];
                LDX4(bh, wb + kc * 32);
                MMAH(aH0, a[kc], bh[0], bh[1]);
                MMAH(aH1, a[kc], bh[2], bh[3]);
            }
            #pragma unroll
            for (int nch = 0; nch < 2; ++nch){
                const float* H = nch ? aH1 : aH0;
                int c = np * 16 + nch * 8 + 2 * (lane & 3);
                float bb0 = bs[c], bb1 = bs[c+1];
                float v0 = H[0] + bb0, v1 = H[1] + bb1;
                if (rga < N){
                    *(float2*)(h + (size_t)rga * HID + c) = make_float2(v0, v1);
                    *(u32*)(&g_hf[(size_t)rga * HID + c]) = h2pack(v0, v1);
                }
                v0 = H[2] + bb0; v1 = H[3] + bb1;
                if (rgb < N){
                    *(float2*)(h + (size_t)rgb * HID + c) = make_float2(v0, v1);
                    *(u32*)(&g_hf[(size_t)rgb * HID + c]) = h2pack(v0, v1);
                }
            }
        }
        __syncthreads();
    }
}

// ---------------- message MLP: HMMA fp16, 512 thr, warp-pair split, 2 blocks/SM ----------------
// SMEM: A/T/stage fp16 [128][272] at 0 (34816); W1 at 34816; W2 at 69632; misc at 104448
#define MW1OFF 34816
#define MW2OFF 69632
#define MSDOFF 104448
#define SMEM_MSG (MSDOFF + 2560)

__global__ __launch_bounds__(512, 2) void k_msg(const float* __restrict__ mw1, const float* __restrict__ mb1,
                                                const float* __restrict__ mb2, int N, int E, int lvl){
    extern __shared__ char smc[];
    u32 smb = s2u(smc);
    int tid = threadIdx.x, wid = tid >> 5, lane = tid & 31;

    int*   sdst = (int*)  (smc + MSDOFF);
    float* seat = (float*)(smc + MSDOFF + 512);
    float* b1s  = (float*)(smc + MSDOFF + 1024);
    float* b2s  = (float*)(smc + MSDOFF + 1536);
    float* wls  = (float*)(smc + MSDOFF + 2048);

    for (int i = tid; i < 2048; i += 512){
        int n = i >> 4, kc = i & 15;
        u32 off = (u32)n * 272 + (u32)kc * 16;
        *(uint4*)(smc + MW1OFF + off) = ((const uint4*)g_w1h)[i];
        *(uint4*)(smc + MW2OFF + off) = ((const uint4*)g_w2h)[i];
    }
    if (tid < 128){
        b1s[tid] = mb1[tid];
        b2s[tid] = mb2[tid];
        wls[tid] = mw1[128 * HID + tid];
    }
    __syncthreads();

    int b0 = g_noff[lvl];
    int ncount = g_ncnt[lvl];
    int b1 = b0 + ncount;
    int base = (b0 < N) ? g_nodeoff[b0] : E;
    int eend = (b1 < N) ? g_nodeoff[b1] : E;
    int cnt = eend - base;
    int ntiles = (cnt + 127) >> 7;

    // warp pair: rgrp owns rows rgrp*16..+15; nh owns col half
    int rgrp = wid >> 1, nh = wid & 1;
    u32 afrag = smb + (u32)(rgrp * 16 + (lane & 15)) * 272 + (u32)((lane >> 4) << 4);
    int ra = rgrp * 16 + (lane >> 2);
    int rb = ra + 8;
    u32 lanemap = (u32)(((lane >> 4) << 3) + (lane & 7)) * 272 + (u32)(((lane >> 3) & 1) << 4);

    for (int t = blockIdx.x; t < ntiles; t += gridDim.x){
        {   // gather: 4 threads per row, 4 uint4 each
            int m = tid >> 2, q = tid & 3;
            int p = t * 128 + m;
            int src = 0;
            if (p < cnt) src = g_esrc[base + p];
            if (q == 0){
                sdst[m] = (p < cnt) ? g_edst[base + p] : -1;
                seat[m] = (p < cnt) ? g_eatt[base + p] : 0.f;
            }
            const uint4* hr = (const uint4*)(&g_hf[(size_t)src * HID]);
            #pragma unroll
            for (int j = 0; j < 4; ++j){
                int q4 = q * 4 + j;
                *(uint4*)(smc + (u32)m * 272 + (u32)q4 * 16) = hr[q4];
            }
        }
        __syncthreads();

        u32 a[8][4];
        #pragma unroll
        for (int kc = 0; kc < 8; ++kc) LDX4(a[kc], afrag + kc * 32);
        float ea_a = seat[ra], ea_b = seat[rb];
        PAIR_BAR(rgrp + 1);     // pair's a-frags loaded before T overwrite

        // layer 1: own col half (4 np groups)
        u32 w1b = smb + MW1OFF + (u32)(nh * 64) * 272 + lanemap;
        #pragma unroll
        for (int np = 0; np < 4; ++np){
            float aH0[4] = {0,0,0,0}, aH1[4] = {0,0,0,0};
            u32 wb = w1b + (u32)np * 16 * 272;
            #pragma unroll
            for (int kc = 0; kc < 8; ++kc){
                u32 bh[4];
                LDX4(bh, wb + kc * 32);
                MMAH(aH0, a[kc], bh[0], bh[1]);
                MMAH(aH1, a[kc], bh[2], bh[3]);
            }
            #pragma unroll
            for (int nch = 0; nch < 2; ++nch){
                const float* H = nch ? aH1 : aH0;
                int c = nh * 64 + np * 16 + nch * 8 + 2 * (lane & 3);
                float w0 = wls[c], w1v = wls[c+1], bb0 = b1s[c], bb1 = b1s[c+1];
                float v0 = fmaxf(H[0] + bb0 + ea_a * w0,  0.f);
                float v1 = fmaxf(H[1] + bb1 + ea_a * w1v, 0.f);
                *(u32*)(smc + (u32)ra * 272 + (u32)c * 2) = h2pack(v0, v1);
                v0 = fmaxf(H[2] + bb0 + ea_b * w0,  0.f);
                v1 = fmaxf(H[3] + bb1 + ea_b * w1v, 0.f);
                *(u32*)(smc + (u32)rb * 272 + (u32)c * 2) = h2pack(v0, v1);
            }
        }
        PAIR_BAR(rgrp + 1);     // T complete for pair's rows
        #pragma unroll
        for (int kc = 0; kc < 8; ++kc) LDX4(a[kc], afrag + kc * 32);
        PAIR_BAR(rgrp + 1);     // T frags in regs before stage overwrite

        // layer 2: stage fp16 into own rows/cols
        u32 w2b = smb + MW2OFF + (u32)(nh * 64) * 272 + lanemap;
        #pragma unroll
        for (int np = 0; np < 4; ++np){
            float aH0[4] = {0,0,0,0}, aH1[4] = {0,0,0,0};
            u32 wb = w2b + (u32)np * 16 * 272;
            #pragma unroll
            for (int kc = 0; kc < 8; ++kc){
                u32 bh[4];
                LDX4(bh, wb + kc * 32);
                MMAH(aH0, a[kc], bh[0], bh[1]);
                MMAH(aH1, a[kc], bh[2], bh[3]);
            }
            #pragma unroll
            for (int nch = 0; nch < 2; ++nch){
                const float* H = nch ? aH1 : aH0;
                int c = nh * 64 + np * 16 + nch * 8 + 2 * (lane & 3);
                float bb0 = b2s[c], bb1 = b2s[c+1];
                float v0 = fmaxf(H[0] + bb0, 0.f);
                float v1 = fmaxf(H[1] + bb1, 0.f);
                *(u32*)(smc + (u32)ra * 272 + (u32)c * 2) = h2pack(v0, v1);
                v0 = fmaxf(H[2] + bb0, 0.f);
                v1 = fmaxf(H[3] + bb1, 0.f);
                *(u32*)(smc + (u32)rb * 272 + (u32)c * 2) = h2pack(v0, v1);
            }
        }
        __syncthreads();

        // segmented flush (dst-sorted rows): 8 groups x 16 rows, half2 cols
        {
            int c2 = tid & 63, g = tid >> 6;
            int r0 = g * 16;
            float run0 = 0.f, run1 = 0.f;
            int prev = sdst[r0];
            for (int r = 0; r < 16; ++r){
                int rr = r0 + r;
                int d = sdst[rr];
                u32 pv = *(u32*)(smc + (u32)rr * 272 + (u32)c2 * 4);
                float2 fv = __half22float2(*(__half2*)&pv);
                if (d != prev){
                    if (prev >= 0){
                        atomicAdd(&g_agg[(size_t)prev * HID + 2*c2],     run0);
                        atomicAdd(&g_agg[(size_t)prev * HID + 2*c2 + 1], run1);
                    }
                    run0 = 0.f; run1 = 0.f;
                    prev = d;
                }
                run0 += fv.x; run1 += fv.y;
            }
            if (prev >= 0){
                atomicAdd(&g_agg[(size_t)prev * HID + 2*c2],     run0);
                atomicAdd(&g_agg[(size_t)prev * HID + 2*c2 + 1], run1);
            }
        }
        __syncthreads();
    }
}

// ---------------- fused node update: HMMA, K=256 then K=128 ----------------
// SMEM: A [128][528] at 0 (67584); T [128][272] at 67584 (34816);
// U1 at 102400 (67584); U2 at 169984 (34816); misc at 204800
#define UT   67584
#define UW1  102400
#define UW2  169984
#define UMISC 204800
#define SMEM_UPD (UMISC + 1536)

__global__ __launch_bounds__(512, 1) void k_upd(float* __restrict__ h, const float* __restrict__ ub1,
                                                const float* __restrict__ ub2, int lvl){
    extern __shared__ char smc[];
    u32 smb = s2u(smc);
    int tid = threadIdx.x, wid = tid >> 5, lane = tid & 31;
    int*   snode = (int*)(smc + UMISC);
    float* b1s   = (float*)(smc + UMISC + 512);
    float* b2s   = (float*)(smc + UMISC + 1024);

    for (int i = tid; i < 4096; i += 512){
        int n = i >> 5, kc = i & 31;
        *(uint4*)(smc + UW1 + (u32)n * 528 + (u32)kc * 16) = ((const uint4*)g_u1h)[i];
    }
    for (int i = tid; i < 2048; i += 512){
        int n = i >> 4, kc = i & 15;
        *(uint4*)(smc + UW2 + (u32)n * 272 + (u32)kc * 16) = ((const uint4*)g_u2h)[i];
    }
    if (tid < 128){ b1s[tid] = ub1[tid]; b2s[tid] = ub2[tid]; }
    __syncthreads();

    int cnt  = g_ncnt[lvl];
    int base = g_noff[lvl];
    int ntiles = (cnt + 127) >> 7;

    int rgrp = wid >> 1, nh = wid & 1;
    u32 afrag1 = smb + (u32)(rgrp * 16 + (lane & 15)) * 528 + (u32)((lane >> 4) << 4);
    u32 afrag2 = smb + UT + (u32)(rgrp * 16 + (lane & 15)) * 272 + (u32)((lane >> 4) << 4);
    int ra = rgrp * 16 + (lane >> 2);
    int rb = ra + 8;
    u32 lanemap1 = (u32)(((lane >> 4) << 3) + (lane & 7)) * 528 + (u32)(((lane >> 3) & 1) << 4);
    u32 lanemap2 = (u32)(((lane >> 4) << 3) + (lane & 7)) * 272 + (u32)(((lane >> 3) & 1) << 4);

    for (int t = blockIdx.x; t < ntiles; t += gridDim.x){
        __syncthreads();
        {   // gather A = [h fp16 | agg*inv fp16]
            int m = tid >> 2, q = tid & 3;
            int p = t * 128 + m;
            int v = (p < cnt) ? g_nperm[base + p] : 0;
            float inv = g_inv[v];
            if (q == 0) snode[m] = (p < cnt) ? v : -1;
            const uint4*  hr = (const uint4*)(&g_hf[(size_t)v * HID]);
            const float4* ar = (const float4*)(&g_agg[(size_t)v * HID]);
            #pragma unroll
            for (int j = 0; j < 4; ++j){
                int q4 = q * 4 + j;
                *(uint4*)(smc + (u32)m * 528 + (u32)q4 * 16) = hr[q4];
                float4 a0 = ar[2 * q4], a1 = ar[2 * q4 + 1];
                uint4 pv;
                pv.x = h2pack(a0.x * inv, a0.y * inv);
                pv.y = h2pack(a0.z * inv, a0.w * inv);
                pv.z = h2pack(a1.x * inv, a1.y * inv);
                pv.w = h2pack(a1.z * inv, a1.w * inv);
                *(uint4*)(smc + (u32)m * 528 + 256 + (u32)q4 * 16) = pv;
            }
        }
        __syncthreads();

        // layer 1 (K = 256)
        u32 a1[16][4];
        #pragma unroll
        for (int kc = 0; kc < 16; ++kc) LDX4(a1[kc], afrag1 + kc * 32);

        u32 w1b = smb + UW1 + (u32)(nh * 64) * 528 + lanemap1;
        #pragma unroll
        for (int np = 0; np < 4; ++np){
            float aH0[4] = {0,0,0,0}, aH1[4] = {0,0,0,0};
            u32 wb = w1b + (u32)np * 16 * 528;
            #pragma unroll
            for (int kc = 0; kc < 16; ++kc){
                u32 bh[4];
                LDX4(bh, wb + kc * 32);
                MMAH(aH0, a1[kc], bh[0], bh[1]);
                MMAH(aH1, a1[kc], bh[2], bh[3]);
            }
            #pragma unroll
            for (int nch = 0; nch < 2; ++nch){
                const float* H = nch ? aH1 : aH0;
                int c = nh * 64 + np * 16 + nch * 8 + 2 * (lane & 3);
                float bb0 = b1s[c], bb1 = b1s[c+1];
                float v0 = fmaxf(H[0] + bb0, 0.f);
                float v1 = fmaxf(H[1] + bb1, 0.f);
                *(u32*)(smc + UT + (u32)ra * 272 + (u32)c * 2) = h2pack(v0, v1);
                v0 = fmaxf(H[2] + bb0, 0.f);
                v1 = fmaxf(H[3] + bb1, 0.f);
                *(u32*)(smc + UT + (u32)rb * 272 + (u32)c * 2) = h2pack(v0, v1);
            }
        }
        PAIR_BAR(rgrp + 1);

        // layer 2 (K = 128)
        u32 a2[8][4];
        #pragma unroll
        for (int kc = 0; kc < 8; ++kc) LDX4(a2[kc], afrag2 + kc * 32);

        u32 w2b = smb + UW2 + (u32)(nh * 64) * 272 + lanemap2;
        int na = snode[ra], nb = snode[rb];
        #pragma unroll
        for (int np = 0; np < 4; ++np){
            float aH0[4] = {0,0,0,0}, aH1[4] = {0,0,0,0};
            u32 wb = w2b + (u32)np * 16 * 272;
            #pragma unroll
            for (int kc = 0; kc < 8; ++kc){
                u32 bh[4];
                LDX4(bh, wb + kc * 32);
                MMAH(aH0, a2[kc], bh[0], bh[1]);
                MMAH(aH1, a2[kc], bh[2], bh[3]);
            }
            #pragma unroll
            for (int nch = 0; nch < 2; ++nch){
                const float* H = nch ? aH1 : aH0;
                int c = nh * 64 + np * 16 + nch * 8 + 2 * (lane & 3);
                float bb0 = b2s[c], bb1 = b2s[c+1];
                float v0 = fmaxf(H[0] + bb0, 0.f);
                float v1 = fmaxf(H[1] + bb1, 0.f);
                if (na >= 0){
                    *(float2*)(h + (size_t)na * HID + c) = make_float2(v0, v1);
                    *(u32*)(&g_hf[(size_t)na * HID + c]) = h2pack(v0, v1);
                }
                v0 = fmaxf(H[2] + bb0, 0.f);
                v1 = fmaxf(H[3] + bb1, 0.f);
                if (nb >= 0){
                    *(float2*)(h + (size_t)nb * HID + c) = make_float2(v0, v1);
                    *(u32*)(&g_hf[(size_t)nb * HID + c]) = h2pack(v0, v1);
                }
            }
        }
    }
}

// ---------------- host launch ----------------
extern "C" void kernel_launch(void* const* d_in, const int* in_sizes, int n_in,
                              void* d_out, int out_size){
    const float* x     = (const float*)d_in[0];
    const int*   ei    = (const int*)  d_in[1];
    const float* eattr = (const float*)d_in[2];
    const int*   depth = (const int*)  d_in[3];
    const float* pw    = (const float*)d_in[4];
    const float* pb    = (const float*)d_in[5];
    const float* mw1   = (const float*)d_in[6];
    const float* mb1   = (const float*)d_in[7];
    const float* mw2   = (const float*)d_in[8];
    const float* mb2   = (const float*)d_in[9];
    const float* uw1   = (const float*)d_in[10];
    const float* ub1   = (const float*)d_in[11];
    const float* uw2   = (const float*)d_in[12];
    const float* ub2   = (const float*)d_in[13];
    float* h = (float*)d_out;

    int N = in_sizes[3];
    int E = in_sizes[2];

    static int sms = 0;
    if (sms == 0){
        cudaDeviceGetAttribute(&sms, cudaDevAttrMultiProcessorCount, 0);
        if (sms <= 0) sms = 148;
        cudaFuncSetAttribute(k_proj, cudaFuncAttributeMaxDynamicSharedMemorySize, SMEM_PROJ);
        cudaFuncSetAttribute(k_msg,  cudaFuncAttributeMaxDynamicSharedMemorySize, SMEM_MSG);
        cudaFuncSetAttribute(k_upd,  cudaFuncAttributeMaxDynamicSharedMemorySize, SMEM_UPD);
    }

    k_zero<<<1024, 256>>>(N * HID, N);
    k_prep<<<384, 256>>>(mw1, mw2, uw1, uw2, pw);

    int mx = (E > N) ? E : N;
    k_count<<<(mx + 255) / 256, 256>>>(ei, depth, N, E);
    k_nscan<<<1, 32>>>();
    k_snodes<<<(N + 255) / 256, 256>>>(depth, N);
    k_escan1<<<256, 256>>>(N);
    k_escan2<<<1, 256>>>();
    k_escan3<<<256, 256>>>(N);
    k_sedges<<<(E + 255) / 256, 256>>>(ei, eattr, E);

    k_proj<<<2 * sms, 256, SMEM_PROJ>>>(x, pb, h, N);

    for (int d = 1; d <= 4; ++d){
        k_msg<<<2 * sms, 512, SMEM_MSG>>>(mw1, mb1, mb2, N, E, d);
        k_upd<<<sms, 512, SMEM_UPD>>>(h, ub1, ub2, d);
    }
}

// round 15
// speedup vs baseline: 6.5560x; 1.0156x over previous
#include <cuda_runtime.h>
#include <cuda_fp16.h>

typedef unsigned int u32;
typedef unsigned long long u64;
typedef unsigned short u16;

#define HID 128
#define NMAX 50000
#define EMAX 500000

// ---------------- device scratch ----------------
__device__ float g_agg[(size_t)NMAX * HID];
__device__ float g_inv[NMAX];
__device__ int   g_indeg[NMAX];
__device__ int   g_nperm[NMAX];
__device__ int   g_rank[NMAX];
__device__ int   g_nodeoff[NMAX];
__device__ int   g_nodecur[NMAX];
__device__ int   g_partial[256];
__device__ int   g_ncnt[8], g_noff[8], g_ncur[8];
__device__ u32   g_done1, g_done2;
// sorted edge arrays (by level, then dst): packed (eattr<<32 | src), dst
__device__ u64   g_ese[EMAX];
__device__ int   g_edst[EMAX];
// fp16 image of h
__device__ u16   g_hf[(size_t)NMAX * HID];
// weight images, [n][k] row-major, single fp16
__device__ u16   g_w1h[16384], g_w2h[16384];
__device__ u16   g_u1h[32768], g_u2h[16384];
__device__ u16   g_pwh[16384];

// ---------------- helpers ----------------
static __device__ __forceinline__ u32 h2pack(float f0, float f1){
    __half2 h = __floats2half2_rn(f0, f1);
    return *(u32*)&h;
}
static __device__ __forceinline__ u32 s2u(const void* p){
    u32 a; asm("{ .reg .u64 t; cvta.to.shared.u64 t, %1; cvt.u32.u64 %0, t; }" : "=r"(a) : "l"(p));
    return a;
}

#define LDX4(r, a) \
    asm volatile("ldmatrix.sync.aligned.m8n8.x4.shared.b16 {%0,%1,%2,%3}, [%4];" \
        : "=r"((r)[0]), "=r"((r)[1]), "=r"((r)[2]), "=r"((r)[3]) : "r"(a))

#define MMAH(d, a, b0, b1) \
    asm("mma.sync.aligned.m16n8k16.row.col.f32.f16.f16.f32 " \
        "{%0,%1,%2,%3}, {%4,%5,%6,%7}, {%8,%9}, {%0,%1,%2,%3};" \
        : "+f"((d)[0]), "+f"((d)[1]), "+f"((d)[2]), "+f"((d)[3]) \
        : "r"((a)[0]), "r"((a)[1]), "r"((a)[2]), "r"((a)[3]), "r"(b0), "r"(b1))

#define PAIR_BAR(id) asm volatile("bar.sync %0, 64;" :: "r"(id) : "memory")

// ---------------- init: zero scratch + build fp16 weight images ----------------
__global__ void k_init(int nagg, int N, const float* __restrict__ mw1, const float* __restrict__ mw2,
                       const float* __restrict__ uw1, const float* __restrict__ uw2,
                       const float* __restrict__ pw){
    int i  = blockIdx.x * blockDim.x + threadIdx.x;
    int st = gridDim.x * blockDim.x;
    for (int j = i; j < nagg; j += st) g_agg[j] = 0.f;
    for (int j = i; j < N;    j += st) g_indeg[j] = 0;
    if (i < 8) g_ncnt[i] = 0;
    for (int idx = i; idx < 98304; idx += st){
        const float* W; u16 *H; int n, k, kdim;
        if (idx < 32768){
            int mtx = idx >> 14, rem = idx & 16383;
            n = rem >> 7; k = rem & 127; kdim = 128;
            W = mtx ? mw2 : mw1; H = mtx ? g_w2h : g_w1h;
        } else if (idx < 65536){
            int j = idx - 32768;
            n = j >> 8; k = j & 255; kdim = 256;
            W = uw1; H = g_u1h;
        } else if (idx < 81920){
            int j = idx - 65536;
            n = j >> 7; k = j & 127; kdim = 128;
            W = uw2; H = g_u2h;
        } else {
            int j = idx - 81920;
            n = j >> 7; k = j & 127; kdim = 128;
            W = pw; H = g_pwh;
        }
        float v = W[k * HID + n];
        __half hh = __float2half_rn(v);
        H[n * kdim + k] = *(u16*)&hh;
    }
}

// ---------------- count (+ fused level scan in last block) ----------------
__global__ void k_count(const int* __restrict__ ei, const int* __restrict__ depth, int N, int E){
    __shared__ int scnt[8];
    int t = threadIdx.x;
    if (t < 8) scnt[t] = 0;
    __syncthreads();
    int i = blockIdx.x * blockDim.x + t;
    if (i < E) atomicAdd(&g_indeg[ei[E + i]], 1);
    if (i < N) atomicAdd(&scnt[depth[i]], 1);
    __syncthreads();
    if (t < 8 && scnt[t]) atomicAdd(&g_ncnt[t], scnt[t]);
    __syncthreads();
    if (t == 0){
        __threadfence();
        u32 old = atomicAdd(&g_done1, 1);
        if (old == gridDim.x - 1){
            g_done1 = 0;
            int n = 0;
            #pragma unroll
            for (int d = 0; d < 8; ++d){
                int c = atomicAdd(&g_ncnt[d], 0);
                g_noff[d] = n; g_ncur[d] = n; n += c;
            }
        }
    }
}

__global__ void k_snodes(const int* __restrict__ depth, int N){
    __shared__ int scnt[8], sbase[8];
    int t = threadIdx.x;
    if (t < 8) scnt[t] = 0;
    __syncthreads();
    int i = blockIdx.x * blockDim.x + t;
    int d = 0, pl = 0;
    if (i < N){ d = depth[i]; pl = atomicAdd(&scnt[d], 1); }
    __syncthreads();
    if (t < 8) sbase[t] = scnt[t] ? atomicAdd(&g_ncur[t], scnt[t]) : 0;
    __syncthreads();
    if (i < N){
        int pos = sbase[d] + pl;
        g_nperm[pos] = i;
        g_rank[i] = pos;
        int c = g_indeg[i];
        g_inv[i] = 1.0f / (float)(c > 0 ? c : 1);
    }
}

// scan phase 1 + (last block) phase 2
__global__ void k_escan12(int N){
    __shared__ int sh[256];
    __shared__ int slast;
    int chunk = (N + 255) / 256;
    int t = threadIdx.x;
    int i = blockIdx.x * chunk + t;
    int v = 0;
    if (t < chunk && i < N) v = g_indeg[g_nperm[i]];
    sh[t] = v; __syncthreads();
    for (int s = 128; s > 0; s >>= 1){
        if (t < s) sh[t] += sh[t + s];
        __syncthreads();
    }
    if (t == 0){
        g_partial[blockIdx.x] = sh[0];
        __threadfence();
        u32 old = atomicAdd(&g_done2, 1);
        slast = (old == gridDim.x - 1) ? 1 : 0;
        if (slast) g_done2 = 0;
    }
    __syncthreads();
    if (slast){
        __threadfence();
        int orig = g_partial[t];
        sh[t] = orig; __syncthreads();
        for (int s = 1; s < 256; s <<= 1){
            int vv = (t >= s) ? sh[t - s] : 0;
            __syncthreads();
            sh[t] += vv;
            __syncthreads();
        }
        g_partial[t] = sh[t] - orig;
    }
}

__global__ void k_escan3(int N){
    __shared__ int sh[256];
    int chunk = (N + 255) / 256;
    int t = threadIdx.x;
    int i = blockIdx.x * chunk + t;
    int orig = 0;
    if (t < chunk && i < N) orig = g_indeg[g_nperm[i]];
    sh[t] = orig; __syncthreads();
    for (int s = 1; s < 256; s <<= 1){
        int v = (t >= s) ? sh[t - s] : 0;
        __syncthreads();
        sh[t] += v;
        __syncthreads();
    }
    if (t < chunk && i < N){
        int excl = g_partial[blockIdx.x] + sh[t] - orig;
        g_nodeoff[i] = excl;
        g_nodecur[i] = excl;
    }
}

__global__ void k_sedges(const int* __restrict__ ei, const float* __restrict__ eattr, int E){
    int e = blockIdx.x * blockDim.x + threadIdx.x;
    if (e < E){
        int dst = ei[E + e];
        int pos = atomicAdd(&g_nodecur[g_rank[dst]], 1);
        u32 sb = (u32)ei[e];
        u32 ab = __float_as_uint(eattr[e]);
        g_ese[pos] = ((u64)ab << 32) | (u64)sb;
        g_edst[pos] = dst;
    }
}

// ---------------- projection: HMMA fp16, warp-owns-rows ----------------
#define PW_OFF 34816
#define PMISC  69632
#define SMEM_PROJ (PMISC + 512)
__global__ __launch_bounds__(256, 2) void k_proj(const float* __restrict__ x, const float* __restrict__ pb,
                                                 float* __restrict__ h, int N){
    extern __shared__ char smc[];
    u32 smb = s2u(smc);
    int tid = threadIdx.x, wid = tid >> 5, lane = tid & 31;
    float* bs = (float*)(smc + PMISC);

    int ntiles = (N + 127) >> 7;
    if (blockIdx.x >= ntiles) return;

    for (int i = tid; i < 2048; i += 256){
        int n = i >> 4, kc = i & 15;
        *(uint4*)(smc + PW_OFF + (u32)n * 272 + (u32)kc * 16) = ((const uint4*)g_pwh)[i];
    }
    if (tid < 128) bs[tid] = pb[tid];
    __syncthreads();

    u32 afrag = smb + (u32)(wid * 16 + (lane & 15)) * 272 + (u32)((lane >> 4) << 4);
    int ra = wid * 16 + (lane >> 2);
    int rb = ra + 8;
    u32 lanemap = (u32)(((lane >> 4) << 3) + (lane & 7)) * 272 + (u32)(((lane >> 3) & 1) << 4);

    for (int t = blockIdx.x; t < ntiles; t += gridDim.x){
        {
            int m = tid >> 1, q = tid & 1;
            int row = t * 128 + m;
            const float4* xr = (const float4*)(x + (size_t)(row < N ? row : 0) * HID) + q * 16;
            #pragma unroll
            for (int j = 0; j < 8; ++j){
                float4 v0 = xr[2*j], v1 = xr[2*j + 1];
                uint4 pv;
                pv.x = h2pack(v0.x, v0.y);
                pv.y = h2pack(v0.z, v0.w);
                pv.z = h2pack(v1.x, v1.y);
                pv.w = h2pack(v1.z, v1.w);
                *(uint4*)(smc + (u32)m * 272 + (u32)(q * 8 + j) * 16) = pv;
            }
        }
        __syncthreads();

        u32 a[8][4];
        #pragma unroll
        for (int kc = 0; kc < 8; ++kc) LDX4(a[kc], afrag + kc * 32);
        __syncwarp();

        u32 wb0 = smb + PW_OFF + lanemap;
        int rga = t * 128 + ra, rgb = t * 128 + rb;
        #pragma unroll
        for (int np = 0; np < 8; ++np){
            float aH0[4] = {0,0,0,0}, aH1[4] = {0,0,0,0};
            u32 wb = wb0 + (u32)np * 16 * 272;
            #pragma unroll
            for (int kc = 0; kc < 8; ++kc){
                u32 bh[4];
                LDX4(bh, wb + kc * 32);
                MMAH(aH0, a[kc], bh[0], bh[1]);
                MMAH(aH1, a[kc], bh[2], bh[3]);
            }
            #pragma unroll
            for (int nch = 0; nch < 2; ++nch){
                const float* H = nch ? aH1 : aH0;
                int c = np * 16 + nch * 8 + 2 * (lane & 3);
                float bb0 = bs[c], bb1 = bs[c+1];
                float v0 = H[0] + bb0, v1 = H[1] + bb1;
                if (rga < N){
                    *(float2*)(h + (size_t)rga * HID + c) = make_float2(v0, v1);
                    *(u32*)(&g_hf[(size_t)rga * HID + c]) = h2pack(v0, v1);
                }
                v0 = H[2] + bb0; v1 = H[3] + bb1;
                if (rgb < N){
                    *(float2*)(h + (size_t)rgb * HID + c) = make_float2(v0, v1);
                    *(u32*)(&g_hf[(size_t)rgb * HID + c]) = h2pack(v0, v1);
                }
            }
        }
        __syncthreads();
    }
}

// ---------------- message MLP: HMMA fp16, 512 thr, warp-pair split, 2 blocks/SM ----------------
#define MW1OFF 34816
#define MW2OFF 69632
#define MSDOFF 104448
#define SMEM_MSG (MSDOFF + 2560)

__global__ __launch_bounds__(512, 2) void k_msg(const float* __restrict__ mw1, const float* __restrict__ mb1,
                                                const float* __restrict__ mb2, int N, int E, int lvl){
    extern __shared__ char smc[];
    u32 smb = s2u(smc);
    int tid = threadIdx.x, wid = tid >> 5, lane = tid & 31;

    int*   sdst = (int*)  (smc + MSDOFF);
    float* seat = (float*)(smc + MSDOFF + 512);
    float* b1s  = (float*)(smc + MSDOFF + 1024);
    float* b2s  = (float*)(smc + MSDOFF + 1536);
    float* wls  = (float*)(smc + MSDOFF + 2048);

    int b0 = g_noff[lvl];
    int ncount = g_ncnt[lvl];
    int b1 = b0 + ncount;
    int base = (b0 < N) ? g_nodeoff[b0] : E;
    int eend = (b1 < N) ? g_nodeoff[b1] : E;
    int cnt = eend - base;
    int ntiles = (cnt + 127) >> 7;
    if ((int)blockIdx.x >= ntiles) return;

    for (int i = tid; i < 2048; i += 512){
        int n = i >> 4, kc = i & 15;
        u32 off = (u32)n * 272 + (u32)kc * 16;
        *(uint4*)(smc + MW1OFF + off) = ((const uint4*)g_w1h)[i];
        *(uint4*)(smc + MW2OFF + off) = ((const uint4*)g_w2h)[i];
    }
    if (tid < 128){
        b1s[tid] = mb1[tid];
        b2s[tid] = mb2[tid];
        wls[tid] = mw1[128 * HID + tid];
    }
    __syncthreads();

    int rgrp = wid >> 1, nh = wid & 1;
    u32 afrag = smb + (u32)(rgrp * 16 + (lane & 15)) * 272 + (u32)((lane >> 4) << 4);
    int ra = rgrp * 16 + (lane >> 2);
    int rb = ra + 8;
    u32 lanemap = (u32)(((lane >> 4) << 3) + (lane & 7)) * 272 + (u32)(((lane >> 3) & 1) << 4);

    for (int t = blockIdx.x; t < ntiles; t += gridDim.x){
        {   // gather: 4 threads per row, 4 uint4 each; packed (src, eattr)
            int m = tid >> 2, q = tid & 3;
            int p = t * 128 + m;
            u64 se = (p < cnt) ? g_ese[base + p] : 0ull;
            int src = (int)(u32)se;
            if (q == 0){
                sdst[m] = (p < cnt) ? g_edst[base + p] : -1;
                seat[m] = __uint_as_float((u32)(se >> 32));
            }
            const uint4* hr = (const uint4*)(&g_hf[(size_t)src * HID]);
            #pragma unroll
            for (int j = 0; j < 4; ++j){
                int q4 = q * 4 + j;
                *(uint4*)(smc + (u32)m * 272 + (u32)q4 * 16) = hr[q4];
            }
        }
        __syncthreads();

        u32 a[8][4];
        #pragma unroll
        for (int kc = 0; kc < 8; ++kc) LDX4(a[kc], afrag + kc * 32);
        float ea_a = seat[ra], ea_b = seat[rb];
        PAIR_BAR(rgrp + 1);

        // layer 1: own col half
        u32 w1b = smb + MW1OFF + (u32)(nh * 64) * 272 + lanemap;
        #pragma unroll
        for (int np = 0; np < 4; ++np){
            float aH0[4] = {0,0,0,0}, aH1[4] = {0,0,0,0};
            u32 wb = w1b + (u32)np * 16 * 272;
            #pragma unroll
            for (int kc = 0; kc < 8; ++kc){
                u32 bh[4];
                LDX4(bh, wb + kc * 32);
                MMAH(aH0, a[kc], bh[0], bh[1]);
                MMAH(aH1, a[kc], bh[2], bh[3]);
            }
            #pragma unroll
            for (int nch = 0; nch < 2; ++nch){
                const float* H = nch ? aH1 : aH0;
                int c = nh * 64 + np * 16 + nch * 8 + 2 * (lane & 3);
                float w0 = wls[c], w1v = wls[c+1], bb0 = b1s[c], bb1 = b1s[c+1];
                float v0 = fmaxf(H[0] + bb0 + ea_a * w0,  0.f);
                float v1 = fmaxf(H[1] + bb1 + ea_a * w1v, 0.f);
                *(u32*)(smc + (u32)ra * 272 + (u32)c * 2) = h2pack(v0, v1);
                v0 = fmaxf(H[2] + bb0 + ea_b * w0,  0.f);
                v1 = fmaxf(H[3] + bb1 + ea_b * w1v, 0.f);
                *(u32*)(smc + (u32)rb * 272 + (u32)c * 2) = h2pack(v0, v1);
            }
        }
        PAIR_BAR(rgrp + 1);
        #pragma unroll
        for (int kc = 0; kc < 8; ++kc) LDX4(a[kc], afrag + kc * 32);
        PAIR_BAR(rgrp + 1);

        // layer 2: stage fp16 into own rows/cols
        u32 w2b = smb + MW2OFF + (u32)(nh * 64) * 272 + lanemap;
        #pragma unroll
        for (int np = 0; np < 4; ++np){
            float aH0[4] = {0,0,0,0}, aH1[4] = {0,0,0,0};
            u32 wb = w2b + (u32)np * 16 * 272;
            #pragma unroll
            for (int kc = 0; kc < 8; ++kc){
                u32 bh[4];
                LDX4(bh, wb + kc * 32);
                MMAH(aH0, a[kc], bh[0], bh[1]);
                MMAH(aH1, a[kc], bh[2], bh[3]);
            }
            #pragma unroll
            for (int nch = 0; nch < 2; ++nch){
                const float* H = nch ? aH1 : aH0;
                int c = nh * 64 + np * 16 + nch * 8 + 2 * (lane & 3);
                float bb0 = b2s[c], bb1 = b2s[c+1];
                float v0 = fmaxf(H[0] + bb0, 0.f);
                float v1 = fmaxf(H[1] + bb1, 0.f);
                *(u32*)(smc + (u32)ra * 272 + (u32)c * 2) = h2pack(v0, v1);
                v0 = fmaxf(H[2] + bb0, 0.f);
                v1 = fmaxf(H[3] + bb1, 0.f);
                *(u32*)(smc + (u32)rb * 272 + (u32)c * 2) = h2pack(v0, v1);
            }
        }
        __syncthreads();

        // segmented flush (dst-sorted rows): 8 groups x 16 rows, half2 cols
        {
            int c2 = tid & 63, g = tid >> 6;
            int r0 = g * 16;
            float run0 = 0.f, run1 = 0.f;
            int prev = sdst[r0];
            #pragma unroll
            for (int r = 0; r < 16; ++r){
                int rr = r0 + r;
                int d = sdst[rr];
                u32 pv = *(u32*)(smc + (u32)rr * 272 + (u32)c2 * 4);
                float2 fv = __half22float2(*(__half2*)&pv);
                if (d != prev){
                    if (prev >= 0){
                        atomicAdd(&g_agg[(size_t)prev * HID + 2*c2],     run0);
                        atomicAdd(&g_agg[(size_t)prev * HID + 2*c2 + 1], run1);
                    }
                    run0 = 0.f; run1 = 0.f;
                    prev = d;
                }
                run0 += fv.x; run1 += fv.y;
            }
            if (prev >= 0){
                atomicAdd(&g_agg[(size_t)prev * HID + 2*c2],     run0);
                atomicAdd(&g_agg[(size_t)prev * HID + 2*c2 + 1], run1);
            }
        }
        __syncthreads();
    }
}

// ---------------- fused node update: HMMA, K=256 then K=128 ----------------
#define UT   67584
#define UW1  102400
#define UW2  169984
#define UMISC 204800
#define SMEM_UPD (UMISC + 1536)

__global__ __launch_bounds__(512, 1) void k_upd(float* __restrict__ h, const float* __restrict__ ub1,
                                                const float* __restrict__ ub2, int lvl){
    extern __shared__ char smc[];
    u32 smb = s2u(smc);
    int tid = threadIdx.x, wid = tid >> 5, lane = tid & 31;
    int*   snode = (int*)(smc + UMISC);
    float* b1s   = (float*)(smc + UMISC + 512);
    float* b2s   = (float*)(smc + UMISC + 1024);

    int cnt  = g_ncnt[lvl];
    int base = g_noff[lvl];
    int ntiles = (cnt + 127) >> 7;
    if ((int)blockIdx.x >= ntiles) return;

    for (int i = tid; i < 4096; i += 512){
        int n = i >> 5, kc = i & 31;
        *(uint4*)(smc + UW1 + (u32)n * 528 + (u32)kc * 16) = ((const uint4*)g_u1h)[i];
    }
    for (int i = tid; i < 2048; i += 512){
        int n = i >> 4, kc = i & 15;
        *(uint4*)(smc + UW2 + (u32)n * 272 + (u32)kc * 16) = ((const uint4*)g_u2h)[i];
    }
    if (tid < 128){ b1s[tid] = ub1[tid]; b2s[tid] = ub2[tid]; }
    __syncthreads();

    int rgrp = wid >> 1, nh = wid & 1;
    u32 afrag1 = smb + (u32)(rgrp * 16 + (lane & 15)) * 528 + (u32)((lane >> 4) << 4);
    u32 afrag2 = smb + UT + (u32)(rgrp * 16 + (lane & 15)) * 272 + (u32)((lane >> 4) << 4);
    int ra = rgrp * 16 + (lane >> 2);
    int rb = ra + 8;
    u32 lanemap1 = (u32)(((lane >> 4) << 3) + (lane & 7)) * 528 + (u32)(((lane >> 3) & 1) << 4);
    u32 lanemap2 = (u32)(((lane >> 4) << 3) + (lane & 7)) * 272 + (u32)(((lane >> 3) & 1) << 4);

    for (int t = blockIdx.x; t < ntiles; t += gridDim.x){
        __syncthreads();
        {
            int m = tid >> 2, q = tid & 3;
            int p = t * 128 + m;
            int v = (p < cnt) ? g_nperm[base + p] : 0;
            float inv = g_inv[v];
            if (q == 0) snode[m] = (p < cnt) ? v : -1;
            const uint4*  hr = (const uint4*)(&g_hf[(size_t)v * HID]);
            const float4* ar = (const float4*)(&g_agg[(size_t)v * HID]);
            #pragma unroll
            for (int j = 0; j < 4; ++j){
                int q4 = q * 4 + j;
                *(uint4*)(smc + (u32)m * 528 + (u32)q4 * 16) = hr[q4];
                float4 a0 = ar[2 * q4], a1 = ar[2 * q4 + 1];
                uint4 pv;
                pv.x = h2pack(a0.x * inv, a0.y * inv);
                pv.y = h2pack(a0.z * inv, a0.w * inv);
                pv.z = h2pack(a1.x * inv, a1.y * inv);
                pv.w = h2pack(a1.z * inv, a1.w * inv);
                *(uint4*)(smc + (u32)m * 528 + 256 + (u32)q4 * 16) = pv;
            }
        }
        __syncthreads();

        u32 a1[16][4];
        #pragma unroll
        for (int kc = 0; kc < 16; ++kc) LDX4(a1[kc], afrag1 + kc * 32);

        u32 w1b = smb + UW1 + (u32)(nh * 64) * 528 + lanemap1;
        #pragma unroll
        for (int np = 0; np < 4; ++np){
            float aH0[4] = {0,0,0,0}, aH1[4] = {0,0,0,0};
            u32 wb = w1b + (u32)np * 16 * 528;
            #pragma unroll
            for (int kc = 0; kc < 16; ++kc){
                u32 bh[4];
                LDX4(bh, wb + kc * 32);
                MMAH(aH0, a1[kc], bh[0], bh[1]);
                MMAH(aH1, a1[kc], bh[2], bh[3]);
            }
            #pragma unroll
            for (int nch = 0; nch < 2; ++nch){
                const float* H = nch ? aH1 : aH0;
                int c = nh * 64 + np * 16 + nch * 8 + 2 * (lane & 3);
                float bb0 = b1s[c], bb1 = b1s[c+1];
                float v0 = fmaxf(H[0] + bb0, 0.f);
                float v1 = fmaxf(H[1] + bb1, 0.f);
                *(u32*)(smc + UT + (u32)ra * 272 + (u32)c * 2) = h2pack(v0, v1);
                v0 = fmaxf(H[2] + bb0, 0.f);
                v1 = fmaxf(H[3] + bb1, 0.f);
                *(u32*)(smc + UT + (u32)rb * 272 + (u32)c * 2) = h2pack(v0, v1);
            }
        }
        PAIR_BAR(rgrp + 1);

        u32 a2[8][4];
        #pragma unroll
        for (int kc = 0; kc < 8; ++kc) LDX4(a2[kc], afrag2 + kc * 32);

        u32 w2b = smb + UW2 + (u32)(nh * 64) * 272 + lanemap2;
        int na = snode[ra], nb = snode[rb];
        #pragma unroll
        for (int np = 0; np < 4; ++np){
            float aH0[4] = {0,0,0,0}, aH1[4] = {0,0,0,0};
            u32 wb = w2b + (u32)np * 16 * 272;
            #pragma unroll
            for (int kc = 0; kc < 8; ++kc){
                u32 bh[4];
                LDX4(bh, wb + kc * 32);
                MMAH(aH0, a2[kc], bh[0], bh[1]);
                MMAH(aH1, a2[kc], bh[2], bh[3]);
            }
            #pragma unroll
            for (int nch = 0; nch < 2; ++nch){
                const float* H = nch ? aH1 : aH0;
                int c = nh * 64 + np * 16 + nch * 8 + 2 * (lane & 3);
                float bb0 = b2s[c], bb1 = b2s[c+1];
                float v0 = fmaxf(H[0] + bb0, 0.f);
                float v1 = fmaxf(H[1] + bb1, 0.f);
                if (na >= 0){
                    *(float2*)(h + (size_t)na * HID + c) = make_float2(v0, v1);
                    *(u32*)(&g_hf[(size_t)na * HID + c]) = h2pack(v0, v1);
                }
                v0 = fmaxf(H[2] + bb0, 0.f);
                v1 = fmaxf(H[3] + bb1, 0.f);
                if (nb >= 0){
                    *(float2*)(h + (size_t)nb * HID + c) = make_float2(v0, v1);
                    *(u32*)(&g_hf[(size_t)nb * HID + c]) = h2pack(v0, v1);
                }
            }
        }
    }
}

// ---------------- host launch ----------------
extern "C" void kernel_launch(void* const* d_in, const int* in_sizes, int n_in,
                              void* d_out, int out_size){
    const float* x     = (const float*)d_in[0];
    const int*   ei    = (const int*)  d_in[1];
    const float* eattr = (const float*)d_in[2];
    const int*   depth = (const int*)  d_in[3];
    const float* pw    = (const float*)d_in[4];
    const float* pb    = (const float*)d_in[5];
    const float* mw1   = (const float*)d_in[6];
    const float* mb1   = (const float*)d_in[7];
    const float* mw2   = (const float*)d_in[8];
    const float* mb2   = (const float*)d_in[9];
    const float* uw1   = (const float*)d_in[10];
    const float* ub1   = (const float*)d_in[11];
    const float* uw2   = (const float*)d_in[12];
    const float* ub2   = (const float*)d_in[13];
    float* h = (float*)d_out;

    int N = in_sizes[3];
    int E = in_sizes[2];

    static int sms = 0;
    if (sms == 0){
        cudaDeviceGetAttribute(&sms, cudaDevAttrMultiProcessorCount, 0);
        if (sms <= 0) sms = 148;
        cudaFuncSetAttribute(k_proj, cudaFuncAttributeMaxDynamicSharedMemorySize, SMEM_PROJ);
        cudaFuncSetAttribute(k_msg,  cudaFuncAttributeMaxDynamicSharedMemorySize, SMEM_MSG);
        cudaFuncSetAttribute(k_upd,  cudaFuncAttributeMaxDynamicSharedMemorySize, SMEM_UPD);
    }

    k_init<<<1024, 256>>>(N * HID, N, mw1, mw2, uw1, uw2, pw);

    int mx = (E > N) ? E : N;
    k_count<<<(mx + 255) / 256, 256>>>(ei, depth, N, E);
    k_snodes<<<(N + 255) / 256, 256>>>(depth, N);
    k_escan12<<<256, 256>>>(N);
    k_escan3<<<256, 256>>>(N);
    k_sedges<<<(E + 255) / 256, 256>>>(ei, eattr, E);

    k_proj<<<2 * sms, 256, SMEM_PROJ>>>(x, pb, h, N);

    for (int d = 1; d <= 4; ++d){
        k_msg<<<2 * sms, 512, SMEM_MSG>>>(mw1, mb1, mb2, N, E, d);
        k_upd<<<sms, 512, SMEM_UPD>>>(h, ub1, ub2, d);
    }
}